// round 4
// baseline (speedup 1.0000x reference)
#include <cuda_runtime.h>
#include <cstddef>

// ---------------- problem constants ----------------
#define B_    2
#define S_    1024
#define DIN_  64
#define D_    512
#define K_    16
#define KU_   3
#define L_    2
#define M_    2
#define H_    2048
#define R_    (B_ * S_)                 // 2048 rows (b*S + t)
#define SPECC (2 * K_ * D_)             // 16384 spectral columns of U
#define UCOLS (SPECC + KU_ * D_)        // 17920 = spectral + AR columns
#define EPS_  1e-5f
#define NSPLIT_ 3

// ---------------- scratch (static device globals; no allocation) ----------------
__device__ float g_x[R_ * D_];
__device__ float g_z[R_ * D_];
__device__ float g_h[R_ * D_];
__device__ float g_U[(size_t)R_ * UCOLS];            // [Up | Um | h, h<<1, h<<2]
__device__ float g_W[(size_t)D_ * UCOLS];            // fused [sig4*mp | sig4*mm | M_u]
__device__ float g_m1[(size_t)R_ * 2 * H_];
__device__ float g_m2[(size_t)R_ * H_];
__device__ float g_part[(size_t)NSPLIT_ * R_ * D_];  // split-K partials

// ---------------- tf32 helpers ----------------
__device__ __forceinline__ unsigned f2tf(float f) {
    unsigned u;
    asm("cvt.rna.tf32.f32 %0, %1;" : "=r"(u) : "f"(f));
    return u;
}
// split a into hi (tf32 bits) and lo (tf32 bits of exact residual)
__device__ __forceinline__ void split_tf(float a, unsigned& hi, unsigned& lo) {
    hi = f2tf(a);
    lo = f2tf(a - __uint_as_float(hi));
}

__device__ __forceinline__ void mma_tf32(float c[4],
                                         unsigned a0, unsigned a1, unsigned a2, unsigned a3,
                                         unsigned b0, unsigned b1) {
    asm volatile(
        "mma.sync.aligned.m16n8k8.row.col.f32.tf32.tf32.f32 "
        "{%0,%1,%2,%3},{%4,%5,%6,%7},{%8,%9},{%0,%1,%2,%3};\n"
        : "+f"(c[0]), "+f"(c[1]), "+f"(c[2]), "+f"(c[3])
        : "r"(a0), "r"(a1), "r"(a2), "r"(a3), "r"(b0), "r"(b1));
}

// ---------------- 3xTF32 NT GEMM: C(M,N) = A(M,K) * B(N,K)^T ----------------
// 256 threads = 8 warps, (BM/WM)*(BN/WN) == 8, BK=16. BM in {64,128}, BN=128.
// NSPLIT>1: grid.z selects K-chunk, writes C + z*M*N (accum forced 0).
template<int BM, int BN, int WM, int WN, int NSPLIT>
__global__ __launch_bounds__(256) void gemm3(
    const float* __restrict__ A, const float* __restrict__ B, float* __restrict__ C,
    int M, int N, int K, int accum)
{
    constexpr int WARPS_M = BM / WM;
    constexpr int MT = WM / 16;
    constexpr int NT = WN / 8;
    __shared__ unsigned Ah[BM][20], Al[BM][20];
    __shared__ unsigned Bh[BN][20], Bl[BN][20];

    int kb = 0, ke = K;
    if (NSPLIT > 1) {
        const int z = blockIdx.z;
        const int steps = K / 16;
        kb = ((z * steps) / NSPLIT) * 16;
        ke = (((z + 1) * steps) / NSPLIT) * 16;
        C += (size_t)z * M * N;
        accum = 0;
    }

    const int bm = blockIdx.y * BM;
    const int bn = blockIdx.x * BN;
    const int tid  = threadIdx.x;
    const int lane = tid & 31;
    const int warp = tid >> 5;
    const int wm = (warp % WARPS_M) * WM;
    const int wn = (warp / WARPS_M) * WN;
    const int g  = lane >> 2;
    const int tg = lane & 3;

    const int lr  = tid >> 2;        // 0..63
    const int lk4 = (tid & 3) * 4;   // 0,4,8,12

    float acc[MT][NT][4] = {};

    for (int k0 = kb; k0 < ke; k0 += 16) {
        float4 va[BM / 64], vb[BN / 64];
#pragma unroll
        for (int r = 0; r < BM / 64; r++)
            va[r] = *(const float4*)&A[(size_t)(bm + lr + 64 * r) * K + k0 + lk4];
#pragma unroll
        for (int r = 0; r < BN / 64; r++)
            vb[r] = *(const float4*)&B[(size_t)(bn + lr + 64 * r) * K + k0 + lk4];
        __syncthreads();
#pragma unroll
        for (int r = 0; r < BM / 64; r++) {
            const int row = lr + 64 * r;
            split_tf(va[r].x, Ah[row][lk4 + 0], Al[row][lk4 + 0]);
            split_tf(va[r].y, Ah[row][lk4 + 1], Al[row][lk4 + 1]);
            split_tf(va[r].z, Ah[row][lk4 + 2], Al[row][lk4 + 2]);
            split_tf(va[r].w, Ah[row][lk4 + 3], Al[row][lk4 + 3]);
        }
#pragma unroll
        for (int r = 0; r < BN / 64; r++) {
            const int row = lr + 64 * r;
            split_tf(vb[r].x, Bh[row][lk4 + 0], Bl[row][lk4 + 0]);
            split_tf(vb[r].y, Bh[row][lk4 + 1], Bl[row][lk4 + 1]);
            split_tf(vb[r].z, Bh[row][lk4 + 2], Bl[row][lk4 + 2]);
            split_tf(vb[r].w, Bh[row][lk4 + 3], Bl[row][lk4 + 3]);
        }
        __syncthreads();

#pragma unroll
        for (int ks = 0; ks < 2; ks++) {
            const int kbse = ks * 8;
            unsigned afh[MT][4], afl[MT][4], bfh[NT][2], bfl[NT][2];
#pragma unroll
            for (int mt = 0; mt < MT; mt++) {
                const int row = wm + mt * 16;
                afh[mt][0] = Ah[row + g    ][kbse + tg    ];
                afh[mt][1] = Ah[row + g + 8][kbse + tg    ];
                afh[mt][2] = Ah[row + g    ][kbse + tg + 4];
                afh[mt][3] = Ah[row + g + 8][kbse + tg + 4];
                afl[mt][0] = Al[row + g    ][kbse + tg    ];
                afl[mt][1] = Al[row + g + 8][kbse + tg    ];
                afl[mt][2] = Al[row + g    ][kbse + tg + 4];
                afl[mt][3] = Al[row + g + 8][kbse + tg + 4];
            }
#pragma unroll
            for (int nt = 0; nt < NT; nt++) {
                const int col = wn + nt * 8 + g;
                bfh[nt][0] = Bh[col][kbse + tg    ];
                bfh[nt][1] = Bh[col][kbse + tg + 4];
                bfl[nt][0] = Bl[col][kbse + tg    ];
                bfl[nt][1] = Bl[col][kbse + tg + 4];
            }
#pragma unroll
            for (int mt = 0; mt < MT; mt++)
#pragma unroll
                for (int nt = 0; nt < NT; nt++) {
                    mma_tf32(acc[mt][nt], afh[mt][0], afh[mt][1], afh[mt][2], afh[mt][3],
                             bfh[nt][0], bfh[nt][1]);
                    mma_tf32(acc[mt][nt], afl[mt][0], afl[mt][1], afl[mt][2], afl[mt][3],
                             bfh[nt][0], bfh[nt][1]);
                    mma_tf32(acc[mt][nt], afh[mt][0], afh[mt][1], afh[mt][2], afh[mt][3],
                             bfl[nt][0], bfl[nt][1]);
                }
        }
        __syncthreads();
    }

#pragma unroll
    for (int mt = 0; mt < MT; mt++) {
        const int r0 = bm + wm + mt * 16 + g;
        const int r1 = r0 + 8;
#pragma unroll
        for (int nt = 0; nt < NT; nt++) {
            const int col = bn + wn + nt * 8 + 2 * tg;
            float2* p0 = (float2*)&C[(size_t)r0 * N + col];
            float2* p1 = (float2*)&C[(size_t)r1 * N + col];
            float2 v0 = make_float2(acc[mt][nt][0], acc[mt][nt][1]);
            float2 v1 = make_float2(acc[mt][nt][2], acc[mt][nt][3]);
            if (accum) {
                float2 o0 = *p0, o1 = *p1;
                v0.x += o0.x; v0.y += o0.y; v1.x += o1.x; v1.y += o1.y;
            }
            *p0 = v0;
            *p1 = v1;
        }
    }
}

// ---------------- causal spectral conv, tf32 MMA, phi split (2xTF32 on A) ----------------
__global__ __launch_bounds__(256) void conv_tc(
    const float* __restrict__ h, const float* __restrict__ phi, float* __restrict__ U)
{
    __shared__ unsigned Xs[32][68];   // [i][d] tf32(h)
    __shared__ unsigned Ph[160], Pl[160];

    const int d0 = blockIdx.x * 64;
    const int t0 = blockIdx.y * 128;
    const int b  = blockIdx.z >> 4;
    const int k  = blockIdx.z & 15;
    const int tid  = threadIdx.x;
    const int lane = tid & 31;
    const int warp = tid >> 5;
    const int wm = (warp & 3) * 32;
    const int wn = (warp >> 2) * 32;
    const int g  = lane >> 2;
    const int tg = lane & 3;
    const unsigned sx = (tg & 1) ? 0x80000000u : 0u;

    float accp[2][4][4] = {};
    float accm[2][4][4] = {};

    const int xr = tid >> 4;          // 0..15
    const int xc = (tid & 15) * 4;    // 0..60
    const int imax = t0 + 128;

    for (int i0 = 0; i0 < imax; i0 += 32) {
        float4 v0 = *(const float4*)&h[(size_t)(b * S_ + i0 + xr     ) * D_ + d0 + xc];
        float4 v1 = *(const float4*)&h[(size_t)(b * S_ + i0 + xr + 16) * D_ + d0 + xc];
        float pv = 0.f;
        if (tid < 159) {
            const int lag = t0 - i0 - 31 + tid;
            if (lag >= 0 && lag < S_) pv = phi[lag * K_ + k];
        }
        __syncthreads();
        Xs[xr][xc + 0] = f2tf(v0.x); Xs[xr][xc + 1] = f2tf(v0.y);
        Xs[xr][xc + 2] = f2tf(v0.z); Xs[xr][xc + 3] = f2tf(v0.w);
        Xs[xr + 16][xc + 0] = f2tf(v1.x); Xs[xr + 16][xc + 1] = f2tf(v1.y);
        Xs[xr + 16][xc + 2] = f2tf(v1.z); Xs[xr + 16][xc + 3] = f2tf(v1.w);
        if (tid < 159) split_tf(pv, Ph[tid], Pl[tid]);
        if (tid == 159) { Ph[159] = 0u; Pl[159] = 0u; }
        __syncthreads();

#pragma unroll
        for (int ks = 0; ks < 4; ks++) {
            const int kb = ks * 8;
            unsigned afh[2][4], afl[2][4], bf[4][2];
#pragma unroll
            for (int mt = 0; mt < 2; mt++) {
                const int row = wm + mt * 16;
                const int i0o = row - kb + 31;
                afh[mt][0] = Ph[i0o + g     - tg    ];
                afh[mt][1] = Ph[i0o + g + 8 - tg    ];
                afh[mt][2] = Ph[i0o + g     - tg - 4];
                afh[mt][3] = Ph[i0o + g + 8 - tg - 4];
                afl[mt][0] = Pl[i0o + g     - tg    ];
                afl[mt][1] = Pl[i0o + g + 8 - tg    ];
                afl[mt][2] = Pl[i0o + g     - tg - 4];
                afl[mt][3] = Pl[i0o + g + 8 - tg - 4];
            }
#pragma unroll
            for (int nt = 0; nt < 4; nt++) {
                const int col = wn + nt * 8 + g;
                bf[nt][0] = Xs[kb + tg    ][col];
                bf[nt][1] = Xs[kb + tg + 4][col];
            }
#pragma unroll
            for (int mt = 0; mt < 2; mt++)
#pragma unroll
                for (int nt = 0; nt < 4; nt++) {
                    mma_tf32(accp[mt][nt], afh[mt][0], afh[mt][1], afh[mt][2], afh[mt][3],
                             bf[nt][0], bf[nt][1]);
                    mma_tf32(accp[mt][nt], afl[mt][0], afl[mt][1], afl[mt][2], afl[mt][3],
                             bf[nt][0], bf[nt][1]);
                    mma_tf32(accm[mt][nt],
                             afh[mt][0] ^ sx, afh[mt][1] ^ sx, afh[mt][2] ^ sx, afh[mt][3] ^ sx,
                             bf[nt][0], bf[nt][1]);
                    mma_tf32(accm[mt][nt],
                             afl[mt][0] ^ sx, afl[mt][1] ^ sx, afl[mt][2] ^ sx, afl[mt][3] ^ sx,
                             bf[nt][0], bf[nt][1]);
                }
        }
        __syncthreads();
    }

#pragma unroll
    for (int mt = 0; mt < 2; mt++) {
        const int t0r = t0 + wm + mt * 16 + g;
#pragma unroll
        for (int half = 0; half < 2; half++) {
            const int t = t0r + half * 8;
            const float st = (t & 1) ? -1.f : 1.f;
            const size_t row = (size_t)(b * S_ + t) * UCOLS;
#pragma unroll
            for (int nt = 0; nt < 4; nt++) {
                const int d = d0 + wn + nt * 8 + 2 * tg;
                const float cp0 = accp[mt][nt][half * 2 + 0];
                const float cp1 = accp[mt][nt][half * 2 + 1];
                const float cm0 = accm[mt][nt][half * 2 + 0];
                const float cm1 = accm[mt][nt][half * 2 + 1];
                *(float2*)&U[row + (size_t)k * D_ + d]        = make_float2(cp0, cp1);
                *(float2*)&U[row + (size_t)(K_ + k) * D_ + d] = make_float2(st * cm0, st * cm1);
            }
        }
    }
}

// ---------------- fp32 NT GEMM (tiny out_proj: N=64) ----------------
__global__ __launch_bounds__(256) void gemm_nt(
    const float* __restrict__ A, const float* __restrict__ B, float* __restrict__ C,
    int M, int N, int K, int accum)
{
    __shared__ float As[16][65];
    __shared__ float Bs[16][65];
    const int bm = blockIdx.y * 64;
    const int bn = blockIdx.x * 64;
    const int tid = threadIdx.x;
    const int tx = tid & 15;
    const int ty = tid >> 4;
    const int lr = tid >> 2;
    const int lk = (tid & 3) << 2;

    const float* Ap = A + (size_t)(bm + lr) * K + lk;
    const float* Bp = B + (size_t)(bn + lr) * K + lk;

    float acc[4][4] = {};

    for (int k0 = 0; k0 < K; k0 += 16) {
        float4 av = *(const float4*)(Ap + k0);
        float4 bv = *(const float4*)(Bp + k0);
        __syncthreads();
        As[lk + 0][lr] = av.x; As[lk + 1][lr] = av.y;
        As[lk + 2][lr] = av.z; As[lk + 3][lr] = av.w;
        Bs[lk + 0][lr] = bv.x; Bs[lk + 1][lr] = bv.y;
        Bs[lk + 2][lr] = bv.z; Bs[lk + 3][lr] = bv.w;
        __syncthreads();
#pragma unroll
        for (int kk = 0; kk < 16; kk++) {
            float a[4], b[4];
#pragma unroll
            for (int i = 0; i < 4; i++) a[i] = As[kk][ty * 4 + i];
#pragma unroll
            for (int j = 0; j < 4; j++) b[j] = Bs[kk][tx * 4 + j];
#pragma unroll
            for (int i = 0; i < 4; i++)
#pragma unroll
                for (int j = 0; j < 4; j++)
                    acc[i][j] += a[i] * b[j];
        }
    }

#pragma unroll
    for (int i = 0; i < 4; i++) {
        const int r = bm + ty * 4 + i;
#pragma unroll
        for (int j = 0; j < 4; j++) {
            const int c = bn + tx * 4 + j;
            const size_t idx = (size_t)r * N + c;
            C[idx] = accum ? (C[idx] + acc[i][j]) : acc[i][j];
        }
    }
}

// ---------------- rmsnorm + AR column scatter ----------------
__global__ __launch_bounds__(256) void rmsnorm_k(
    const float* __restrict__ x, const float* __restrict__ w,
    float* __restrict__ h, float* __restrict__ U)
{
    __shared__ float red[256];
    const int row = blockIdx.x;
    const int t = row & (S_ - 1);
    const int tid = threadIdx.x;

    const float v0 = x[(size_t)row * D_ + tid];
    const float v1 = x[(size_t)row * D_ + 256 + tid];
    red[tid] = v0 * v0 + v1 * v1;
    __syncthreads();
    for (int s = 128; s > 0; s >>= 1) {
        if (tid < s) red[tid] += red[tid + s];
        __syncthreads();
    }
    const float scale = rsqrtf(red[0] * (1.f / D_) + EPS_);
    const float h0 = v0 * scale * w[tid];
    const float h1 = v1 * scale * w[tid + 256];
    h[(size_t)row * D_ + tid] = h0;
    h[(size_t)row * D_ + 256 + tid] = h1;

#pragma unroll
    for (int j = 0; j < KU_; j++) {
        if (t + j < S_) {
            const size_t base = (size_t)(row + j) * UCOLS + SPECC + j * D_;
            U[base + tid] = h0;
            U[base + 256 + tid] = h1;
        }
        if (t < j) {
            const size_t base = (size_t)row * UCOLS + SPECC + j * D_;
            U[base + tid] = 0.f;
            U[base + 256 + tid] = 0.f;
        }
    }
}

// ---------------- fused weight fill ----------------
__global__ __launch_bounds__(256) void wfill_k(
    const float* __restrict__ sigma, const float* __restrict__ mp,
    const float* __restrict__ mm, const float* __restrict__ mu,
    float* __restrict__ W)
{
    const size_t idx = (size_t)blockIdx.x * 256 + threadIdx.x;
    if (idx >= (size_t)D_ * UCOLS) return;
    const int o = (int)(idx / UCOLS);
    const int col = (int)(idx % UCOLS);
    float v;
    if (col < K_ * D_) {
        const int k = col / D_, d = col % D_;
        v = sqrtf(sqrtf(sigma[k])) * mp[((size_t)k * D_ + d) * D_ + o];
    } else if (col < SPECC) {
        const int c = col - K_ * D_;
        const int k = c / D_, d = c % D_;
        v = sqrtf(sqrtf(sigma[k])) * mm[((size_t)k * D_ + d) * D_ + o];
    } else {
        const int c = col - SPECC;
        const int j = c / D_, d = c % D_;
        v = mu[((size_t)j * D_ + d) * D_ + o];
    }
    W[idx] = v;
}

// ---------------- elementwise kernels ----------------
__global__ __launch_bounds__(256) void silu_k(const float* __restrict__ m1, float* __restrict__ m2)
{
    const int idx = blockIdx.x * 256 + threadIdx.x;
    const int r = idx >> 11;
    const int j = idx & (H_ - 1);
    const float y = m1[(size_t)r * (2 * H_) + j];
    const float g = m1[(size_t)r * (2 * H_) + H_ + j];
    m2[idx] = y * g / (1.f + expf(-g));
}

__global__ __launch_bounds__(256) void copy_k(float* __restrict__ dst, const float* __restrict__ src)
{
    const int i = blockIdx.x * 256 + threadIdx.x;
    ((float4*)dst)[i] = ((const float4*)src)[i];
}

__global__ __launch_bounds__(256) void add_k(float* __restrict__ dst, const float* __restrict__ src)
{
    const int i = blockIdx.x * 256 + threadIdx.x;
    float4 a = ((const float4*)dst)[i];
    float4 b = ((const float4*)src)[i];
    a.x += b.x; a.y += b.y; a.z += b.z; a.w += b.w;
    ((float4*)dst)[i] = a;
}

// x[i] += p0[i] + p1[i] + p2[i]
__global__ __launch_bounds__(256) void reduce3_k(float* __restrict__ x, const float* __restrict__ p)
{
    const int i = blockIdx.x * 256 + threadIdx.x;   // over R_*D_/4
    const size_t MN4 = (size_t)R_ * D_ / 4;
    float4 a = ((const float4*)x)[i];
    float4 b0 = ((const float4*)p)[i];
    float4 b1 = ((const float4*)p)[i + MN4];
    float4 b2 = ((const float4*)p)[i + 2 * MN4];
    a.x += b0.x + b1.x + b2.x;
    a.y += b0.y + b1.y + b2.y;
    a.z += b0.z + b1.z + b2.z;
    a.w += b0.w + b1.w + b2.w;
    ((float4*)x)[i] = a;
}

// ---------------- launch ----------------
extern "C" void kernel_launch(void* const* d_in, const int* in_sizes, int n_in,
                              void* d_out, int out_size)
{
    const float* inputs  = (const float*)d_in[0];
    const float* sigma   = (const float*)d_in[1];
    const float* phi     = (const float*)d_in[2];
    const float* in_proj = (const float*)d_in[3];
    const float* rn_w    = (const float*)d_in[4];
    const float* M_u     = (const float*)d_in[5];
    const float* M_p     = (const float*)d_in[6];
    const float* M_m     = (const float*)d_in[7];
    const float* fc1     = (const float*)d_in[8];
    const float* fc2     = (const float*)d_in[9];
    const float* out_w   = (const float*)d_in[10];
    float* out = (float*)d_out;

    float *x, *z, *h, *U, *W, *m1, *m2, *part;
    cudaGetSymbolAddress((void**)&x,  g_x);
    cudaGetSymbolAddress((void**)&z,  g_z);
    cudaGetSymbolAddress((void**)&h,  g_h);
    cudaGetSymbolAddress((void**)&U,  g_U);
    cudaGetSymbolAddress((void**)&W,  g_W);
    cudaGetSymbolAddress((void**)&m1, g_m1);
    cudaGetSymbolAddress((void**)&m2, g_m2);
    cudaGetSymbolAddress((void**)&part, g_part);

    const int ew_blocks = (R_ * D_ / 4) / 256;
    const int wfill_blocks = (int)(((size_t)D_ * UCOLS + 255) / 256);
    const int silu_blocks = (R_ * H_) / 256;

    for (int m = 0; m < M_; m++) {
        // x = inputs @ in_proj[m]^T   (2048 x 512, K=64)
        gemm3<64, 128, 16, 64, 1><<<dim3(D_ / 128, R_ / 64), 256>>>(
            inputs, in_proj + (size_t)m * D_ * DIN_, x, R_, D_, DIN_, 0);

        for (int l = 0; l < L_; l++) {
            const int ml = m * L_ + l;

            copy_k<<<ew_blocks, 256>>>(z, x);
            rmsnorm_k<<<R_, 256>>>(x, rn_w + (size_t)ml * D_, h, U);
            conv_tc<<<dim3(D_ / 64, S_ / 128, B_ * K_), 256>>>(h, phi, U);
            wfill_k<<<wfill_blocks, 256>>>(
                sigma,
                M_p + (size_t)ml * K_ * D_ * D_,
                M_m + (size_t)ml * K_ * D_ * D_,
                M_u + (size_t)ml * KU_ * D_ * D_,
                W);
            // partials = U @ W^T  (split-K=3), then x += sum(partials)
            gemm3<128, 128, 32, 64, NSPLIT_><<<dim3(D_ / 128, R_ / 128, NSPLIT_), 256>>>(
                U, W, part, R_, D_, UCOLS, 0);
            reduce3_k<<<ew_blocks, 256>>>(x, part);

            // MLP
            gemm3<128, 128, 32, 64, 1><<<dim3(2 * H_ / 128, R_ / 128), 256>>>(
                x, fc1 + (size_t)ml * 2 * H_ * D_, m1, R_, 2 * H_, D_, 0);
            silu_k<<<silu_blocks, 256>>>(m1, m2);
            gemm3<64, 128, 16, 64, 1><<<dim3(D_ / 128, R_ / 64), 256>>>(
                m2, fc2 + (size_t)ml * D_ * H_, x, R_, D_, H_, 1);

            add_k<<<ew_blocks, 256>>>(x, z);
        }

        // preds += x @ out_proj[m]^T  (N=64)
        gemm_nt<<<dim3(DIN_ / 64, R_ / 64), 256>>>(
            x, out_w + (size_t)m * DIN_ * D_, out, R_, DIN_, D_, m);
    }
    (void)in_sizes; (void)n_in; (void)out_size;
}

// round 6
// speedup vs baseline: 1.7562x; 1.7562x over previous
#include <cuda_runtime.h>
#include <cuda_bf16.h>
#include <cstddef>

// ---------------- problem constants ----------------
#define B_    2
#define S_    1024
#define DIN_  64
#define D_    512
#define K_    16
#define KU_   3
#define L_    2
#define M_    2
#define H_    2048
#define R_    (B_ * S_)                 // 2048 rows (b*S + t)
#define SPECC (2 * K_ * D_)             // 16384 spectral columns of U
#define UCOLS (SPECC + KU_ * D_)        // 17920 = spectral + AR columns
#define EPS_  1e-5f
#define NSPLIT_ 3

typedef unsigned short u16;
typedef unsigned int   u32;

// ---------------- scratch (static device globals; no allocation) ----------------
__device__ __align__(16) float g_x[R_ * D_];
__device__ __align__(16) float g_z[R_ * D_];
__device__ __align__(16) float g_h[R_ * D_];
__device__ __align__(16) float g_part[(size_t)NSPLIT_ * R_ * D_];
__device__ __align__(16) float g_m1[(size_t)R_ * 2 * H_];

__device__ __align__(16) u16 g_Uh[(size_t)R_ * UCOLS];
__device__ __align__(16) u16 g_Ul[(size_t)R_ * UCOLS];
__device__ __align__(16) u16 g_Wh[(size_t)D_ * UCOLS];
__device__ __align__(16) u16 g_Wl[(size_t)D_ * UCOLS];
__device__ __align__(16) u16 g_m2h[(size_t)R_ * H_];
__device__ __align__(16) u16 g_m2l[(size_t)R_ * H_];
__device__ __align__(16) u16 g_hTh[B_ * D_ * S_];
__device__ __align__(16) u16 g_hTl[B_ * D_ * S_];
__device__ __align__(16) u16 g_xh[R_ * D_];
__device__ __align__(16) u16 g_xl[R_ * D_];
__device__ __align__(16) u16 g_inh[R_ * DIN_];
__device__ __align__(16) u16 g_inl[R_ * DIN_];
__device__ __align__(16) u16 g_iph[D_ * DIN_];
__device__ __align__(16) u16 g_ipl[D_ * DIN_];
__device__ __align__(16) u16 g_f1h[2 * H_ * D_];
__device__ __align__(16) u16 g_f1l[2 * H_ * D_];
__device__ __align__(16) u16 g_f2h[D_ * H_];
__device__ __align__(16) u16 g_f2l[D_ * H_];
__device__ __align__(16) u16 g_phih[K_ * S_];
__device__ __align__(16) u16 g_phil[K_ * S_];

// ---------------- bf16 helpers ----------------
__device__ __forceinline__ void split_bf(float a, u16& hi, u16& lo) {
    __nv_bfloat16 h = __float2bfloat16(a);
    float r = a - __bfloat162float(h);
    __nv_bfloat16 l = __float2bfloat16(r);
    hi = reinterpret_cast<u16&>(h);
    lo = reinterpret_cast<u16&>(l);
}

__device__ __forceinline__ void mma_bf16(float c[4],
                                         u32 a0, u32 a1, u32 a2, u32 a3,
                                         u32 b0, u32 b1) {
    asm volatile(
        "mma.sync.aligned.m16n8k16.row.col.f32.bf16.bf16.f32 "
        "{%0,%1,%2,%3},{%4,%5,%6,%7},{%8,%9},{%0,%1,%2,%3};\n"
        : "+f"(c[0]), "+f"(c[1]), "+f"(c[2]), "+f"(c[3])
        : "r"(a0), "r"(a1), "r"(a2), "r"(a3), "r"(b0), "r"(b1));
}

// ---------------- bf16 3-term NT GEMM: C(M,N) = A(M,K) * B(N,K)^T ----------------
// A,B pre-split into (hi, lo) bf16 arrays, row-major [rows][K]. BK=32, 256 threads.
// K % 32 == 0, M % BM == 0, N % BN == 0.
template<int BM, int BN, int WARPS_M, int NSPLIT>
__global__ __launch_bounds__(256) void gemm_bf3(
    const u16* __restrict__ Ah, const u16* __restrict__ Al,
    const u16* __restrict__ Bh, const u16* __restrict__ Bl,
    float* __restrict__ C, int M, int N, int K, int accum)
{
    constexpr int WARPS_N = 8 / WARPS_M;
    constexpr int WM = BM / WARPS_M;
    constexpr int WN = BN / WARPS_N;
    constexpr int MT = WM / 16;
    constexpr int NT = WN / 8;
    __shared__ u32 sAh[BM][20], sAl[BM][20], sBh[BN][20], sBl[BN][20];

    int kb = 0, ke = K;
    if (NSPLIT > 1) {
        const int z = blockIdx.z;
        const int steps = K / 32;
        kb = ((z * steps) / NSPLIT) * 32;
        ke = (((z + 1) * steps) / NSPLIT) * 32;
        C += (size_t)z * M * N;
        accum = 0;
    }

    const int bm = blockIdx.y * BM;
    const int bn = blockIdx.x * BN;
    const int tid  = threadIdx.x;
    const int lane = tid & 31;
    const int warp = tid >> 5;
    const int wm = (warp % WARPS_M) * WM;
    const int wn = (warp / WARPS_M) * WN;
    const int g  = lane >> 2;
    const int tg = lane & 3;

    const int lr  = tid >> 2;        // 0..63
    const int lku = (tid & 3) * 4;   // uint col: 0,4,8,12

    float acc[MT][NT][4] = {};

    for (int k0 = kb; k0 < ke; k0 += 32) {
        uint4 vah[BM / 64], val_[BM / 64], vbh[BN / 64], vbl[BN / 64];
#pragma unroll
        for (int r = 0; r < BM / 64; r++) {
            const size_t off = (size_t)(bm + lr + 64 * r) * K + k0 + lku * 2;
            vah[r]  = *(const uint4*)&Ah[off];
            val_[r] = *(const uint4*)&Al[off];
        }
#pragma unroll
        for (int r = 0; r < BN / 64; r++) {
            const size_t off = (size_t)(bn + lr + 64 * r) * K + k0 + lku * 2;
            vbh[r] = *(const uint4*)&Bh[off];
            vbl[r] = *(const uint4*)&Bl[off];
        }
        __syncthreads();
#pragma unroll
        for (int r = 0; r < BM / 64; r++) {
            *(uint4*)&sAh[lr + 64 * r][lku] = vah[r];
            *(uint4*)&sAl[lr + 64 * r][lku] = val_[r];
        }
#pragma unroll
        for (int r = 0; r < BN / 64; r++) {
            *(uint4*)&sBh[lr + 64 * r][lku] = vbh[r];
            *(uint4*)&sBl[lr + 64 * r][lku] = vbl[r];
        }
        __syncthreads();

#pragma unroll
        for (int ks = 0; ks < 2; ks++) {
            const int ku = ks * 8;
            u32 ah[MT][4], al[MT][4];
#pragma unroll
            for (int mt = 0; mt < MT; mt++) {
                const int row = wm + mt * 16;
                ah[mt][0] = sAh[row + g    ][ku + tg    ];
                ah[mt][1] = sAh[row + g + 8][ku + tg    ];
                ah[mt][2] = sAh[row + g    ][ku + tg + 4];
                ah[mt][3] = sAh[row + g + 8][ku + tg + 4];
                al[mt][0] = sAl[row + g    ][ku + tg    ];
                al[mt][1] = sAl[row + g + 8][ku + tg    ];
                al[mt][2] = sAl[row + g    ][ku + tg + 4];
                al[mt][3] = sAl[row + g + 8][ku + tg + 4];
            }
#pragma unroll
            for (int nt = 0; nt < NT; nt++) {
                const int col = wn + nt * 8 + g;
                const u32 bh0 = sBh[col][ku + tg];
                const u32 bh1 = sBh[col][ku + tg + 4];
                const u32 bl0 = sBl[col][ku + tg];
                const u32 bl1 = sBl[col][ku + tg + 4];
#pragma unroll
                for (int mt = 0; mt < MT; mt++) {
                    mma_bf16(acc[mt][nt], ah[mt][0], ah[mt][1], ah[mt][2], ah[mt][3], bh0, bh1);
                    mma_bf16(acc[mt][nt], al[mt][0], al[mt][1], al[mt][2], al[mt][3], bh0, bh1);
                    mma_bf16(acc[mt][nt], ah[mt][0], ah[mt][1], ah[mt][2], ah[mt][3], bl0, bl1);
                }
            }
        }
        __syncthreads();
    }

#pragma unroll
    for (int mt = 0; mt < MT; mt++) {
        const int r0 = bm + wm + mt * 16 + g;
        const int r1 = r0 + 8;
#pragma unroll
        for (int nt = 0; nt < NT; nt++) {
            const int col = bn + wn + nt * 8 + 2 * tg;
            float2* p0 = (float2*)&C[(size_t)r0 * N + col];
            float2* p1 = (float2*)&C[(size_t)r1 * N + col];
            float2 v0 = make_float2(acc[mt][nt][0], acc[mt][nt][1]);
            float2 v1 = make_float2(acc[mt][nt][2], acc[mt][nt][3]);
            if (accum) {
                float2 o0 = *p0, o1 = *p1;
                v0.x += o0.x; v0.y += o0.y; v1.x += o1.x; v1.y += o1.y;
            }
            *p0 = v0;
            *p1 = v1;
        }
    }
}

// ---------------- causal spectral conv, bf16 3-term Toeplitz MMA ----------------
// grid (D/64, S/128, B*K). B operand = hT (b,d,i) bf16 pairs; A = phi lag window.
__global__ __launch_bounds__(256) void conv_bf(
    const u16* __restrict__ hTh, const u16* __restrict__ hTl,
    const u16* __restrict__ phih, const u16* __restrict__ phil,
    u16* __restrict__ Uh, u16* __restrict__ Ul)
{
    __shared__ u32 sXh[64][20], sXl[64][20];   // [d][i-pair]
    __shared__ u32 Qh[161], Ql[161];           // packed phi pairs: low=phi[lag], high=phi[lag-1]

    const int d0 = blockIdx.x * 64;
    const int t0 = blockIdx.y * 128;
    const int b  = blockIdx.z >> 4;
    const int k  = blockIdx.z & 15;
    const int tid  = threadIdx.x;
    const int lane = tid & 31;
    const int warp = tid >> 5;
    const int wm = (warp & 3) * 32;   // t offset
    const int wn = (warp >> 2) * 32;  // d offset
    const int g  = lane >> 2;
    const int tg = lane & 3;
    // sgn[i] with i = i0 + ks*16 + kk (i0, ks*16 even): sign = (-1)^kk.
    // In each A register, low bf16 = even kk (keep +), high bf16 = odd kk (flip).
    // => flip ONLY the high element's sign bit (bit 31), same mask for all lanes.
    const u32 mk = 0x80000000u;

    float accp[2][4][4] = {};
    float accm[2][4][4] = {};

    const int xr  = tid >> 2;        // 0..63 (d row)
    const int xcu = (tid & 3) * 4;   // uint col
    const int imax = t0 + 128;

    for (int i0 = 0; i0 < imax; i0 += 32) {
        const size_t hoff = (size_t)(b * D_ + d0 + xr) * S_ + i0 + xcu * 2;
        uint4 vh = *(const uint4*)&hTh[hoff];
        uint4 vl = *(const uint4*)&hTl[hoff];
        u32 qh = 0, ql = 0;
        if (tid < 161) {
            const int lag = t0 - i0 - 32 + tid;
            u16 l_h = 0, l_l = 0, h_h = 0, h_l = 0;
            if (lag >= 0 && lag < S_)         { l_h = phih[k * S_ + lag];     l_l = phil[k * S_ + lag]; }
            if (lag - 1 >= 0 && lag - 1 < S_) { h_h = phih[k * S_ + lag - 1]; h_l = phil[k * S_ + lag - 1]; }
            qh = (u32)l_h | ((u32)h_h << 16);
            ql = (u32)l_l | ((u32)h_l << 16);
        }
        __syncthreads();
        *(uint4*)&sXh[xr][xcu] = vh;
        *(uint4*)&sXl[xr][xcu] = vl;
        if (tid < 161) { Qh[tid] = qh; Ql[tid] = ql; }
        __syncthreads();

#pragma unroll
        for (int ks = 0; ks < 2; ks++) {
            const int ku = ks * 8;
            u32 ah[2][3], al[2][3];     // a frag = {q0, q1, q2, q0}
#pragma unroll
            for (int mt = 0; mt < 2; mt++) {
                const int j0 = wm + mt * 16 - ks * 16 + 32 + g - 2 * tg;
                ah[mt][0] = Qh[j0]; ah[mt][1] = Qh[j0 + 8]; ah[mt][2] = Qh[j0 - 8];
                al[mt][0] = Ql[j0]; al[mt][1] = Ql[j0 + 8]; al[mt][2] = Ql[j0 - 8];
            }
#pragma unroll
            for (int nt = 0; nt < 4; nt++) {
                const int col = wn + nt * 8 + g;
                const u32 bh0 = sXh[col][ku + tg];
                const u32 bh1 = sXh[col][ku + tg + 4];
                const u32 bl0 = sXl[col][ku + tg];
                const u32 bl1 = sXl[col][ku + tg + 4];
#pragma unroll
                for (int mt = 0; mt < 2; mt++) {
                    const u32 a0 = ah[mt][0], a1 = ah[mt][1], a2 = ah[mt][2];
                    const u32 c0 = al[mt][0], c1 = al[mt][1], c2 = al[mt][2];
                    mma_bf16(accp[mt][nt], a0, a1, a2, a0, bh0, bh1);
                    mma_bf16(accp[mt][nt], c0, c1, c2, c0, bh0, bh1);
                    mma_bf16(accp[mt][nt], a0, a1, a2, a0, bl0, bl1);
                    mma_bf16(accm[mt][nt], a0 ^ mk, a1 ^ mk, a2 ^ mk, a0 ^ mk, bh0, bh1);
                    mma_bf16(accm[mt][nt], c0 ^ mk, c1 ^ mk, c2 ^ mk, c0 ^ mk, bh0, bh1);
                    mma_bf16(accm[mt][nt], a0 ^ mk, a1 ^ mk, a2 ^ mk, a0 ^ mk, bl0, bl1);
                }
            }
        }
        __syncthreads();
    }

#pragma unroll
    for (int mt = 0; mt < 2; mt++) {
#pragma unroll
        for (int half = 0; half < 2; half++) {
            const int t = t0 + wm + mt * 16 + g + half * 8;
            const float st = (t & 1) ? -1.f : 1.f;
            const size_t row = (size_t)(b * S_ + t) * UCOLS;
#pragma unroll
            for (int nt = 0; nt < 4; nt++) {
                const int d = d0 + wn + nt * 8 + 2 * tg;
                const float cp0 = accp[mt][nt][half * 2 + 0];
                const float cp1 = accp[mt][nt][half * 2 + 1];
                const float cm0 = st * accm[mt][nt][half * 2 + 0];
                const float cm1 = st * accm[mt][nt][half * 2 + 1];
                u16 h0, l0, h1, l1;
                split_bf(cp0, h0, l0); split_bf(cp1, h1, l1);
                *(ushort2*)&Uh[row + (size_t)k * D_ + d] = make_ushort2(h0, h1);
                *(ushort2*)&Ul[row + (size_t)k * D_ + d] = make_ushort2(l0, l1);
                split_bf(cm0, h0, l0); split_bf(cm1, h1, l1);
                *(ushort2*)&Uh[row + (size_t)(K_ + k) * D_ + d] = make_ushort2(h0, h1);
                *(ushort2*)&Ul[row + (size_t)(K_ + k) * D_ + d] = make_ushort2(l0, l1);
            }
        }
    }
}

// ---------------- fp32 NT GEMM (tiny out_proj: N=64) ----------------
__global__ __launch_bounds__(256) void gemm_nt(
    const float* __restrict__ A, const float* __restrict__ B, float* __restrict__ C,
    int M, int N, int K, int accum)
{
    __shared__ float As[16][65];
    __shared__ float Bs[16][65];
    const int bm = blockIdx.y * 64;
    const int bn = blockIdx.x * 64;
    const int tid = threadIdx.x;
    const int tx = tid & 15;
    const int ty = tid >> 4;
    const int lr = tid >> 2;
    const int lk = (tid & 3) << 2;

    const float* Ap = A + (size_t)(bm + lr) * K + lk;
    const float* Bp = B + (size_t)(bn + lr) * K + lk;

    float acc[4][4] = {};

    for (int k0 = 0; k0 < K; k0 += 16) {
        float4 av = *(const float4*)(Ap + k0);
        float4 bv = *(const float4*)(Bp + k0);
        __syncthreads();
        As[lk + 0][lr] = av.x; As[lk + 1][lr] = av.y;
        As[lk + 2][lr] = av.z; As[lk + 3][lr] = av.w;
        Bs[lk + 0][lr] = bv.x; Bs[lk + 1][lr] = bv.y;
        Bs[lk + 2][lr] = bv.z; Bs[lk + 3][lr] = bv.w;
        __syncthreads();
#pragma unroll
        for (int kk = 0; kk < 16; kk++) {
            float a[4], b[4];
#pragma unroll
            for (int i = 0; i < 4; i++) a[i] = As[kk][ty * 4 + i];
#pragma unroll
            for (int j = 0; j < 4; j++) b[j] = Bs[kk][tx * 4 + j];
#pragma unroll
            for (int i = 0; i < 4; i++)
#pragma unroll
                for (int j = 0; j < 4; j++)
                    acc[i][j] += a[i] * b[j];
        }
    }

#pragma unroll
    for (int i = 0; i < 4; i++) {
        const int r = bm + ty * 4 + i;
#pragma unroll
        for (int j = 0; j < 4; j++) {
            const int c = bn + tx * 4 + j;
            const size_t idx = (size_t)r * N + c;
            C[idx] = accum ? (C[idx] + acc[i][j]) : acc[i][j];
        }
    }
}

// ---------------- rmsnorm + AR column scatter (bf16 pairs) ----------------
__global__ __launch_bounds__(256) void rmsnorm_k(
    const float* __restrict__ x, const float* __restrict__ w,
    float* __restrict__ h, u16* __restrict__ Uh, u16* __restrict__ Ul)
{
    __shared__ float red[256];
    const int row = blockIdx.x;
    const int t = row & (S_ - 1);
    const int tid = threadIdx.x;

    const float v0 = x[(size_t)row * D_ + tid];
    const float v1 = x[(size_t)row * D_ + 256 + tid];
    red[tid] = v0 * v0 + v1 * v1;
    __syncthreads();
    for (int s = 128; s > 0; s >>= 1) {
        if (tid < s) red[tid] += red[tid + s];
        __syncthreads();
    }
    const float scale = rsqrtf(red[0] * (1.f / D_) + EPS_);
    const float h0 = v0 * scale * w[tid];
    const float h1 = v1 * scale * w[tid + 256];
    h[(size_t)row * D_ + tid] = h0;
    h[(size_t)row * D_ + 256 + tid] = h1;

    u16 h0h, h0l, h1h, h1l;
    split_bf(h0, h0h, h0l); split_bf(h1, h1h, h1l);

#pragma unroll
    for (int j = 0; j < KU_; j++) {
        if (t + j < S_) {
            const size_t base = (size_t)(row + j) * UCOLS + SPECC + j * D_;
            Uh[base + tid] = h0h; Ul[base + tid] = h0l;
            Uh[base + 256 + tid] = h1h; Ul[base + 256 + tid] = h1l;
        }
        if (t < j) {
            const size_t base = (size_t)row * UCOLS + SPECC + j * D_;
            Uh[base + tid] = 0; Ul[base + tid] = 0;
            Uh[base + 256 + tid] = 0; Ul[base + 256 + tid] = 0;
        }
    }
}

// ---------------- transpose + split h -> hT pairs ----------------
// grid (S/32, D/32, B), block 256 (32x8)
__global__ __launch_bounds__(256) void transplit_k(
    const float* __restrict__ h, u16* __restrict__ hTh, u16* __restrict__ hTl)
{
    __shared__ float tile[32][33];
    const int i0 = blockIdx.x * 32;
    const int d0 = blockIdx.y * 32;
    const int b  = blockIdx.z;
    const int tx = threadIdx.x & 31;
    const int ty = threadIdx.x >> 5;
#pragma unroll
    for (int r = 0; r < 4; r++)
        tile[ty + 8 * r][tx] = h[(size_t)(b * S_ + i0 + ty + 8 * r) * D_ + d0 + tx];
    __syncthreads();
#pragma unroll
    for (int r = 0; r < 4; r++) {
        const float v = tile[tx][ty + 8 * r];
        u16 hi, lo; split_bf(v, hi, lo);
        const size_t o = (size_t)(b * D_ + d0 + ty + 8 * r) * S_ + i0 + tx;
        hTh[o] = hi; hTl[o] = lo;
    }
}

// ---------------- fused weight fill (bf16 pairs) ----------------
__global__ __launch_bounds__(256) void wfill_k(
    const float* __restrict__ sigma, const float* __restrict__ mp,
    const float* __restrict__ mm, const float* __restrict__ mu,
    u16* __restrict__ Wh, u16* __restrict__ Wl)
{
    const size_t idx = (size_t)blockIdx.x * 256 + threadIdx.x;
    if (idx >= (size_t)D_ * UCOLS) return;
    const int o = (int)(idx / UCOLS);
    const int col = (int)(idx % UCOLS);
    float v;
    if (col < K_ * D_) {
        const int k = col / D_, d = col % D_;
        v = sqrtf(sqrtf(sigma[k])) * mp[((size_t)k * D_ + d) * D_ + o];
    } else if (col < SPECC) {
        const int c = col - K_ * D_;
        const int k = c / D_, d = c % D_;
        v = sqrtf(sqrtf(sigma[k])) * mm[((size_t)k * D_ + d) * D_ + o];
    } else {
        const int c = col - SPECC;
        const int j = c / D_, d = c % D_;
        v = mu[((size_t)j * D_ + d) * D_ + o];
    }
    u16 hi, lo; split_bf(v, hi, lo);
    Wh[idx] = hi; Wl[idx] = lo;
}

// ---------------- generic split ----------------
__global__ __launch_bounds__(256) void split_k(
    const float* __restrict__ src, u16* __restrict__ hi, u16* __restrict__ lo, int n)
{
    const int i = blockIdx.x * 256 + threadIdx.x;
    if (i < n) { u16 h, l; split_bf(src[i], h, l); hi[i] = h; lo[i] = l; }
}

// ---------------- phi transpose + split: phi[lag][k] -> phiT pairs [k][lag] ----------------
__global__ __launch_bounds__(256) void phisplit_k(
    const float* __restrict__ phi, u16* __restrict__ ph, u16* __restrict__ pl)
{
    const int i = blockIdx.x * 256 + threadIdx.x;   // over K_*S_
    if (i >= K_ * S_) return;
    const int k = i / S_, lag = i % S_;
    u16 h, l; split_bf(phi[lag * K_ + k], h, l);
    ph[i] = h; pl[i] = l;
}

// ---------------- elementwise ----------------
__global__ __launch_bounds__(256) void silu_k(
    const float* __restrict__ m1, u16* __restrict__ m2h, u16* __restrict__ m2l)
{
    const int idx = blockIdx.x * 256 + threadIdx.x;
    const int r = idx >> 11;
    const int j = idx & (H_ - 1);
    const float y = m1[(size_t)r * (2 * H_) + j];
    const float gg = m1[(size_t)r * (2 * H_) + H_ + j];
    const float v = y * gg / (1.f + expf(-gg));
    u16 h, l; split_bf(v, h, l);
    m2h[idx] = h; m2l[idx] = l;
}

__global__ __launch_bounds__(256) void copy_k(float* __restrict__ dst, const float* __restrict__ src)
{
    const int i = blockIdx.x * 256 + threadIdx.x;
    ((float4*)dst)[i] = ((const float4*)src)[i];
}

__global__ __launch_bounds__(256) void add_k(float* __restrict__ dst, const float* __restrict__ src)
{
    const int i = blockIdx.x * 256 + threadIdx.x;
    float4 a = ((const float4*)dst)[i];
    float4 b = ((const float4*)src)[i];
    a.x += b.x; a.y += b.y; a.z += b.z; a.w += b.w;
    ((float4*)dst)[i] = a;
}

// x += p0+p1+p2, and emit bf16 split of new x
__global__ __launch_bounds__(256) void reduce3_k(
    float* __restrict__ x, const float* __restrict__ p,
    u16* __restrict__ xh, u16* __restrict__ xl)
{
    const int i = blockIdx.x * 256 + threadIdx.x;   // over R_*D_/4
    const size_t MN4 = (size_t)R_ * D_ / 4;
    float4 a = ((const float4*)x)[i];
    float4 b0 = ((const float4*)p)[i];
    float4 b1 = ((const float4*)p)[i + MN4];
    float4 b2 = ((const float4*)p)[i + 2 * MN4];
    a.x += b0.x + b1.x + b2.x;
    a.y += b0.y + b1.y + b2.y;
    a.z += b0.z + b1.z + b2.z;
    a.w += b0.w + b1.w + b2.w;
    ((float4*)x)[i] = a;
    ushort4 vh, vl;
    split_bf(a.x, vh.x, vl.x); split_bf(a.y, vh.y, vl.y);
    split_bf(a.z, vh.z, vl.z); split_bf(a.w, vh.w, vl.w);
    ((ushort4*)xh)[i] = vh;
    ((ushort4*)xl)[i] = vl;
}

// ---------------- launch ----------------
extern "C" void kernel_launch(void* const* d_in, const int* in_sizes, int n_in,
                              void* d_out, int out_size)
{
    const float* inputs  = (const float*)d_in[0];
    const float* sigma   = (const float*)d_in[1];
    const float* phi     = (const float*)d_in[2];
    const float* in_proj = (const float*)d_in[3];
    const float* rn_w    = (const float*)d_in[4];
    const float* M_u     = (const float*)d_in[5];
    const float* M_p     = (const float*)d_in[6];
    const float* M_m     = (const float*)d_in[7];
    const float* fc1     = (const float*)d_in[8];
    const float* fc2     = (const float*)d_in[9];
    const float* out_w   = (const float*)d_in[10];
    float* out = (float*)d_out;

    float *x, *z, *h, *part, *m1;
    u16 *Uh, *Ul, *Wh, *Wl, *m2h, *m2l, *hTh, *hTl, *xh, *xl;
    u16 *inh, *inl, *iph, *ipl, *f1h, *f1l, *f2h, *f2l, *phh, *phl;
    cudaGetSymbolAddress((void**)&x,   g_x);
    cudaGetSymbolAddress((void**)&z,   g_z);
    cudaGetSymbolAddress((void**)&h,   g_h);
    cudaGetSymbolAddress((void**)&part,g_part);
    cudaGetSymbolAddress((void**)&m1,  g_m1);
    cudaGetSymbolAddress((void**)&Uh,  g_Uh);
    cudaGetSymbolAddress((void**)&Ul,  g_Ul);
    cudaGetSymbolAddress((void**)&Wh,  g_Wh);
    cudaGetSymbolAddress((void**)&Wl,  g_Wl);
    cudaGetSymbolAddress((void**)&m2h, g_m2h);
    cudaGetSymbolAddress((void**)&m2l, g_m2l);
    cudaGetSymbolAddress((void**)&hTh, g_hTh);
    cudaGetSymbolAddress((void**)&hTl, g_hTl);
    cudaGetSymbolAddress((void**)&xh,  g_xh);
    cudaGetSymbolAddress((void**)&xl,  g_xl);
    cudaGetSymbolAddress((void**)&inh, g_inh);
    cudaGetSymbolAddress((void**)&inl, g_inl);
    cudaGetSymbolAddress((void**)&iph, g_iph);
    cudaGetSymbolAddress((void**)&ipl, g_ipl);
    cudaGetSymbolAddress((void**)&f1h, g_f1h);
    cudaGetSymbolAddress((void**)&f1l, g_f1l);
    cudaGetSymbolAddress((void**)&f2h, g_f2h);
    cudaGetSymbolAddress((void**)&f2l, g_f2l);
    cudaGetSymbolAddress((void**)&phh, g_phih);
    cudaGetSymbolAddress((void**)&phl, g_phil);

    const int ew_blocks = (R_ * D_ / 4) / 256;
    const int wfill_blocks = (int)(((size_t)D_ * UCOLS + 255) / 256);
    const int silu_blocks = (R_ * H_) / 256;

    phisplit_k<<<(K_ * S_ + 255) / 256, 256>>>(phi, phh, phl);
    split_k<<<(R_ * DIN_ + 255) / 256, 256>>>(inputs, inh, inl, R_ * DIN_);

    for (int m = 0; m < M_; m++) {
        // x = inputs @ in_proj[m]^T   (2048 x 512, K=64)
        split_k<<<(D_ * DIN_ + 255) / 256, 256>>>(
            in_proj + (size_t)m * D_ * DIN_, iph, ipl, D_ * DIN_);
        gemm_bf3<64, 128, 2, 1><<<dim3(D_ / 128, R_ / 64), 256>>>(
            inh, inl, iph, ipl, x, R_, D_, DIN_, 0);

        for (int l = 0; l < L_; l++) {
            const int ml = m * L_ + l;

            copy_k<<<ew_blocks, 256>>>(z, x);
            rmsnorm_k<<<R_, 256>>>(x, rn_w + (size_t)ml * D_, h, Uh, Ul);
            transplit_k<<<dim3(S_ / 32, D_ / 32, B_), 256>>>(h, hTh, hTl);
            conv_bf<<<dim3(D_ / 64, S_ / 128, B_ * K_), 256>>>(hTh, hTl, phh, phl, Uh, Ul);
            wfill_k<<<wfill_blocks, 256>>>(
                sigma,
                M_p + (size_t)ml * K_ * D_ * D_,
                M_m + (size_t)ml * K_ * D_ * D_,
                M_u + (size_t)ml * KU_ * D_ * D_,
                Wh, Wl);
            // partials = U @ W^T (split-K=3); x += sum; emit x split for fc1
            gemm_bf3<128, 128, 4, NSPLIT_><<<dim3(D_ / 128, R_ / 128, NSPLIT_), 256>>>(
                Uh, Ul, Wh, Wl, part, R_, D_, UCOLS, 0);
            reduce3_k<<<ew_blocks, 256>>>(x, part, xh, xl);

            // MLP
            split_k<<<(2 * H_ * D_ + 255) / 256, 256>>>(
                fc1 + (size_t)ml * 2 * H_ * D_, f1h, f1l, 2 * H_ * D_);
            gemm_bf3<128, 128, 4, 1><<<dim3(2 * H_ / 128, R_ / 128), 256>>>(
                xh, xl, f1h, f1l, m1, R_, 2 * H_, D_, 0);
            silu_k<<<silu_blocks, 256>>>(m1, m2h, m2l);
            split_k<<<(D_ * H_ + 255) / 256, 256>>>(
                fc2 + (size_t)ml * D_ * H_, f2h, f2l, D_ * H_);
            gemm_bf3<64, 128, 2, 1><<<dim3(D_ / 128, R_ / 64), 256>>>(
                m2h, m2l, f2h, f2l, x, R_, D_, H_, 1);

            add_k<<<ew_blocks, 256>>>(x, z);
        }

        // preds += x @ out_proj[m]^T  (N=64)
        gemm_nt<<<dim3(DIN_ / 64, R_ / 64), 256>>>(
            x, out_w + (size_t)m * DIN_ * D_, out, R_, DIN_, D_, m);
    }
    (void)in_sizes; (void)n_in; (void)out_size;
}

// round 7
// speedup vs baseline: 2.0782x; 1.1834x over previous
#include <cuda_runtime.h>
#include <cuda_bf16.h>
#include <cstddef>

// ---------------- problem constants ----------------
#define B_    2
#define S_    1024
#define DIN_  64
#define D_    512
#define K_    16
#define KU_   3
#define L_    2
#define M_    2
#define H_    2048
#define R_    (B_ * S_)                 // 2048 rows (b*S + t)
#define SPECC (2 * K_ * D_)             // 16384 spectral columns of U
#define UCOLS (SPECC + KU_ * D_)        // 17920 = spectral + AR columns
#define EPS_  1e-5f
#define NSPLIT_ 4
#define P2LEN 1280                      // phi pair table length per k (lag+128)

typedef unsigned short u16;
typedef unsigned int   u32;

// ---------------- scratch (static device globals; no allocation) ----------------
__device__ __align__(16) float g_x[R_ * D_];
__device__ __align__(16) float g_z[R_ * D_];
__device__ __align__(16) float g_h[R_ * D_];
__device__ __align__(16) float g_part[(size_t)NSPLIT_ * R_ * D_];
__device__ __align__(16) float g_m1[(size_t)R_ * 2 * H_];

__device__ __align__(16) u16 g_Uh[(size_t)R_ * UCOLS];
__device__ __align__(16) u16 g_Ul[(size_t)R_ * UCOLS];
__device__ __align__(16) u16 g_Wh[(size_t)D_ * UCOLS];
__device__ __align__(16) u16 g_Wl[(size_t)D_ * UCOLS];
__device__ __align__(16) u16 g_m2h[(size_t)R_ * H_];
__device__ __align__(16) u16 g_m2l[(size_t)R_ * H_];
__device__ __align__(16) u16 g_hTh[B_ * D_ * S_];
__device__ __align__(16) u16 g_hTl[B_ * D_ * S_];
__device__ __align__(16) u16 g_xh[R_ * D_];
__device__ __align__(16) u16 g_xl[R_ * D_];
__device__ __align__(16) u16 g_inh[R_ * DIN_];
__device__ __align__(16) u16 g_inl[R_ * DIN_];
__device__ __align__(16) u16 g_iph[D_ * DIN_];
__device__ __align__(16) u16 g_ipl[D_ * DIN_];
__device__ __align__(16) u16 g_f1h[2 * H_ * D_];
__device__ __align__(16) u16 g_f1l[2 * H_ * D_];
__device__ __align__(16) u16 g_f2h[D_ * H_];
__device__ __align__(16) u16 g_f2l[D_ * H_];
__device__ __align__(16) u32 g_P2h[K_ * P2LEN];
__device__ __align__(16) u32 g_P2l[K_ * P2LEN];

// ---------------- helpers ----------------
__device__ __forceinline__ void split_bf(float a, u16& hi, u16& lo) {
    __nv_bfloat16 h = __float2bfloat16(a);
    float r = a - __bfloat162float(h);
    __nv_bfloat16 l = __float2bfloat16(r);
    hi = reinterpret_cast<u16&>(h);
    lo = reinterpret_cast<u16&>(l);
}

__device__ __forceinline__ void mma_bf16(float c[4],
                                         u32 a0, u32 a1, u32 a2, u32 a3,
                                         u32 b0, u32 b1) {
    asm volatile(
        "mma.sync.aligned.m16n8k16.row.col.f32.bf16.bf16.f32 "
        "{%0,%1,%2,%3},{%4,%5,%6,%7},{%8,%9},{%0,%1,%2,%3};\n"
        : "+f"(c[0]), "+f"(c[1]), "+f"(c[2]), "+f"(c[3])
        : "r"(a0), "r"(a1), "r"(a2), "r"(a3), "r"(b0), "r"(b1));
}

__device__ __forceinline__ void cp16(u32* smem_dst, const void* gsrc) {
    unsigned saddr = (unsigned)__cvta_generic_to_shared(smem_dst);
    asm volatile("cp.async.cg.shared.global [%0], [%1], 16;\n" :: "r"(saddr), "l"(gsrc));
}
#define CP_COMMIT() asm volatile("cp.async.commit_group;\n" ::: "memory")
#define CP_WAIT1()  asm volatile("cp.async.wait_group 1;\n" ::: "memory")

// ---------------- bf16 3-term NT GEMM, cp.async 2-stage pipeline ----------------
// C(M,N) = A(M,K) * B(N,K)^T. A,B pre-split bf16 (hi, lo). K%32==0.
template<int BM, int BN, int WARPS_M, int NSPLIT>
__global__ __launch_bounds__(256) void gemm_bf3(
    const u16* __restrict__ Ah, const u16* __restrict__ Al,
    const u16* __restrict__ Bh, const u16* __restrict__ Bl,
    float* __restrict__ C, int M, int N, int K, int accum)
{
    constexpr int WARPS_N = 8 / WARPS_M;
    constexpr int WM = BM / WARPS_M;
    constexpr int WN = BN / WARPS_N;
    constexpr int MT = WM / 16;
    constexpr int NT = WN / 8;
    constexpr int AOFF  = 0;
    constexpr int ALOFF = BM * 20;
    constexpr int BOFF  = 2 * BM * 20;
    constexpr int BLOFF = 2 * BM * 20 + BN * 20;
    constexpr int STAGE = 2 * (BM + BN) * 20;   // u32 per stage
    extern __shared__ __align__(16) u32 dsm[];

    int kb = 0, ke = K;
    if (NSPLIT > 1) {
        const int z = blockIdx.z;
        const int steps = K / 32;
        kb = ((z * steps) / NSPLIT) * 32;
        ke = (((z + 1) * steps) / NSPLIT) * 32;
        C += (size_t)z * M * N;
        accum = 0;
    }

    const int bm = blockIdx.y * BM;
    const int bn = blockIdx.x * BN;
    const int tid  = threadIdx.x;
    const int lane = tid & 31;
    const int warp = tid >> 5;
    const int wm = (warp % WARPS_M) * WM;
    const int wn = (warp / WARPS_M) * WN;
    const int g  = lane >> 2;
    const int tg = lane & 3;

    const int lr = tid >> 2;        // 0..63
    const int c4 = (tid & 3) * 4;   // u32 chunk offset (16B)

    auto issue = [&](int k0, int s) {
        u32* base = dsm + s * STAGE;
#pragma unroll
        for (int r = 0; r < BM / 64; r++) {
            const int row = lr + 64 * r;
            const size_t go = (size_t)(bm + row) * K + k0 + c4 * 2;
            cp16(base + AOFF  + row * 20 + c4, &Ah[go]);
            cp16(base + ALOFF + row * 20 + c4, &Al[go]);
        }
#pragma unroll
        for (int r = 0; r < BN / 64; r++) {
            const int row = lr + 64 * r;
            const size_t go = (size_t)(bn + row) * K + k0 + c4 * 2;
            cp16(base + BOFF  + row * 20 + c4, &Bh[go]);
            cp16(base + BLOFF + row * 20 + c4, &Bl[go]);
        }
    };

    float acc[MT][NT][4] = {};

    const int nIters = (ke - kb) / 32;
    issue(kb, 0); CP_COMMIT();

    for (int i = 0; i < nIters; i++) {
        if (i + 1 < nIters) issue(kb + (i + 1) * 32, (i + 1) & 1);
        CP_COMMIT();
        CP_WAIT1();
        __syncthreads();
        const u32* base = dsm + (i & 1) * STAGE;

#pragma unroll
        for (int ks = 0; ks < 2; ks++) {
            const int ku = ks * 8;
            u32 ah[MT][4], al[MT][4];
#pragma unroll
            for (int mt = 0; mt < MT; mt++) {
                const int row = wm + mt * 16;
                ah[mt][0] = base[AOFF + (row + g    ) * 20 + ku + tg    ];
                ah[mt][1] = base[AOFF + (row + g + 8) * 20 + ku + tg    ];
                ah[mt][2] = base[AOFF + (row + g    ) * 20 + ku + tg + 4];
                ah[mt][3] = base[AOFF + (row + g + 8) * 20 + ku + tg + 4];
                al[mt][0] = base[ALOFF + (row + g    ) * 20 + ku + tg    ];
                al[mt][1] = base[ALOFF + (row + g + 8) * 20 + ku + tg    ];
                al[mt][2] = base[ALOFF + (row + g    ) * 20 + ku + tg + 4];
                al[mt][3] = base[ALOFF + (row + g + 8) * 20 + ku + tg + 4];
            }
#pragma unroll
            for (int nt = 0; nt < NT; nt++) {
                const int col = wn + nt * 8 + g;
                const u32 bh0 = base[BOFF  + col * 20 + ku + tg];
                const u32 bh1 = base[BOFF  + col * 20 + ku + tg + 4];
                const u32 bl0 = base[BLOFF + col * 20 + ku + tg];
                const u32 bl1 = base[BLOFF + col * 20 + ku + tg + 4];
#pragma unroll
                for (int mt = 0; mt < MT; mt++) {
                    mma_bf16(acc[mt][nt], ah[mt][0], ah[mt][1], ah[mt][2], ah[mt][3], bh0, bh1);
                    mma_bf16(acc[mt][nt], al[mt][0], al[mt][1], al[mt][2], al[mt][3], bh0, bh1);
                    mma_bf16(acc[mt][nt], ah[mt][0], ah[mt][1], ah[mt][2], ah[mt][3], bl0, bl1);
                }
            }
        }
        __syncthreads();
    }

#pragma unroll
    for (int mt = 0; mt < MT; mt++) {
        const int r0 = bm + wm + mt * 16 + g;
        const int r1 = r0 + 8;
#pragma unroll
        for (int nt = 0; nt < NT; nt++) {
            const int col = bn + wn + nt * 8 + 2 * tg;
            float2* p0 = (float2*)&C[(size_t)r0 * N + col];
            float2* p1 = (float2*)&C[(size_t)r1 * N + col];
            float2 v0 = make_float2(acc[mt][nt][0], acc[mt][nt][1]);
            float2 v1 = make_float2(acc[mt][nt][2], acc[mt][nt][3]);
            if (accum) {
                float2 o0 = *p0, o1 = *p1;
                v0.x += o0.x; v0.y += o0.y; v1.x += o1.x; v1.y += o1.y;
            }
            *p0 = v0;
            *p1 = v1;
        }
    }
}

// ---------------- causal spectral conv, cp.async 3-stage pipeline ----------------
// grid (D/64, S/128, B*K). B operand = hT (b,d,i) bf16 pairs; A = P2 phi pair window.
__global__ __launch_bounds__(256) void conv_bf(
    const u16* __restrict__ hTh, const u16* __restrict__ hTl,
    const u32* __restrict__ P2h, const u32* __restrict__ P2l,
    u16* __restrict__ Uh, u16* __restrict__ Ul)
{
    constexpr int CXH = 0;
    constexpr int CXL = 64 * 20;
    constexpr int CQH = 2 * 64 * 20;
    constexpr int CQL = CQH + 164;
    constexpr int CSTAGE = 2 * 64 * 20 + 2 * 164;   // 2888 u32
    __shared__ __align__(16) u32 csm[3 * CSTAGE];

    const int d0 = blockIdx.x * 64;
    const int t0 = blockIdx.y * 128;
    const int b  = blockIdx.z >> 4;
    const int k  = blockIdx.z & 15;
    const int tid  = threadIdx.x;
    const int lane = tid & 31;
    const int warp = tid >> 5;
    const int wm = (warp & 3) * 32;   // t offset
    const int wn = (warp >> 2) * 32;  // d offset
    const int g  = lane >> 2;
    const int tg = lane & 3;
    // sgn[i], i = even_base + kk: sign = (-1)^kk; low bf16 = even kk, high = odd kk.
    const u32 mk = 0x80000000u;

    const int xr = tid >> 2;        // 0..63 (d row)
    const int c4 = (tid & 3) * 4;   // u32 chunk

    auto issue = [&](int i0, int s) {
        u32* base = csm + s * CSTAGE;
        const size_t go = (size_t)(b * D_ + d0 + xr) * S_ + i0 + c4 * 2;
        cp16(base + CXH + xr * 20 + c4, &hTh[go]);
        cp16(base + CXL + xr * 20 + c4, &hTl[go]);
        const int p0 = t0 - i0 + 96;   // multiple of 32 -> 128B aligned
        if (tid < 41)
            cp16(base + CQH + tid * 4, &P2h[k * P2LEN + p0 + tid * 4]);
        else if (tid >= 64 && tid < 105)
            cp16(base + CQL + (tid - 64) * 4, &P2l[k * P2LEN + p0 + (tid - 64) * 4]);
    };

    float accp[2][4][4] = {};
    float accm[2][4][4] = {};

    const int nIters = (t0 + 128) / 32;   // >= 4
    issue(0, 0); CP_COMMIT();
    issue(32, 1); CP_COMMIT();

    for (int i = 0; i < nIters; i++) {
        CP_WAIT1();
        __syncthreads();
        if (i + 2 < nIters) issue((i + 2) * 32, (i + 2) % 3);
        CP_COMMIT();
        const u32* base = csm + (i % 3) * CSTAGE;
        const u32* sQh = base + CQH;
        const u32* sQl = base + CQL;

#pragma unroll
        for (int ks = 0; ks < 2; ks++) {
            const int ku = ks * 8;
            u32 ah[2][3], al[2][3];     // a frag = {q0, q1, q2, q0}
#pragma unroll
            for (int mt = 0; mt < 2; mt++) {
                const int j0 = wm + mt * 16 - ks * 16 + 32 + g - 2 * tg;
                ah[mt][0] = sQh[j0]; ah[mt][1] = sQh[j0 + 8]; ah[mt][2] = sQh[j0 - 8];
                al[mt][0] = sQl[j0]; al[mt][1] = sQl[j0 + 8]; al[mt][2] = sQl[j0 - 8];
            }
#pragma unroll
            for (int nt = 0; nt < 4; nt++) {
                const int col = wn + nt * 8 + g;
                const u32 bh0 = base[CXH + col * 20 + ku + tg];
                const u32 bh1 = base[CXH + col * 20 + ku + tg + 4];
                const u32 bl0 = base[CXL + col * 20 + ku + tg];
                const u32 bl1 = base[CXL + col * 20 + ku + tg + 4];
#pragma unroll
                for (int mt = 0; mt < 2; mt++) {
                    const u32 a0 = ah[mt][0], a1 = ah[mt][1], a2 = ah[mt][2];
                    const u32 c0 = al[mt][0], c1 = al[mt][1], c2 = al[mt][2];
                    mma_bf16(accp[mt][nt], a0, a1, a2, a0, bh0, bh1);
                    mma_bf16(accp[mt][nt], c0, c1, c2, c0, bh0, bh1);
                    mma_bf16(accp[mt][nt], a0, a1, a2, a0, bl0, bl1);
                    mma_bf16(accm[mt][nt], a0 ^ mk, a1 ^ mk, a2 ^ mk, a0 ^ mk, bh0, bh1);
                    mma_bf16(accm[mt][nt], c0 ^ mk, c1 ^ mk, c2 ^ mk, c0 ^ mk, bh0, bh1);
                    mma_bf16(accm[mt][nt], a0 ^ mk, a1 ^ mk, a2 ^ mk, a0 ^ mk, bl0, bl1);
                }
            }
        }
        __syncthreads();
    }

#pragma unroll
    for (int mt = 0; mt < 2; mt++) {
#pragma unroll
        for (int half = 0; half < 2; half++) {
            const int t = t0 + wm + mt * 16 + g + half * 8;
            const float st = (t & 1) ? -1.f : 1.f;
            const size_t row = (size_t)(b * S_ + t) * UCOLS;
#pragma unroll
            for (int nt = 0; nt < 4; nt++) {
                const int d = d0 + wn + nt * 8 + 2 * tg;
                const float cp0 = accp[mt][nt][half * 2 + 0];
                const float cp1 = accp[mt][nt][half * 2 + 1];
                const float cm0 = st * accm[mt][nt][half * 2 + 0];
                const float cm1 = st * accm[mt][nt][half * 2 + 1];
                u16 h0, l0, h1, l1;
                split_bf(cp0, h0, l0); split_bf(cp1, h1, l1);
                *(ushort2*)&Uh[row + (size_t)k * D_ + d] = make_ushort2(h0, h1);
                *(ushort2*)&Ul[row + (size_t)k * D_ + d] = make_ushort2(l0, l1);
                split_bf(cm0, h0, l0); split_bf(cm1, h1, l1);
                *(ushort2*)&Uh[row + (size_t)(K_ + k) * D_ + d] = make_ushort2(h0, h1);
                *(ushort2*)&Ul[row + (size_t)(K_ + k) * D_ + d] = make_ushort2(l0, l1);
            }
        }
    }
}

// ---------------- fp32 NT GEMM (tiny out_proj: N=64) ----------------
__global__ __launch_bounds__(256) void gemm_nt(
    const float* __restrict__ A, const float* __restrict__ B, float* __restrict__ C,
    int M, int N, int K, int accum)
{
    __shared__ float As[16][65];
    __shared__ float Bs[16][65];
    const int bm = blockIdx.y * 64;
    const int bn = blockIdx.x * 64;
    const int tid = threadIdx.x;
    const int tx = tid & 15;
    const int ty = tid >> 4;
    const int lr = tid >> 2;
    const int lk = (tid & 3) << 2;

    const float* Ap = A + (size_t)(bm + lr) * K + lk;
    const float* Bp = B + (size_t)(bn + lr) * K + lk;

    float acc[4][4] = {};

    for (int k0 = 0; k0 < K; k0 += 16) {
        float4 av = *(const float4*)(Ap + k0);
        float4 bv = *(const float4*)(Bp + k0);
        __syncthreads();
        As[lk + 0][lr] = av.x; As[lk + 1][lr] = av.y;
        As[lk + 2][lr] = av.z; As[lk + 3][lr] = av.w;
        Bs[lk + 0][lr] = bv.x; Bs[lk + 1][lr] = bv.y;
        Bs[lk + 2][lr] = bv.z; Bs[lk + 3][lr] = bv.w;
        __syncthreads();
#pragma unroll
        for (int kk = 0; kk < 16; kk++) {
            float a[4], b[4];
#pragma unroll
            for (int i = 0; i < 4; i++) a[i] = As[kk][ty * 4 + i];
#pragma unroll
            for (int j = 0; j < 4; j++) b[j] = Bs[kk][tx * 4 + j];
#pragma unroll
            for (int i = 0; i < 4; i++)
#pragma unroll
                for (int j = 0; j < 4; j++)
                    acc[i][j] += a[i] * b[j];
        }
    }

#pragma unroll
    for (int i = 0; i < 4; i++) {
        const int r = bm + ty * 4 + i;
#pragma unroll
        for (int j = 0; j < 4; j++) {
            const int c = bn + tx * 4 + j;
            const size_t idx = (size_t)r * N + c;
            C[idx] = accum ? (C[idx] + acc[i][j]) : acc[i][j];
        }
    }
}

// ---------------- rmsnorm + AR column scatter (bf16 pairs) ----------------
__global__ __launch_bounds__(256) void rmsnorm_k(
    const float* __restrict__ x, const float* __restrict__ w,
    float* __restrict__ h, u16* __restrict__ Uh, u16* __restrict__ Ul)
{
    __shared__ float red[256];
    const int row = blockIdx.x;
    const int t = row & (S_ - 1);
    const int tid = threadIdx.x;

    const float v0 = x[(size_t)row * D_ + tid];
    const float v1 = x[(size_t)row * D_ + 256 + tid];
    red[tid] = v0 * v0 + v1 * v1;
    __syncthreads();
    for (int s = 128; s > 0; s >>= 1) {
        if (tid < s) red[tid] += red[tid + s];
        __syncthreads();
    }
    const float scale = rsqrtf(red[0] * (1.f / D_) + EPS_);
    const float h0 = v0 * scale * w[tid];
    const float h1 = v1 * scale * w[tid + 256];
    h[(size_t)row * D_ + tid] = h0;
    h[(size_t)row * D_ + 256 + tid] = h1;

    u16 h0h, h0l, h1h, h1l;
    split_bf(h0, h0h, h0l); split_bf(h1, h1h, h1l);

#pragma unroll
    for (int j = 0; j < KU_; j++) {
        if (t + j < S_) {
            const size_t base = (size_t)(row + j) * UCOLS + SPECC + j * D_;
            Uh[base + tid] = h0h; Ul[base + tid] = h0l;
            Uh[base + 256 + tid] = h1h; Ul[base + 256 + tid] = h1l;
        }
        if (t < j) {
            const size_t base = (size_t)row * UCOLS + SPECC + j * D_;
            Uh[base + tid] = 0; Ul[base + tid] = 0;
            Uh[base + 256 + tid] = 0; Ul[base + 256 + tid] = 0;
        }
    }
}

// ---------------- transpose + split h -> hT pairs ----------------
__global__ __launch_bounds__(256) void transplit_k(
    const float* __restrict__ h, u16* __restrict__ hTh, u16* __restrict__ hTl)
{
    __shared__ float tile[32][33];
    const int i0 = blockIdx.x * 32;
    const int d0 = blockIdx.y * 32;
    const int b  = blockIdx.z;
    const int tx = threadIdx.x & 31;
    const int ty = threadIdx.x >> 5;
#pragma unroll
    for (int r = 0; r < 4; r++)
        tile[ty + 8 * r][tx] = h[(size_t)(b * S_ + i0 + ty + 8 * r) * D_ + d0 + tx];
    __syncthreads();
#pragma unroll
    for (int r = 0; r < 4; r++) {
        const float v = tile[tx][ty + 8 * r];
        u16 hi, lo; split_bf(v, hi, lo);
        const size_t o = (size_t)(b * D_ + d0 + ty + 8 * r) * S_ + i0 + tx;
        hTh[o] = hi; hTl[o] = lo;
    }
}

// ---------------- fused weight fill (bf16 pairs) ----------------
__global__ __launch_bounds__(256) void wfill_k(
    const float* __restrict__ sigma, const float* __restrict__ mp,
    const float* __restrict__ mm, const float* __restrict__ mu,
    u16* __restrict__ Wh, u16* __restrict__ Wl)
{
    const size_t idx = (size_t)blockIdx.x * 256 + threadIdx.x;
    if (idx >= (size_t)D_ * UCOLS) return;
    const int o = (int)(idx / UCOLS);
    const int col = (int)(idx % UCOLS);
    float v;
    if (col < K_ * D_) {
        const int k = col / D_, d = col % D_;
        v = sqrtf(sqrtf(sigma[k])) * mp[((size_t)k * D_ + d) * D_ + o];
    } else if (col < SPECC) {
        const int c = col - K_ * D_;
        const int k = c / D_, d = c % D_;
        v = sqrtf(sqrtf(sigma[k])) * mm[((size_t)k * D_ + d) * D_ + o];
    } else {
        const int c = col - SPECC;
        const int j = c / D_, d = c % D_;
        v = mu[((size_t)j * D_ + d) * D_ + o];
    }
    u16 hi, lo; split_bf(v, hi, lo);
    Wh[idx] = hi; Wl[idx] = lo;
}

// ---------------- generic split ----------------
__global__ __launch_bounds__(256) void split_k(
    const float* __restrict__ src, u16* __restrict__ hi, u16* __restrict__ lo, int n)
{
    const int i = blockIdx.x * 256 + threadIdx.x;
    if (i < n) { u16 h, l; split_bf(src[i], h, l); hi[i] = h; lo[i] = l; }
}

// ---------------- phi pair table: P2[k][p] = pack(phi[p-128], phi[p-129]) ----------------
__global__ __launch_bounds__(256) void phipack_k(
    const float* __restrict__ phi, u32* __restrict__ P2h, u32* __restrict__ P2l)
{
    const int i = blockIdx.x * 256 + threadIdx.x;   // over K_*P2LEN
    if (i >= K_ * P2LEN) return;
    const int k = i / P2LEN, p = i % P2LEN;
    const int lag = p - 128;
    u16 lh = 0, ll = 0, hh = 0, hl = 0;
    if (lag >= 0 && lag < S_)         split_bf(phi[lag * K_ + k], lh, ll);
    if (lag - 1 >= 0 && lag - 1 < S_) split_bf(phi[(lag - 1) * K_ + k], hh, hl);
    P2h[i] = (u32)lh | ((u32)hh << 16);
    P2l[i] = (u32)ll | ((u32)hl << 16);
}

// ---------------- elementwise ----------------
__global__ __launch_bounds__(256) void silu_k(
    const float* __restrict__ m1, u16* __restrict__ m2h, u16* __restrict__ m2l)
{
    const int idx = blockIdx.x * 256 + threadIdx.x;
    const int r = idx >> 11;
    const int j = idx & (H_ - 1);
    const float y = m1[(size_t)r * (2 * H_) + j];
    const float gg = m1[(size_t)r * (2 * H_) + H_ + j];
    const float v = y * gg / (1.f + expf(-gg));
    u16 h, l; split_bf(v, h, l);
    m2h[idx] = h; m2l[idx] = l;
}

__global__ __launch_bounds__(256) void copy_k(float* __restrict__ dst, const float* __restrict__ src)
{
    const int i = blockIdx.x * 256 + threadIdx.x;
    ((float4*)dst)[i] = ((const float4*)src)[i];
}

__global__ __launch_bounds__(256) void add_k(float* __restrict__ dst, const float* __restrict__ src)
{
    const int i = blockIdx.x * 256 + threadIdx.x;
    float4 a = ((const float4*)dst)[i];
    float4 b = ((const float4*)src)[i];
    a.x += b.x; a.y += b.y; a.z += b.z; a.w += b.w;
    ((float4*)dst)[i] = a;
}

// x += p0+p1+p2+p3, and emit bf16 split of new x
__global__ __launch_bounds__(256) void reduce4_k(
    float* __restrict__ x, const float* __restrict__ p,
    u16* __restrict__ xh, u16* __restrict__ xl)
{
    const int i = blockIdx.x * 256 + threadIdx.x;   // over R_*D_/4
    const size_t MN4 = (size_t)R_ * D_ / 4;
    float4 a = ((const float4*)x)[i];
    float4 b0 = ((const float4*)p)[i];
    float4 b1 = ((const float4*)p)[i + MN4];
    float4 b2 = ((const float4*)p)[i + 2 * MN4];
    float4 b3 = ((const float4*)p)[i + 3 * MN4];
    a.x += (b0.x + b1.x) + (b2.x + b3.x);
    a.y += (b0.y + b1.y) + (b2.y + b3.y);
    a.z += (b0.z + b1.z) + (b2.z + b3.z);
    a.w += (b0.w + b1.w) + (b2.w + b3.w);
    ((float4*)x)[i] = a;
    ushort4 vh, vl;
    split_bf(a.x, vh.x, vl.x); split_bf(a.y, vh.y, vl.y);
    split_bf(a.z, vh.z, vl.z); split_bf(a.w, vh.w, vl.w);
    ((ushort4*)xh)[i] = vh;
    ((ushort4*)xl)[i] = vl;
}

// ---------------- launch ----------------
extern "C" void kernel_launch(void* const* d_in, const int* in_sizes, int n_in,
                              void* d_out, int out_size)
{
    const float* inputs  = (const float*)d_in[0];
    const float* sigma   = (const float*)d_in[1];
    const float* phi     = (const float*)d_in[2];
    const float* in_proj = (const float*)d_in[3];
    const float* rn_w    = (const float*)d_in[4];
    const float* M_u     = (const float*)d_in[5];
    const float* M_p     = (const float*)d_in[6];
    const float* M_m     = (const float*)d_in[7];
    const float* fc1     = (const float*)d_in[8];
    const float* fc2     = (const float*)d_in[9];
    const float* out_w   = (const float*)d_in[10];
    float* out = (float*)d_out;

    float *x, *z, *h, *part, *m1;
    u16 *Uh, *Ul, *Wh, *Wl, *m2h, *m2l, *hTh, *hTl, *xh, *xl;
    u16 *inh, *inl, *iph, *ipl, *f1h, *f1l, *f2h, *f2l;
    u32 *P2h, *P2l;
    cudaGetSymbolAddress((void**)&x,   g_x);
    cudaGetSymbolAddress((void**)&z,   g_z);
    cudaGetSymbolAddress((void**)&h,   g_h);
    cudaGetSymbolAddress((void**)&part,g_part);
    cudaGetSymbolAddress((void**)&m1,  g_m1);
    cudaGetSymbolAddress((void**)&Uh,  g_Uh);
    cudaGetSymbolAddress((void**)&Ul,  g_Ul);
    cudaGetSymbolAddress((void**)&Wh,  g_Wh);
    cudaGetSymbolAddress((void**)&Wl,  g_Wl);
    cudaGetSymbolAddress((void**)&m2h, g_m2h);
    cudaGetSymbolAddress((void**)&m2l, g_m2l);
    cudaGetSymbolAddress((void**)&hTh, g_hTh);
    cudaGetSymbolAddress((void**)&hTl, g_hTl);
    cudaGetSymbolAddress((void**)&xh,  g_xh);
    cudaGetSymbolAddress((void**)&xl,  g_xl);
    cudaGetSymbolAddress((void**)&inh, g_inh);
    cudaGetSymbolAddress((void**)&inl, g_inl);
    cudaGetSymbolAddress((void**)&iph, g_iph);
    cudaGetSymbolAddress((void**)&ipl, g_ipl);
    cudaGetSymbolAddress((void**)&f1h, g_f1h);
    cudaGetSymbolAddress((void**)&f1l, g_f1l);
    cudaGetSymbolAddress((void**)&f2h, g_f2h);
    cudaGetSymbolAddress((void**)&f2l, g_f2l);
    cudaGetSymbolAddress((void**)&P2h, g_P2h);
    cudaGetSymbolAddress((void**)&P2l, g_P2l);

    // dynamic smem limits for the 128x128 instantiations (81920 B > 48K default)
    cudaFuncSetAttribute(gemm_bf3<128, 128, 4, 1>,
                         cudaFuncAttributeMaxDynamicSharedMemorySize, 81920);
    cudaFuncSetAttribute(gemm_bf3<128, 128, 4, NSPLIT_>,
                         cudaFuncAttributeMaxDynamicSharedMemorySize, 81920);

    const int ew_blocks = (R_ * D_ / 4) / 256;
    const int wfill_blocks = (int)(((size_t)D_ * UCOLS + 255) / 256);
    const int silu_blocks = (R_ * H_) / 256;

    phipack_k<<<(K_ * P2LEN + 255) / 256, 256>>>(phi, P2h, P2l);
    split_k<<<(R_ * DIN_ + 255) / 256, 256>>>(inputs, inh, inl, R_ * DIN_);

    for (int m = 0; m < M_; m++) {
        // x = inputs @ in_proj[m]^T   (2048 x 512, K=64)
        split_k<<<(D_ * DIN_ + 255) / 256, 256>>>(
            in_proj + (size_t)m * D_ * DIN_, iph, ipl, D_ * DIN_);
        gemm_bf3<64, 64, 2, 1><<<dim3(D_ / 64, R_ / 64), 256, 40960>>>(
            inh, inl, iph, ipl, x, R_, D_, DIN_, 0);

        for (int l = 0; l < L_; l++) {
            const int ml = m * L_ + l;

            copy_k<<<ew_blocks, 256>>>(z, x);
            rmsnorm_k<<<R_, 256>>>(x, rn_w + (size_t)ml * D_, h, Uh, Ul);
            transplit_k<<<dim3(S_ / 32, D_ / 32, B_), 256>>>(h, hTh, hTl);
            conv_bf<<<dim3(D_ / 64, S_ / 128, B_ * K_), 256>>>(hTh, hTl, P2h, P2l, Uh, Ul);
            wfill_k<<<wfill_blocks, 256>>>(
                sigma,
                M_p + (size_t)ml * K_ * D_ * D_,
                M_m + (size_t)ml * K_ * D_ * D_,
                M_u + (size_t)ml * KU_ * D_ * D_,
                Wh, Wl);
            // partials = U @ W^T (split-K=4); x += sum; emit x split for fc1
            gemm_bf3<128, 128, 4, NSPLIT_>
                <<<dim3(D_ / 128, R_ / 128, NSPLIT_), 256, 81920>>>(
                Uh, Ul, Wh, Wl, part, R_, D_, UCOLS, 0);
            reduce4_k<<<ew_blocks, 256>>>(x, part, xh, xl);

            // MLP
            split_k<<<(2 * H_ * D_ + 255) / 256, 256>>>(
                fc1 + (size_t)ml * 2 * H_ * D_, f1h, f1l, 2 * H_ * D_);
            gemm_bf3<128, 128, 4, 1><<<dim3(2 * H_ / 128, R_ / 128), 256, 81920>>>(
                xh, xl, f1h, f1l, m1, R_, 2 * H_, D_, 0);
            silu_k<<<silu_blocks, 256>>>(m1, m2h, m2l);
            split_k<<<(D_ * H_ + 255) / 256, 256>>>(
                fc2 + (size_t)ml * D_ * H_, f2h, f2l, D_ * H_);
            gemm_bf3<64, 64, 2, 1><<<dim3(D_ / 64, R_ / 64), 256, 40960>>>(
                m2h, m2l, f2h, f2l, x, R_, D_, H_, 1);

            add_k<<<ew_blocks, 256>>>(x, z);
        }

        // preds += x @ out_proj[m]^T  (N=64)
        gemm_nt<<<dim3(DIN_ / 64, R_ / 64), 256>>>(
            x, out_w + (size_t)m * DIN_ * D_, out, R_, DIN_, D_, m);
    }
    (void)in_sizes; (void)n_in; (void)out_size;
}

// round 9
// speedup vs baseline: 2.1727x; 1.0455x over previous
#include <cuda_runtime.h>
#include <cuda_bf16.h>
#include <cstddef>

// ---------------- problem constants ----------------
#define B_    2
#define S_    1024
#define DIN_  64
#define D_    512
#define K_    16
#define KU_   3
#define L_    2
#define M_    2
#define H_    2048
#define R_    (B_ * S_)                 // 2048 rows (b*S + t)
#define SPECC (2 * K_ * D_)             // 16384 spectral columns of U
#define UCOLS (SPECC + KU_ * D_)        // 17920 = spectral + AR columns
#define EPS_  1e-5f
#define NSPLIT_ 4
#define P2LEN 1280

typedef unsigned short u16;
typedef unsigned int   u32;

// ---------------- scratch (static device globals; no allocation) ----------------
__device__ __align__(16) float g_x[R_ * D_];
__device__ __align__(16) float g_z[R_ * D_];
__device__ __align__(16) float g_h[R_ * D_];
__device__ __align__(16) float g_part[(size_t)NSPLIT_ * R_ * D_];
__device__ __align__(16) float g_m1[(size_t)R_ * 2 * H_];

__device__ __align__(16) u16 g_Uh[(size_t)R_ * UCOLS];
__device__ __align__(16) u16 g_Ul[(size_t)R_ * UCOLS];
__device__ __align__(16) u16 g_Wh[(size_t)D_ * UCOLS];
__device__ __align__(16) u16 g_Wl[(size_t)D_ * UCOLS];
__device__ __align__(16) u16 g_m2h[(size_t)R_ * H_];
__device__ __align__(16) u16 g_m2l[(size_t)R_ * H_];
__device__ __align__(16) u16 g_hTh[B_ * D_ * S_];
__device__ __align__(16) u16 g_hTl[B_ * D_ * S_];
__device__ __align__(16) u16 g_xh[R_ * D_];
__device__ __align__(16) u16 g_xl[R_ * D_];
__device__ __align__(16) u16 g_inh[R_ * DIN_];
__device__ __align__(16) u16 g_inl[R_ * DIN_];
__device__ __align__(16) u16 g_iph[D_ * DIN_];
__device__ __align__(16) u16 g_ipl[D_ * DIN_];
__device__ __align__(16) u16 g_f1h[2 * H_ * D_];
__device__ __align__(16) u16 g_f1l[2 * H_ * D_];
__device__ __align__(16) u16 g_f2h[D_ * H_];
__device__ __align__(16) u16 g_f2l[D_ * H_];
__device__ __align__(16) u32 g_P2h[K_ * P2LEN];
__device__ __align__(16) u32 g_P2l[K_ * P2LEN];

// ---------------- helpers ----------------
__device__ __forceinline__ void split_bf(float a, u16& hi, u16& lo) {
    __nv_bfloat16 h = __float2bfloat16(a);
    float r = a - __bfloat162float(h);
    __nv_bfloat16 l = __float2bfloat16(r);
    hi = reinterpret_cast<u16&>(h);
    lo = reinterpret_cast<u16&>(l);
}

__device__ __forceinline__ void mma_bf16(float c[4],
                                         u32 a0, u32 a1, u32 a2, u32 a3,
                                         u32 b0, u32 b1) {
    asm volatile(
        "mma.sync.aligned.m16n8k16.row.col.f32.bf16.bf16.f32 "
        "{%0,%1,%2,%3},{%4,%5,%6,%7},{%8,%9},{%0,%1,%2,%3};\n"
        : "+f"(c[0]), "+f"(c[1]), "+f"(c[2]), "+f"(c[3])
        : "r"(a0), "r"(a1), "r"(a2), "r"(a3), "r"(b0), "r"(b1));
}

__device__ __forceinline__ u32 smem_u32(const void* p) {
    u32 a;
    asm("{ .reg .u64 t; cvta.to.shared.u64 t, %1; cvt.u32.u64 %0, t; }" : "=r"(a) : "l"(p));
    return a;
}

__device__ __forceinline__ void ldsm4(u32& r0, u32& r1, u32& r2, u32& r3, u32 saddr) {
    asm volatile("ldmatrix.sync.aligned.m8n8.x4.shared.b16 {%0,%1,%2,%3}, [%4];"
                 : "=r"(r0), "=r"(r1), "=r"(r2), "=r"(r3) : "r"(saddr));
}

__device__ __forceinline__ void cp16(u32* smem_dst, const void* gsrc) {
    unsigned saddr = (unsigned)__cvta_generic_to_shared(smem_dst);
    asm volatile("cp.async.cg.shared.global [%0], [%1], 16;\n" :: "r"(saddr), "l"(gsrc));
}
#define CP_COMMIT() asm volatile("cp.async.commit_group;\n" ::: "memory")
#define CP_WAIT1()  asm volatile("cp.async.wait_group 1;\n" ::: "memory")

// ---------------- bf16 3-term NT GEMM, cp.async 2-stage + ldmatrix ----------------
// C(M,N) = A(M,K)*B(N,K)^T. A,B pre-split bf16 (hi, lo). K%32==0. NT even.
template<int BM, int BN, int WARPS_M, int NSPLIT>
__global__ __launch_bounds__(256) void gemm_bf3(
    const u16* __restrict__ Ah, const u16* __restrict__ Al,
    const u16* __restrict__ Bh, const u16* __restrict__ Bl,
    float* __restrict__ C, int M, int N, int K, int accum)
{
    constexpr int WARPS_N = 8 / WARPS_M;
    constexpr int WM = BM / WARPS_M;
    constexpr int WN = BN / WARPS_N;
    constexpr int MT = WM / 16;
    constexpr int NT = WN / 8;
    constexpr int AOFF  = 0;
    constexpr int ALOFF = BM * 20;
    constexpr int BOFF  = 2 * BM * 20;
    constexpr int BLOFF = 2 * BM * 20 + BN * 20;
    constexpr int STAGE = 2 * (BM + BN) * 20;   // u32 per stage
    extern __shared__ __align__(16) u32 dsm[];

    int kb = 0, ke = K;
    if (NSPLIT > 1) {
        const int z = blockIdx.z;
        const int steps = K / 32;
        kb = ((z * steps) / NSPLIT) * 32;
        ke = (((z + 1) * steps) / NSPLIT) * 32;
        C += (size_t)z * M * N;
        accum = 0;
    }

    const int bm = blockIdx.y * BM;
    const int bn = blockIdx.x * BN;
    const int tid  = threadIdx.x;
    const int lane = tid & 31;
    const int warp = tid >> 5;
    const int wm = (warp % WARPS_M) * WM;
    const int wn = (warp / WARPS_M) * WN;
    const int g  = lane >> 2;
    const int tg = lane & 3;

    const int lr = tid >> 2;
    const int c4 = (tid & 3) * 4;

    const u32 dsmAddr = smem_u32(dsm);
    // ldmatrix lane address components (bytes)
    const u32 rowA = (lane & 7) + ((lane >> 3) & 1) * 8;
    const u32 kbA  = ((lane >> 4) & 1) * 16;
    const u32 colB = (lane & 7) + ((lane >> 4) & 1) * 8;
    const u32 kbB  = ((lane >> 3) & 1) * 16;
    const u32 aoff = (u32)AOFF * 4 + (wm + rowA) * 80 + kbA;
    const u32 boff = (u32)BOFF * 4 + (wn + colB) * 80 + kbB;

    auto issue = [&](int k0, int s) {
        u32* base = dsm + s * STAGE;
#pragma unroll
        for (int r = 0; r < BM / 64; r++) {
            const int rrow = lr + 64 * r;
            const size_t go = (size_t)(bm + rrow) * K + k0 + c4 * 2;
            cp16(base + AOFF  + rrow * 20 + c4, &Ah[go]);
            cp16(base + ALOFF + rrow * 20 + c4, &Al[go]);
        }
#pragma unroll
        for (int r = 0; r < BN / 64; r++) {
            const int rrow = lr + 64 * r;
            const size_t go = (size_t)(bn + rrow) * K + k0 + c4 * 2;
            cp16(base + BOFF  + rrow * 20 + c4, &Bh[go]);
            cp16(base + BLOFF + rrow * 20 + c4, &Bl[go]);
        }
    };

    float acc[MT][NT][4] = {};

    const int nIters = (ke - kb) / 32;
    issue(kb, 0); CP_COMMIT();

    for (int i = 0; i < nIters; i++) {
        if (i + 1 < nIters) issue(kb + (i + 1) * 32, (i + 1) & 1);
        CP_COMMIT();
        CP_WAIT1();
        __syncthreads();
        const u32 sb = dsmAddr + (u32)((i & 1) * STAGE * 4);

#pragma unroll
        for (int ks = 0; ks < 2; ks++) {
            const u32 kso = (u32)ks * 32;
            u32 ah[MT][4], al[MT][4];
#pragma unroll
            for (int mt = 0; mt < MT; mt++) {
                const u32 base_a = sb + aoff + (u32)mt * 1280 + kso;
                ldsm4(ah[mt][0], ah[mt][1], ah[mt][2], ah[mt][3], base_a);
                ldsm4(al[mt][0], al[mt][1], al[mt][2], al[mt][3], base_a + (u32)BM * 80);
            }
#pragma unroll
            for (int ntp = 0; ntp < NT / 2; ntp++) {
                u32 bh0, bh1, bh2, bh3, bl0, bl1, bl2, bl3;
                const u32 base_b = sb + boff + (u32)ntp * 1280 + kso;
                ldsm4(bh0, bh1, bh2, bh3, base_b);
                ldsm4(bl0, bl1, bl2, bl3, base_b + (u32)BN * 80);
#pragma unroll
                for (int mt = 0; mt < MT; mt++) {
                    mma_bf16(acc[mt][2 * ntp],     ah[mt][0], ah[mt][1], ah[mt][2], ah[mt][3], bh0, bh1);
                    mma_bf16(acc[mt][2 * ntp],     al[mt][0], al[mt][1], al[mt][2], al[mt][3], bh0, bh1);
                    mma_bf16(acc[mt][2 * ntp],     ah[mt][0], ah[mt][1], ah[mt][2], ah[mt][3], bl0, bl1);
                    mma_bf16(acc[mt][2 * ntp + 1], ah[mt][0], ah[mt][1], ah[mt][2], ah[mt][3], bh2, bh3);
                    mma_bf16(acc[mt][2 * ntp + 1], al[mt][0], al[mt][1], al[mt][2], al[mt][3], bh2, bh3);
                    mma_bf16(acc[mt][2 * ntp + 1], ah[mt][0], ah[mt][1], ah[mt][2], ah[mt][3], bl2, bl3);
                }
            }
        }
        __syncthreads();
    }

#pragma unroll
    for (int mt = 0; mt < MT; mt++) {
        const int r0 = bm + wm + mt * 16 + g;
        const int r1 = r0 + 8;
#pragma unroll
        for (int nt = 0; nt < NT; nt++) {
            const int col = bn + wn + nt * 8 + 2 * tg;
            float2* p0 = (float2*)&C[(size_t)r0 * N + col];
            float2* p1 = (float2*)&C[(size_t)r1 * N + col];
            float2 v0 = make_float2(acc[mt][nt][0], acc[mt][nt][1]);
            float2 v1 = make_float2(acc[mt][nt][2], acc[mt][nt][3]);
            if (accum) {
                float2 o0 = *p0, o1 = *p1;
                v0.x += o0.x; v0.y += o0.y; v1.x += o1.x; v1.y += o1.y;
            }
            *p0 = v0;
            *p1 = v1;
        }
    }
}

// ---------------- causal spectral conv, cp.async 3-stage + ldmatrix X ----------------
__global__ __launch_bounds__(256) void conv_bf(
    const u16* __restrict__ hTh, const u16* __restrict__ hTl,
    const u32* __restrict__ P2h, const u32* __restrict__ P2l,
    u16* __restrict__ Uh, u16* __restrict__ Ul)
{
    constexpr int CXH = 0;
    constexpr int CXL = 64 * 20;
    constexpr int CQH = 2 * 64 * 20;
    constexpr int CQL = CQH + 164;
    constexpr int CSTAGE = 2 * 64 * 20 + 2 * 164;   // u32; bytes = 11552 (16-mult)
    __shared__ __align__(16) u32 csm[3 * CSTAGE];

    const int d0 = blockIdx.x * 64;
    const int t0 = blockIdx.y * 128;
    const int b  = blockIdx.z >> 4;
    const int k  = blockIdx.z & 15;
    const int tid  = threadIdx.x;
    const int lane = tid & 31;
    const int warp = tid >> 5;
    const int wm = (warp & 3) * 32;
    const int wn = (warp >> 2) * 32;
    const int g  = lane >> 2;
    const int tg = lane & 3;
    const u32 mk = 0x80000000u;   // flip odd-kk (high bf16) sign only

    const int xr = tid >> 2;
    const int c4 = (tid & 3) * 4;

    const u32 csmAddr = smem_u32(csm);
    const u32 colB = (lane & 7) + ((lane >> 4) & 1) * 8;
    const u32 kbB  = ((lane >> 3) & 1) * 16;
    const u32 xoff = (wn + colB) * 80 + kbB;    // within CXH region

    auto issue = [&](int i0, int s) {
        u32* base = csm + s * CSTAGE;
        const size_t go = (size_t)(b * D_ + d0 + xr) * S_ + i0 + c4 * 2;
        cp16(base + CXH + xr * 20 + c4, &hTh[go]);
        cp16(base + CXL + xr * 20 + c4, &hTl[go]);
        const int p0 = t0 - i0 + 96;
        if (tid < 41)
            cp16(base + CQH + tid * 4, &P2h[k * P2LEN + p0 + tid * 4]);
        else if (tid >= 64 && tid < 105)
            cp16(base + CQL + (tid - 64) * 4, &P2l[k * P2LEN + p0 + (tid - 64) * 4]);
    };

    float accp[2][4][4] = {};
    float accm[2][4][4] = {};

    const int nIters = (t0 + 128) / 32;
    issue(0, 0); CP_COMMIT();
    issue(32, 1); CP_COMMIT();

    for (int i = 0; i < nIters; i++) {
        CP_WAIT1();
        __syncthreads();
        if (i + 2 < nIters) issue((i + 2) * 32, (i + 2) % 3);
        CP_COMMIT();
        const int s = i % 3;
        const u32 sb = csmAddr + (u32)(s * CSTAGE * 4);
        const u32* base = csm + s * CSTAGE;
        const u32* sQh = base + CQH;
        const u32* sQl = base + CQL;

#pragma unroll
        for (int ks = 0; ks < 2; ks++) {
            u32 ah[2][3], al[2][3];     // a frag = {q0, q1, q2, q0}
#pragma unroll
            for (int mt = 0; mt < 2; mt++) {
                const int j0 = wm + mt * 16 - ks * 16 + 32 + g - 2 * tg;
                ah[mt][0] = sQh[j0]; ah[mt][1] = sQh[j0 + 8]; ah[mt][2] = sQh[j0 - 8];
                al[mt][0] = sQl[j0]; al[mt][1] = sQl[j0 + 8]; al[mt][2] = sQl[j0 - 8];
            }
#pragma unroll
            for (int ntp = 0; ntp < 2; ntp++) {
                u32 xh0, xh1, xh2, xh3, xl0, xl1, xl2, xl3;
                const u32 base_x = sb + xoff + (u32)ntp * 1280 + (u32)ks * 32;
                ldsm4(xh0, xh1, xh2, xh3, base_x);
                ldsm4(xl0, xl1, xl2, xl3, base_x + 5120u);   // CXL offset = 64*80
#pragma unroll
                for (int mt = 0; mt < 2; mt++) {
                    const u32 a0 = ah[mt][0], a1 = ah[mt][1], a2 = ah[mt][2];
                    const u32 c0 = al[mt][0], c1 = al[mt][1], c2 = al[mt][2];
                    float* ap0 = accp[mt][2 * ntp];
                    float* am0 = accm[mt][2 * ntp];
                    float* ap1 = accp[mt][2 * ntp + 1];
                    float* am1 = accm[mt][2 * ntp + 1];
                    mma_bf16(ap0, a0, a1, a2, a0, xh0, xh1);
                    mma_bf16(ap0, c0, c1, c2, c0, xh0, xh1);
                    mma_bf16(ap0, a0, a1, a2, a0, xl0, xl1);
                    mma_bf16(am0, a0 ^ mk, a1 ^ mk, a2 ^ mk, a0 ^ mk, xh0, xh1);
                    mma_bf16(am0, c0 ^ mk, c1 ^ mk, c2 ^ mk, c0 ^ mk, xh0, xh1);
                    mma_bf16(am0, a0 ^ mk, a1 ^ mk, a2 ^ mk, a0 ^ mk, xl0, xl1);
                    mma_bf16(ap1, a0, a1, a2, a0, xh2, xh3);
                    mma_bf16(ap1, c0, c1, c2, c0, xh2, xh3);
                    mma_bf16(ap1, a0, a1, a2, a0, xl2, xl3);
                    mma_bf16(am1, a0 ^ mk, a1 ^ mk, a2 ^ mk, a0 ^ mk, xh2, xh3);
                    mma_bf16(am1, c0 ^ mk, c1 ^ mk, c2 ^ mk, c0 ^ mk, xh2, xh3);
                    mma_bf16(am1, a0 ^ mk, a1 ^ mk, a2 ^ mk, a0 ^ mk, xl2, xl3);
                }
            }
        }
        __syncthreads();
    }

#pragma unroll
    for (int mt = 0; mt < 2; mt++) {
#pragma unroll
        for (int half = 0; half < 2; half++) {
            const int t = t0 + wm + mt * 16 + g + half * 8;
            const float st = (t & 1) ? -1.f : 1.f;
            const size_t rowo = (size_t)(b * S_ + t) * UCOLS;
#pragma unroll
            for (int nt = 0; nt < 4; nt++) {
                const int d = d0 + wn + nt * 8 + 2 * tg;
                const float cp0 = accp[mt][nt][half * 2 + 0];
                const float cp1 = accp[mt][nt][half * 2 + 1];
                const float cm0 = st * accm[mt][nt][half * 2 + 0];
                const float cm1 = st * accm[mt][nt][half * 2 + 1];
                u16 h0, l0, h1, l1;
                split_bf(cp0, h0, l0); split_bf(cp1, h1, l1);
                *(ushort2*)&Uh[rowo + (size_t)k * D_ + d] = make_ushort2(h0, h1);
                *(ushort2*)&Ul[rowo + (size_t)k * D_ + d] = make_ushort2(l0, l1);
                split_bf(cm0, h0, l0); split_bf(cm1, h1, l1);
                *(ushort2*)&Uh[rowo + (size_t)(K_ + k) * D_ + d] = make_ushort2(h0, h1);
                *(ushort2*)&Ul[rowo + (size_t)(K_ + k) * D_ + d] = make_ushort2(l0, l1);
            }
        }
    }
}

// ---------------- fp32 NT GEMM (tiny out_proj: N=64) ----------------
__global__ __launch_bounds__(256) void gemm_nt(
    const float* __restrict__ A, const float* __restrict__ B, float* __restrict__ C,
    int M, int N, int K, int accum)
{
    __shared__ float As[16][65];
    __shared__ float Bs[16][65];
    const int bm = blockIdx.y * 64;
    const int bn = blockIdx.x * 64;
    const int tid = threadIdx.x;
    const int tx = tid & 15;
    const int ty = tid >> 4;
    const int lr = tid >> 2;
    const int lk = (tid & 3) << 2;

    const float* Ap = A + (size_t)(bm + lr) * K + lk;
    const float* Bp = B + (size_t)(bn + lr) * K + lk;

    float acc[4][4] = {};

    for (int k0 = 0; k0 < K; k0 += 16) {
        float4 av = *(const float4*)(Ap + k0);
        float4 bv = *(const float4*)(Bp + k0);
        __syncthreads();
        As[lk + 0][lr] = av.x; As[lk + 1][lr] = av.y;
        As[lk + 2][lr] = av.z; As[lk + 3][lr] = av.w;
        Bs[lk + 0][lr] = bv.x; Bs[lk + 1][lr] = bv.y;
        Bs[lk + 2][lr] = bv.z; Bs[lk + 3][lr] = bv.w;
        __syncthreads();
#pragma unroll
        for (int kk = 0; kk < 16; kk++) {
            float a[4], b[4];
#pragma unroll
            for (int i = 0; i < 4; i++) a[i] = As[kk][ty * 4 + i];
#pragma unroll
            for (int j = 0; j < 4; j++) b[j] = Bs[kk][tx * 4 + j];
#pragma unroll
            for (int i = 0; i < 4; i++)
#pragma unroll
                for (int j = 0; j < 4; j++)
                    acc[i][j] += a[i] * b[j];
        }
    }

#pragma unroll
    for (int i = 0; i < 4; i++) {
        const int r = bm + ty * 4 + i;
#pragma unroll
        for (int j = 0; j < 4; j++) {
            const int c = bn + tx * 4 + j;
            const size_t idx = (size_t)r * N + c;
            C[idx] = accum ? (C[idx] + acc[i][j]) : acc[i][j];
        }
    }
}

// ---------------- rmsnorm + z copy + AR column scatter (bf16 pairs) ----------------
__global__ __launch_bounds__(256) void rmsnorm_k(
    const float* __restrict__ x, const float* __restrict__ w,
    float* __restrict__ h, float* __restrict__ z,
    u16* __restrict__ Uh, u16* __restrict__ Ul)
{
    __shared__ float red[256];
    const int row = blockIdx.x;
    const int t = row & (S_ - 1);
    const int tid = threadIdx.x;

    const float v0 = x[(size_t)row * D_ + tid];
    const float v1 = x[(size_t)row * D_ + 256 + tid];
    z[(size_t)row * D_ + tid] = v0;
    z[(size_t)row * D_ + 256 + tid] = v1;
    red[tid] = v0 * v0 + v1 * v1;
    __syncthreads();
    for (int s = 128; s > 0; s >>= 1) {
        if (tid < s) red[tid] += red[tid + s];
        __syncthreads();
    }
    const float scale = rsqrtf(red[0] * (1.f / D_) + EPS_);
    const float h0 = v0 * scale * w[tid];
    const float h1 = v1 * scale * w[tid + 256];
    h[(size_t)row * D_ + tid] = h0;
    h[(size_t)row * D_ + 256 + tid] = h1;

    u16 h0h, h0l, h1h, h1l;
    split_bf(h0, h0h, h0l); split_bf(h1, h1h, h1l);

#pragma unroll
    for (int j = 0; j < KU_; j++) {
        if (t + j < S_) {
            const size_t base = (size_t)(row + j) * UCOLS + SPECC + j * D_;
            Uh[base + tid] = h0h; Ul[base + tid] = h0l;
            Uh[base + 256 + tid] = h1h; Ul[base + 256 + tid] = h1l;
        }
        if (t < j) {
            const size_t base = (size_t)row * UCOLS + SPECC + j * D_;
            Uh[base + tid] = 0; Ul[base + tid] = 0;
            Uh[base + 256 + tid] = 0; Ul[base + 256 + tid] = 0;
        }
    }
}

// ---------------- transpose + split h -> hT pairs ----------------
__global__ __launch_bounds__(256) void transplit_k(
    const float* __restrict__ h, u16* __restrict__ hTh, u16* __restrict__ hTl)
{
    __shared__ float tile[32][33];
    const int i0 = blockIdx.x * 32;
    const int d0 = blockIdx.y * 32;
    const int b  = blockIdx.z;
    const int tx = threadIdx.x & 31;
    const int ty = threadIdx.x >> 5;
#pragma unroll
    for (int r = 0; r < 4; r++)
        tile[ty + 8 * r][tx] = h[(size_t)(b * S_ + i0 + ty + 8 * r) * D_ + d0 + tx];
    __syncthreads();
#pragma unroll
    for (int r = 0; r < 4; r++) {
        const float v = tile[tx][ty + 8 * r];
        u16 hi, lo; split_bf(v, hi, lo);
        const size_t o = (size_t)(b * D_ + d0 + ty + 8 * r) * S_ + i0 + tx;
        hTh[o] = hi; hTl[o] = lo;
    }
}

// ---------------- fused weight fill (bf16 pairs) ----------------
__global__ __launch_bounds__(256) void wfill_k(
    const float* __restrict__ sigma, const float* __restrict__ mp,
    const float* __restrict__ mm, const float* __restrict__ mu,
    u16* __restrict__ Wh, u16* __restrict__ Wl)
{
    const size_t idx = (size_t)blockIdx.x * 256 + threadIdx.x;
    if (idx >= (size_t)D_ * UCOLS) return;
    const int o = (int)(idx / UCOLS);
    const int col = (int)(idx % UCOLS);
    float v;
    if (col < K_ * D_) {
        const int k = col / D_, d = col % D_;
        v = sqrtf(sqrtf(sigma[k])) * mp[((size_t)k * D_ + d) * D_ + o];
    } else if (col < SPECC) {
        const int c = col - K_ * D_;
        const int k = c / D_, d = c % D_;
        v = sqrtf(sqrtf(sigma[k])) * mm[((size_t)k * D_ + d) * D_ + o];
    } else {
        const int c = col - SPECC;
        const int j = c / D_, d = c % D_;
        v = mu[((size_t)j * D_ + d) * D_ + o];
    }
    u16 hi, lo; split_bf(v, hi, lo);
    Wh[idx] = hi; Wl[idx] = lo;
}

// ---------------- generic split ----------------
__global__ __launch_bounds__(256) void split_k(
    const float* __restrict__ src, u16* __restrict__ hi, u16* __restrict__ lo, int n)
{
    const int i = blockIdx.x * 256 + threadIdx.x;
    if (i < n) { u16 h, l; split_bf(src[i], h, l); hi[i] = h; lo[i] = l; }
}

// ---------------- phi pair table ----------------
__global__ __launch_bounds__(256) void phipack_k(
    const float* __restrict__ phi, u32* __restrict__ P2h, u32* __restrict__ P2l)
{
    const int i = blockIdx.x * 256 + threadIdx.x;
    if (i >= K_ * P2LEN) return;
    const int k = i / P2LEN, p = i % P2LEN;
    const int lag = p - 128;
    u16 lh = 0, ll = 0, hh = 0, hl = 0;
    if (lag >= 0 && lag < S_)         split_bf(phi[lag * K_ + k], lh, ll);
    if (lag - 1 >= 0 && lag - 1 < S_) split_bf(phi[(lag - 1) * K_ + k], hh, hl);
    P2h[i] = (u32)lh | ((u32)hh << 16);
    P2l[i] = (u32)ll | ((u32)hl << 16);
}

// ---------------- elementwise ----------------
__global__ __launch_bounds__(256) void silu_k(
    const float* __restrict__ m1, u16* __restrict__ m2h, u16* __restrict__ m2l)
{
    const int idx = blockIdx.x * 256 + threadIdx.x;
    const int r = idx >> 11;
    const int j = idx & (H_ - 1);
    const float y = m1[(size_t)r * (2 * H_) + j];
    const float gg = m1[(size_t)r * (2 * H_) + H_ + j];
    const float v = y * gg / (1.f + expf(-gg));
    u16 h, l; split_bf(v, h, l);
    m2h[idx] = h; m2l[idx] = l;
}

__global__ __launch_bounds__(256) void add_k(float* __restrict__ dst, const float* __restrict__ src)
{
    const int i = blockIdx.x * 256 + threadIdx.x;
    float4 a = ((const float4*)dst)[i];
    float4 b = ((const float4*)src)[i];
    a.x += b.x; a.y += b.y; a.z += b.z; a.w += b.w;
    ((float4*)dst)[i] = a;
}

__global__ __launch_bounds__(256) void reduce4_k(
    float* __restrict__ x, const float* __restrict__ p,
    u16* __restrict__ xh, u16* __restrict__ xl)
{
    const int i = blockIdx.x * 256 + threadIdx.x;
    const size_t MN4 = (size_t)R_ * D_ / 4;
    float4 a = ((const float4*)x)[i];
    float4 b0 = ((const float4*)p)[i];
    float4 b1 = ((const float4*)p)[i + MN4];
    float4 b2 = ((const float4*)p)[i + 2 * MN4];
    float4 b3 = ((const float4*)p)[i + 3 * MN4];
    a.x += (b0.x + b1.x) + (b2.x + b3.x);
    a.y += (b0.y + b1.y) + (b2.y + b3.y);
    a.z += (b0.z + b1.z) + (b2.z + b3.z);
    a.w += (b0.w + b1.w) + (b2.w + b3.w);
    ((float4*)x)[i] = a;
    ushort4 vh, vl;
    split_bf(a.x, vh.x, vl.x); split_bf(a.y, vh.y, vl.y);
    split_bf(a.z, vh.z, vl.z); split_bf(a.w, vh.w, vl.w);
    ((ushort4*)xh)[i] = vh;
    ((ushort4*)xl)[i] = vl;
}

// ---------------- launch ----------------
extern "C" void kernel_launch(void* const* d_in, const int* in_sizes, int n_in,
                              void* d_out, int out_size)
{
    const float* inputs  = (const float*)d_in[0];
    const float* sigma   = (const float*)d_in[1];
    const float* phi     = (const float*)d_in[2];
    const float* in_proj = (const float*)d_in[3];
    const float* rn_w    = (const float*)d_in[4];
    const float* M_u     = (const float*)d_in[5];
    const float* M_p     = (const float*)d_in[6];
    const float* M_m     = (const float*)d_in[7];
    const float* fc1     = (const float*)d_in[8];
    const float* fc2     = (const float*)d_in[9];
    const float* out_w   = (const float*)d_in[10];
    float* out = (float*)d_out;

    float *x, *z, *h, *part, *m1;
    u16 *Uh, *Ul, *Wh, *Wl, *m2h, *m2l, *hTh, *hTl, *xh, *xl;
    u16 *inh, *inl, *iph, *ipl, *f1h, *f1l, *f2h, *f2l;
    u32 *P2h, *P2l;
    cudaGetSymbolAddress((void**)&x,   g_x);
    cudaGetSymbolAddress((void**)&z,   g_z);
    cudaGetSymbolAddress((void**)&h,   g_h);
    cudaGetSymbolAddress((void**)&part,g_part);
    cudaGetSymbolAddress((void**)&m1,  g_m1);
    cudaGetSymbolAddress((void**)&Uh,  g_Uh);
    cudaGetSymbolAddress((void**)&Ul,  g_Ul);
    cudaGetSymbolAddress((void**)&Wh,  g_Wh);
    cudaGetSymbolAddress((void**)&Wl,  g_Wl);
    cudaGetSymbolAddress((void**)&m2h, g_m2h);
    cudaGetSymbolAddress((void**)&m2l, g_m2l);
    cudaGetSymbolAddress((void**)&hTh, g_hTh);
    cudaGetSymbolAddress((void**)&hTl, g_hTl);
    cudaGetSymbolAddress((void**)&xh,  g_xh);
    cudaGetSymbolAddress((void**)&xl,  g_xl);
    cudaGetSymbolAddress((void**)&inh, g_inh);
    cudaGetSymbolAddress((void**)&inl, g_inl);
    cudaGetSymbolAddress((void**)&iph, g_iph);
    cudaGetSymbolAddress((void**)&ipl, g_ipl);
    cudaGetSymbolAddress((void**)&f1h, g_f1h);
    cudaGetSymbolAddress((void**)&f1l, g_f1l);
    cudaGetSymbolAddress((void**)&f2h, g_f2h);
    cudaGetSymbolAddress((void**)&f2l, g_f2l);
    cudaGetSymbolAddress((void**)&P2h, g_P2h);
    cudaGetSymbolAddress((void**)&P2l, g_P2l);

    cudaFuncSetAttribute(gemm_bf3<128, 128, 4, 1>,
                         cudaFuncAttributeMaxDynamicSharedMemorySize, 81920);
    cudaFuncSetAttribute(gemm_bf3<128, 128, 4, NSPLIT_>,
                         cudaFuncAttributeMaxDynamicSharedMemorySize, 81920);

    const int ew_blocks = (R_ * D_ / 4) / 256;
    const int wfill_blocks = (int)(((size_t)D_ * UCOLS + 255) / 256);
    const int silu_blocks = (R_ * H_) / 256;

    phipack_k<<<(K_ * P2LEN + 255) / 256, 256>>>(phi, P2h, P2l);
    split_k<<<(R_ * DIN_ + 255) / 256, 256>>>(inputs, inh, inl, R_ * DIN_);

    for (int m = 0; m < M_; m++) {
        // x = inputs @ in_proj[m]^T   (2048 x 512, K=64)
        split_k<<<(D_ * DIN_ + 255) / 256, 256>>>(
            in_proj + (size_t)m * D_ * DIN_, iph, ipl, D_ * DIN_);
        gemm_bf3<64, 64, 2, 1><<<dim3(D_ / 64, R_ / 64), 256, 40960>>>(
            inh, inl, iph, ipl, x, R_, D_, DIN_, 0);

        for (int l = 0; l < L_; l++) {
            const int ml = m * L_ + l;

            rmsnorm_k<<<R_, 256>>>(x, rn_w + (size_t)ml * D_, h, z, Uh, Ul);
            transplit_k<<<dim3(S_ / 32, D_ / 32, B_), 256>>>(h, hTh, hTl);
            conv_bf<<<dim3(D_ / 64, S_ / 128, B_ * K_), 256>>>(hTh, hTl, P2h, P2l, Uh, Ul);
            wfill_k<<<wfill_blocks, 256>>>(
                sigma,
                M_p + (size_t)ml * K_ * D_ * D_,
                M_m + (size_t)ml * K_ * D_ * D_,
                M_u + (size_t)ml * KU_ * D_ * D_,
                Wh, Wl);
            // partials = U @ W^T (split-K=4); x += sum; emit x split for fc1
            gemm_bf3<128, 128, 4, NSPLIT_>
                <<<dim3(D_ / 128, R_ / 128, NSPLIT_), 256, 81920>>>(
                Uh, Ul, Wh, Wl, part, R_, D_, UCOLS, 0);
            reduce4_k<<<ew_blocks, 256>>>(x, part, xh, xl);

            // MLP
            split_k<<<(2 * H_ * D_ + 255) / 256, 256>>>(
                fc1 + (size_t)ml * 2 * H_ * D_, f1h, f1l, 2 * H_ * D_);
            gemm_bf3<128, 128, 4, 1><<<dim3(2 * H_ / 128, R_ / 128), 256, 81920>>>(
                xh, xl, f1h, f1l, m1, R_, 2 * H_, D_, 0);
            silu_k<<<silu_blocks, 256>>>(m1, m2h, m2l);
            split_k<<<(D_ * H_ + 255) / 256, 256>>>(
                fc2 + (size_t)ml * D_ * H_, f2h, f2l, D_ * H_);
            gemm_bf3<64, 64, 2, 1><<<dim3(D_ / 64, R_ / 64), 256, 40960>>>(
                m2h, m2l, f2h, f2l, x, R_, D_, H_, 1);

            add_k<<<ew_blocks, 256>>>(x, z);
        }

        // preds += x @ out_proj[m]^T  (N=64)
        gemm_nt<<<dim3(DIN_ / 64, R_ / 64), 256>>>(
            x, out_w + (size_t)m * DIN_ * D_, out, R_, DIN_, D_, m);
    }
    (void)in_sizes; (void)n_in; (void)out_size;
}

// round 10
// speedup vs baseline: 2.4601x; 1.1323x over previous
#include <cuda_runtime.h>
#include <cuda_bf16.h>
#include <cstddef>

// ---------------- problem constants ----------------
#define B_    2
#define S_    1024
#define S2_   (S_ / 2)
#define DIN_  64
#define D_    512
#define K_    16
#define KU_   3
#define L_    2
#define M_    2
#define H_    2048
#define R_    (B_ * S_)                 // 2048 rows (b*S + t)
#define SPECC (2 * K_ * D_)             // 16384 spectral columns of U
#define UCOLS (SPECC + KU_ * D_)        // 17920 = spectral + AR columns
#define EPS_  1e-5f
#define NSPLIT_ 4
#define P2LEN 1280                      // stride-2 phi pair table (offset 192)

typedef unsigned short u16;
typedef unsigned int   u32;

// ---------------- scratch (static device globals; no allocation) ----------------
__device__ __align__(16) float g_x[R_ * D_];
__device__ __align__(16) float g_z[R_ * D_];
__device__ __align__(16) float g_h[R_ * D_];
__device__ __align__(16) float g_part[(size_t)NSPLIT_ * R_ * D_];
__device__ __align__(16) float g_m1[(size_t)R_ * 2 * H_];

__device__ __align__(16) u16 g_Uh[(size_t)R_ * UCOLS];
__device__ __align__(16) u16 g_Ul[(size_t)R_ * UCOLS];
__device__ __align__(16) u16 g_Wh[(size_t)D_ * UCOLS];
__device__ __align__(16) u16 g_Wl[(size_t)D_ * UCOLS];
__device__ __align__(16) u16 g_m2h[(size_t)R_ * H_];
__device__ __align__(16) u16 g_m2l[(size_t)R_ * H_];
__device__ __align__(16) u16 g_hTeh[B_ * D_ * S2_];
__device__ __align__(16) u16 g_hTel[B_ * D_ * S2_];
__device__ __align__(16) u16 g_hToh[B_ * D_ * S2_];
__device__ __align__(16) u16 g_hTol[B_ * D_ * S2_];
__device__ __align__(16) u16 g_xh[R_ * D_];
__device__ __align__(16) u16 g_xl[R_ * D_];
__device__ __align__(16) u16 g_inh[R_ * DIN_];
__device__ __align__(16) u16 g_inl[R_ * DIN_];
__device__ __align__(16) u16 g_iph[D_ * DIN_];
__device__ __align__(16) u16 g_ipl[D_ * DIN_];
__device__ __align__(16) u16 g_f1h[2 * H_ * D_];
__device__ __align__(16) u16 g_f1l[2 * H_ * D_];
__device__ __align__(16) u16 g_f2h[D_ * H_];
__device__ __align__(16) u16 g_f2l[D_ * H_];
__device__ __align__(16) u32 g_P2h[K_ * P2LEN];
__device__ __align__(16) u32 g_P2l[K_ * P2LEN];

// ---------------- helpers ----------------
__device__ __forceinline__ void split_bf(float a, u16& hi, u16& lo) {
    __nv_bfloat16 h = __float2bfloat16(a);
    float r = a - __bfloat162float(h);
    __nv_bfloat16 l = __float2bfloat16(r);
    hi = reinterpret_cast<u16&>(h);
    lo = reinterpret_cast<u16&>(l);
}

__device__ __forceinline__ void mma_bf16(float c[4],
                                         u32 a0, u32 a1, u32 a2, u32 a3,
                                         u32 b0, u32 b1) {
    asm volatile(
        "mma.sync.aligned.m16n8k16.row.col.f32.bf16.bf16.f32 "
        "{%0,%1,%2,%3},{%4,%5,%6,%7},{%8,%9},{%0,%1,%2,%3};\n"
        : "+f"(c[0]), "+f"(c[1]), "+f"(c[2]), "+f"(c[3])
        : "r"(a0), "r"(a1), "r"(a2), "r"(a3), "r"(b0), "r"(b1));
}

__device__ __forceinline__ u32 smem_u32(const void* p) {
    u32 a;
    asm("{ .reg .u64 t; cvta.to.shared.u64 t, %1; cvt.u32.u64 %0, t; }" : "=r"(a) : "l"(p));
    return a;
}

__device__ __forceinline__ void ldsm4(u32& r0, u32& r1, u32& r2, u32& r3, u32 saddr) {
    asm volatile("ldmatrix.sync.aligned.m8n8.x4.shared.b16 {%0,%1,%2,%3}, [%4];"
                 : "=r"(r0), "=r"(r1), "=r"(r2), "=r"(r3) : "r"(saddr));
}

__device__ __forceinline__ void cp16(u32* smem_dst, const void* gsrc) {
    unsigned saddr = (unsigned)__cvta_generic_to_shared(smem_dst);
    asm volatile("cp.async.cg.shared.global [%0], [%1], 16;\n" :: "r"(saddr), "l"(gsrc));
}
#define CP_COMMIT() asm volatile("cp.async.commit_group;\n" ::: "memory")
#define CP_WAIT1()  asm volatile("cp.async.wait_group 1;\n" ::: "memory")

// ---------------- bf16 3-term NT GEMM, cp.async 2-stage + ldmatrix ----------------
template<int BM, int BN, int WARPS_M, int NSPLIT>
__global__ __launch_bounds__(256) void gemm_bf3(
    const u16* __restrict__ Ah, const u16* __restrict__ Al,
    const u16* __restrict__ Bh, const u16* __restrict__ Bl,
    float* __restrict__ C, int M, int N, int K, int accum)
{
    constexpr int WARPS_N = 8 / WARPS_M;
    constexpr int WM = BM / WARPS_M;
    constexpr int WN = BN / WARPS_N;
    constexpr int MT = WM / 16;
    constexpr int NT = WN / 8;
    constexpr int AOFF  = 0;
    constexpr int ALOFF = BM * 20;
    constexpr int BOFF  = 2 * BM * 20;
    constexpr int BLOFF = 2 * BM * 20 + BN * 20;
    constexpr int STAGE = 2 * (BM + BN) * 20;   // u32 per stage
    extern __shared__ __align__(16) u32 dsm[];

    int kb = 0, ke = K;
    if (NSPLIT > 1) {
        const int z = blockIdx.z;
        const int steps = K / 32;
        kb = ((z * steps) / NSPLIT) * 32;
        ke = (((z + 1) * steps) / NSPLIT) * 32;
        C += (size_t)z * M * N;
        accum = 0;
    }

    const int bm = blockIdx.y * BM;
    const int bn = blockIdx.x * BN;
    const int tid  = threadIdx.x;
    const int lane = tid & 31;
    const int warp = tid >> 5;
    const int wm = (warp % WARPS_M) * WM;
    const int wn = (warp / WARPS_M) * WN;
    const int g  = lane >> 2;
    const int tg = lane & 3;

    const int lr = tid >> 2;
    const int c4 = (tid & 3) * 4;

    const u32 dsmAddr = smem_u32(dsm);
    const u32 rowA = (lane & 7) + ((lane >> 3) & 1) * 8;
    const u32 kbA  = ((lane >> 4) & 1) * 16;
    const u32 colB = (lane & 7) + ((lane >> 4) & 1) * 8;
    const u32 kbB  = ((lane >> 3) & 1) * 16;
    const u32 aoff = (u32)AOFF * 4 + (wm + rowA) * 80 + kbA;
    const u32 boff = (u32)BOFF * 4 + (wn + colB) * 80 + kbB;

    auto issue = [&](int k0, int s) {
        u32* base = dsm + s * STAGE;
#pragma unroll
        for (int r = 0; r < BM / 64; r++) {
            const int rrow = lr + 64 * r;
            const size_t go = (size_t)(bm + rrow) * K + k0 + c4 * 2;
            cp16(base + AOFF  + rrow * 20 + c4, &Ah[go]);
            cp16(base + ALOFF + rrow * 20 + c4, &Al[go]);
        }
#pragma unroll
        for (int r = 0; r < BN / 64; r++) {
            const int rrow = lr + 64 * r;
            const size_t go = (size_t)(bn + rrow) * K + k0 + c4 * 2;
            cp16(base + BOFF  + rrow * 20 + c4, &Bh[go]);
            cp16(base + BLOFF + rrow * 20 + c4, &Bl[go]);
        }
    };

    float acc[MT][NT][4] = {};

    const int nIters = (ke - kb) / 32;
    issue(kb, 0); CP_COMMIT();

    for (int i = 0; i < nIters; i++) {
        if (i + 1 < nIters) issue(kb + (i + 1) * 32, (i + 1) & 1);
        CP_COMMIT();
        CP_WAIT1();
        __syncthreads();
        const u32 sb = dsmAddr + (u32)((i & 1) * STAGE * 4);

#pragma unroll
        for (int ks = 0; ks < 2; ks++) {
            const u32 kso = (u32)ks * 32;
            u32 ah[MT][4], al[MT][4];
#pragma unroll
            for (int mt = 0; mt < MT; mt++) {
                const u32 base_a = sb + aoff + (u32)mt * 1280 + kso;
                ldsm4(ah[mt][0], ah[mt][1], ah[mt][2], ah[mt][3], base_a);
                ldsm4(al[mt][0], al[mt][1], al[mt][2], al[mt][3], base_a + (u32)BM * 80);
            }
#pragma unroll
            for (int ntp = 0; ntp < NT / 2; ntp++) {
                u32 bh0, bh1, bh2, bh3, bl0, bl1, bl2, bl3;
                const u32 base_b = sb + boff + (u32)ntp * 1280 + kso;
                ldsm4(bh0, bh1, bh2, bh3, base_b);
                ldsm4(bl0, bl1, bl2, bl3, base_b + (u32)BN * 80);
#pragma unroll
                for (int mt = 0; mt < MT; mt++) {
                    mma_bf16(acc[mt][2 * ntp],     ah[mt][0], ah[mt][1], ah[mt][2], ah[mt][3], bh0, bh1);
                    mma_bf16(acc[mt][2 * ntp],     al[mt][0], al[mt][1], al[mt][2], al[mt][3], bh0, bh1);
                    mma_bf16(acc[mt][2 * ntp],     ah[mt][0], ah[mt][1], ah[mt][2], ah[mt][3], bl0, bl1);
                    mma_bf16(acc[mt][2 * ntp + 1], ah[mt][0], ah[mt][1], ah[mt][2], ah[mt][3], bh2, bh3);
                    mma_bf16(acc[mt][2 * ntp + 1], al[mt][0], al[mt][1], al[mt][2], al[mt][3], bh2, bh3);
                    mma_bf16(acc[mt][2 * ntp + 1], ah[mt][0], ah[mt][1], ah[mt][2], ah[mt][3], bl2, bl3);
                }
            }
        }
        __syncthreads();
    }

#pragma unroll
    for (int mt = 0; mt < MT; mt++) {
        const int r0 = bm + wm + mt * 16 + g;
        const int r1 = r0 + 8;
#pragma unroll
        for (int nt = 0; nt < NT; nt++) {
            const int col = bn + wn + nt * 8 + 2 * tg;
            float2* p0 = (float2*)&C[(size_t)r0 * N + col];
            float2* p1 = (float2*)&C[(size_t)r1 * N + col];
            float2 v0 = make_float2(acc[mt][nt][0], acc[mt][nt][1]);
            float2 v1 = make_float2(acc[mt][nt][2], acc[mt][nt][3]);
            if (accum) {
                float2 o0 = *p0, o1 = *p1;
                v0.x += o0.x; v0.y += o0.y; v1.x += o1.x; v1.y += o1.y;
            }
            *p0 = v0;
            *p1 = v1;
        }
    }
}

// ---------------- causal spectral conv, PARITY-SPLIT (half K-depth) ----------------
// E = sum over even i, O = sum over odd i; Up = E+O, Um = st*(E-O).
// B operand: hTe/hTo [b][d][j] (j = i/2) bf16 pairs; A: stride-2 phi pairs.
__global__ __launch_bounds__(256) void conv_bf(
    const u16* __restrict__ hTeh, const u16* __restrict__ hTel,
    const u16* __restrict__ hToh, const u16* __restrict__ hTol,
    const u32* __restrict__ P2h, const u32* __restrict__ P2l,
    u16* __restrict__ Uh, u16* __restrict__ Ul)
{
    constexpr int CXEH = 0;
    constexpr int CXEL = 1280;
    constexpr int CXOH = 2560;
    constexpr int CXOL = 3840;
    constexpr int CQH  = 5120;
    constexpr int CQL  = 5320;
    constexpr int CSTAGE = 5520;   // u32; 22080 B/stage, 2 stages = 44160 B
    __shared__ __align__(16) u32 csm[2 * CSTAGE];

    const int d0 = blockIdx.x * 64;
    const int t0 = blockIdx.y * 128;
    const int b  = blockIdx.z >> 4;
    const int k  = blockIdx.z & 15;
    const int tid  = threadIdx.x;
    const int lane = tid & 31;
    const int warp = tid >> 5;
    const int wm = (warp & 3) * 32;
    const int wn = (warp >> 2) * 32;
    const int g  = lane >> 2;
    const int tg = lane & 3;

    const int xr = tid >> 2;
    const int c4 = (tid & 3) * 4;

    const u32 csmAddr = smem_u32(csm);
    const u32 colB = (lane & 7) + ((lane >> 4) & 1) * 8;
    const u32 kbB  = ((lane >> 3) & 1) * 16;
    const u32 xoff = (wn + colB) * 80 + kbB;

    auto issue = [&](int ii, int s) {
        u32* base = csm + s * CSTAGE;
        const int j0 = ii * 32;
        const size_t go = (size_t)(b * D_ + d0 + xr) * S2_ + j0 + c4 * 2;
        cp16(base + CXEH + xr * 20 + c4, &hTeh[go]);
        cp16(base + CXEL + xr * 20 + c4, &hTel[go]);
        cp16(base + CXOH + xr * 20 + c4, &hToh[go]);
        cp16(base + CXOL + xr * 20 + c4, &hTol[go]);
        // Q window: w[q] = P2[p_start + q], p_start = t0 - 2*j0 - 68 (table offset 192)
        const int tb = k * P2LEN + t0 - 2 * j0 + 124;
        if (tid < 50)
            cp16(base + CQH + tid * 4, &P2h[tb + tid * 4]);
        else if (tid >= 64 && tid < 114)
            cp16(base + CQL + (tid - 64) * 4, &P2l[tb + (tid - 64) * 4]);
    };

    float accE[2][4][4] = {};
    float accO[2][4][4] = {};

    const int nIters = (t0 + 128) / 64;   // >= 2
    issue(0, 0); CP_COMMIT();

    for (int i = 0; i < nIters; i++) {
        if (i + 1 < nIters) issue(i + 1, (i + 1) & 1);
        CP_COMMIT();
        CP_WAIT1();
        __syncthreads();
        const int s = i & 1;
        const u32 sb = csmAddr + (u32)(s * CSTAGE * 4);
        const u32* base = csm + s * CSTAGE;
        const u32* sQh = base + CQH;
        const u32* sQl = base + CQL;

#pragma unroll
        for (int ks = 0; ks < 2; ks++) {
            u32 aEh[2][4], aEl[2][4], aOh[2][4], aOl[2][4];
#pragma unroll
            for (int mt = 0; mt < 2; mt++) {
                const int n = wm + mt * 16 + g - 32 * ks - 4 * tg + 68;
                aEh[mt][0] = sQh[n];      aEh[mt][1] = sQh[n + 8];
                aEh[mt][2] = sQh[n - 16]; aEh[mt][3] = sQh[n - 8];
                aEl[mt][0] = sQl[n];      aEl[mt][1] = sQl[n + 8];
                aEl[mt][2] = sQl[n - 16]; aEl[mt][3] = sQl[n - 8];
                aOh[mt][0] = sQh[n - 1];      aOh[mt][1] = sQh[n + 7];
                aOh[mt][2] = sQh[n - 17];     aOh[mt][3] = sQh[n - 9];
                aOl[mt][0] = sQl[n - 1];      aOl[mt][1] = sQl[n + 7];
                aOl[mt][2] = sQl[n - 17];     aOl[mt][3] = sQl[n - 9];
            }
#pragma unroll
            for (int ntp = 0; ntp < 2; ntp++) {
                u32 eh0, eh1, eh2, eh3, el0, el1, el2, el3;
                u32 oh0, oh1, oh2, oh3, ol0, ol1, ol2, ol3;
                const u32 base_x = sb + xoff + (u32)ntp * 1280 + (u32)ks * 32;
                ldsm4(eh0, eh1, eh2, eh3, base_x);
                ldsm4(el0, el1, el2, el3, base_x + 5120u);
                ldsm4(oh0, oh1, oh2, oh3, base_x + 10240u);
                ldsm4(ol0, ol1, ol2, ol3, base_x + 15360u);
#pragma unroll
                for (int mt = 0; mt < 2; mt++) {
                    float* e0 = accE[mt][2 * ntp];
                    float* e1 = accE[mt][2 * ntp + 1];
                    float* o0 = accO[mt][2 * ntp];
                    float* o1 = accO[mt][2 * ntp + 1];
                    mma_bf16(e0, aEh[mt][0], aEh[mt][1], aEh[mt][2], aEh[mt][3], eh0, eh1);
                    mma_bf16(e0, aEl[mt][0], aEl[mt][1], aEl[mt][2], aEl[mt][3], eh0, eh1);
                    mma_bf16(e0, aEh[mt][0], aEh[mt][1], aEh[mt][2], aEh[mt][3], el0, el1);
                    mma_bf16(e1, aEh[mt][0], aEh[mt][1], aEh[mt][2], aEh[mt][3], eh2, eh3);
                    mma_bf16(e1, aEl[mt][0], aEl[mt][1], aEl[mt][2], aEl[mt][3], eh2, eh3);
                    mma_bf16(e1, aEh[mt][0], aEh[mt][1], aEh[mt][2], aEh[mt][3], el2, el3);
                    mma_bf16(o0, aOh[mt][0], aOh[mt][1], aOh[mt][2], aOh[mt][3], oh0, oh1);
                    mma_bf16(o0, aOl[mt][0], aOl[mt][1], aOl[mt][2], aOl[mt][3], oh0, oh1);
                    mma_bf16(o0, aOh[mt][0], aOh[mt][1], aOh[mt][2], aOh[mt][3], ol0, ol1);
                    mma_bf16(o1, aOh[mt][0], aOh[mt][1], aOh[mt][2], aOh[mt][3], oh2, oh3);
                    mma_bf16(o1, aOl[mt][0], aOl[mt][1], aOl[mt][2], aOl[mt][3], oh2, oh3);
                    mma_bf16(o1, aOh[mt][0], aOh[mt][1], aOh[mt][2], aOh[mt][3], ol2, ol3);
                }
            }
        }
        __syncthreads();
    }

#pragma unroll
    for (int mt = 0; mt < 2; mt++) {
#pragma unroll
        for (int half = 0; half < 2; half++) {
            const int t = t0 + wm + mt * 16 + g + half * 8;
            const float st = (t & 1) ? -1.f : 1.f;
            const size_t rowo = (size_t)(b * S_ + t) * UCOLS;
#pragma unroll
            for (int nt = 0; nt < 4; nt++) {
                const int d = d0 + wn + nt * 8 + 2 * tg;
                const float e0 = accE[mt][nt][half * 2 + 0];
                const float e1 = accE[mt][nt][half * 2 + 1];
                const float o0 = accO[mt][nt][half * 2 + 0];
                const float o1 = accO[mt][nt][half * 2 + 1];
                const float up0 = e0 + o0, up1 = e1 + o1;
                const float um0 = st * (e0 - o0), um1 = st * (e1 - o1);
                u16 h0, l0, h1, l1;
                split_bf(up0, h0, l0); split_bf(up1, h1, l1);
                *(ushort2*)&Uh[rowo + (size_t)k * D_ + d] = make_ushort2(h0, h1);
                *(ushort2*)&Ul[rowo + (size_t)k * D_ + d] = make_ushort2(l0, l1);
                split_bf(um0, h0, l0); split_bf(um1, h1, l1);
                *(ushort2*)&Uh[rowo + (size_t)(K_ + k) * D_ + d] = make_ushort2(h0, h1);
                *(ushort2*)&Ul[rowo + (size_t)(K_ + k) * D_ + d] = make_ushort2(l0, l1);
            }
        }
    }
}

// ---------------- fp32 NT GEMM (tiny out_proj: N=64) ----------------
__global__ __launch_bounds__(256) void gemm_nt(
    const float* __restrict__ A, const float* __restrict__ B, float* __restrict__ C,
    int M, int N, int K, int accum)
{
    __shared__ float As[16][65];
    __shared__ float Bs[16][65];
    const int bm = blockIdx.y * 64;
    const int bn = blockIdx.x * 64;
    const int tid = threadIdx.x;
    const int tx = tid & 15;
    const int ty = tid >> 4;
    const int lr = tid >> 2;
    const int lk = (tid & 3) << 2;

    const float* Ap = A + (size_t)(bm + lr) * K + lk;
    const float* Bp = B + (size_t)(bn + lr) * K + lk;

    float acc[4][4] = {};

    for (int k0 = 0; k0 < K; k0 += 16) {
        float4 av = *(const float4*)(Ap + k0);
        float4 bv = *(const float4*)(Bp + k0);
        __syncthreads();
        As[lk + 0][lr] = av.x; As[lk + 1][lr] = av.y;
        As[lk + 2][lr] = av.z; As[lk + 3][lr] = av.w;
        Bs[lk + 0][lr] = bv.x; Bs[lk + 1][lr] = bv.y;
        Bs[lk + 2][lr] = bv.z; Bs[lk + 3][lr] = bv.w;
        __syncthreads();
#pragma unroll
        for (int kk = 0; kk < 16; kk++) {
            float a[4], b[4];
#pragma unroll
            for (int i = 0; i < 4; i++) a[i] = As[kk][ty * 4 + i];
#pragma unroll
            for (int j = 0; j < 4; j++) b[j] = Bs[kk][tx * 4 + j];
#pragma unroll
            for (int i = 0; i < 4; i++)
#pragma unroll
                for (int j = 0; j < 4; j++)
                    acc[i][j] += a[i] * b[j];
        }
    }

#pragma unroll
    for (int i = 0; i < 4; i++) {
        const int r = bm + ty * 4 + i;
#pragma unroll
        for (int j = 0; j < 4; j++) {
            const int c = bn + tx * 4 + j;
            const size_t idx = (size_t)r * N + c;
            C[idx] = accum ? (C[idx] + acc[i][j]) : acc[i][j];
        }
    }
}

// ---------------- rmsnorm + z copy + AR column scatter (bf16 pairs) ----------------
__global__ __launch_bounds__(256) void rmsnorm_k(
    const float* __restrict__ x, const float* __restrict__ w,
    float* __restrict__ h, float* __restrict__ z,
    u16* __restrict__ Uh, u16* __restrict__ Ul)
{
    __shared__ float red[256];
    const int row = blockIdx.x;
    const int t = row & (S_ - 1);
    const int tid = threadIdx.x;

    const float v0 = x[(size_t)row * D_ + tid];
    const float v1 = x[(size_t)row * D_ + 256 + tid];
    z[(size_t)row * D_ + tid] = v0;
    z[(size_t)row * D_ + 256 + tid] = v1;
    red[tid] = v0 * v0 + v1 * v1;
    __syncthreads();
    for (int s = 128; s > 0; s >>= 1) {
        if (tid < s) red[tid] += red[tid + s];
        __syncthreads();
    }
    const float scale = rsqrtf(red[0] * (1.f / D_) + EPS_);
    const float h0 = v0 * scale * w[tid];
    const float h1 = v1 * scale * w[tid + 256];
    h[(size_t)row * D_ + tid] = h0;
    h[(size_t)row * D_ + 256 + tid] = h1;

    u16 h0h, h0l, h1h, h1l;
    split_bf(h0, h0h, h0l); split_bf(h1, h1h, h1l);

#pragma unroll
    for (int j = 0; j < KU_; j++) {
        if (t + j < S_) {
            const size_t base = (size_t)(row + j) * UCOLS + SPECC + j * D_;
            Uh[base + tid] = h0h; Ul[base + tid] = h0l;
            Uh[base + 256 + tid] = h1h; Ul[base + 256 + tid] = h1l;
        }
        if (t < j) {
            const size_t base = (size_t)row * UCOLS + SPECC + j * D_;
            Uh[base + tid] = 0; Ul[base + tid] = 0;
            Uh[base + 256 + tid] = 0; Ul[base + 256 + tid] = 0;
        }
    }
}

// ---------------- transpose + parity split h -> hTe/hTo pairs ----------------
__global__ __launch_bounds__(256) void transplit_k(
    const float* __restrict__ h,
    u16* __restrict__ hTeh, u16* __restrict__ hTel,
    u16* __restrict__ hToh, u16* __restrict__ hTol)
{
    __shared__ float tile[32][33];
    const int i0 = blockIdx.x * 32;
    const int d0 = blockIdx.y * 32;
    const int b  = blockIdx.z;
    const int tx = threadIdx.x & 31;
    const int ty = threadIdx.x >> 5;
#pragma unroll
    for (int r = 0; r < 4; r++)
        tile[ty + 8 * r][tx] = h[(size_t)(b * S_ + i0 + ty + 8 * r) * D_ + d0 + tx];
    __syncthreads();
#pragma unroll
    for (int r = 0; r < 4; r++) {
        const float v = tile[tx][ty + 8 * r];   // h[b, i0+tx, d0+ty+8r]
        u16 hi, lo; split_bf(v, hi, lo);
        const size_t o = (size_t)(b * D_ + d0 + ty + 8 * r) * S2_ + (i0 >> 1) + (tx >> 1);
        if (tx & 1) { hToh[o] = hi; hTol[o] = lo; }
        else        { hTeh[o] = hi; hTel[o] = lo; }
    }
}

// ---------------- fused weight fill (bf16 pairs) ----------------
__global__ __launch_bounds__(256) void wfill_k(
    const float* __restrict__ sigma, const float* __restrict__ mp,
    const float* __restrict__ mm, const float* __restrict__ mu,
    u16* __restrict__ Wh, u16* __restrict__ Wl)
{
    const size_t idx = (size_t)blockIdx.x * 256 + threadIdx.x;
    if (idx >= (size_t)D_ * UCOLS) return;
    const int o = (int)(idx / UCOLS);
    const int col = (int)(idx % UCOLS);
    float v;
    if (col < K_ * D_) {
        const int k = col / D_, d = col % D_;
        v = sqrtf(sqrtf(sigma[k])) * mp[((size_t)k * D_ + d) * D_ + o];
    } else if (col < SPECC) {
        const int c = col - K_ * D_;
        const int k = c / D_, d = c % D_;
        v = sqrtf(sqrtf(sigma[k])) * mm[((size_t)k * D_ + d) * D_ + o];
    } else {
        const int c = col - SPECC;
        const int j = c / D_, d = c % D_;
        v = mu[((size_t)j * D_ + d) * D_ + o];
    }
    u16 hi, lo; split_bf(v, hi, lo);
    Wh[idx] = hi; Wl[idx] = lo;
}

// ---------------- generic split ----------------
__global__ __launch_bounds__(256) void split_k(
    const float* __restrict__ src, u16* __restrict__ hi, u16* __restrict__ lo, int n)
{
    const int i = blockIdx.x * 256 + threadIdx.x;
    if (i < n) { u16 h, l; split_bf(src[i], h, l); hi[i] = h; lo[i] = l; }
}

// ---------------- stride-2 phi pair table: P2[k][i] = pack(phi[i-192], phi[i-194]) ----------------
__global__ __launch_bounds__(256) void phipack_k(
    const float* __restrict__ phi, u32* __restrict__ P2h, u32* __restrict__ P2l)
{
    const int i = blockIdx.x * 256 + threadIdx.x;
    if (i >= K_ * P2LEN) return;
    const int k = i / P2LEN, pp = i % P2LEN;
    const int p = pp - 192;
    u16 lh = 0, ll = 0, hh = 0, hl = 0;
    if (p >= 0 && p < S_)         split_bf(phi[p * K_ + k], lh, ll);
    if (p - 2 >= 0 && p - 2 < S_) split_bf(phi[(p - 2) * K_ + k], hh, hl);
    P2h[i] = (u32)lh | ((u32)hh << 16);
    P2l[i] = (u32)ll | ((u32)hl << 16);
}

// ---------------- elementwise ----------------
__global__ __launch_bounds__(256) void silu_k(
    const float* __restrict__ m1, u16* __restrict__ m2h, u16* __restrict__ m2l)
{
    const int idx = blockIdx.x * 256 + threadIdx.x;
    const int r = idx >> 11;
    const int j = idx & (H_ - 1);
    const float y = m1[(size_t)r * (2 * H_) + j];
    const float gg = m1[(size_t)r * (2 * H_) + H_ + j];
    const float v = y * gg / (1.f + expf(-gg));
    u16 h, l; split_bf(v, h, l);
    m2h[idx] = h; m2l[idx] = l;
}

__global__ __launch_bounds__(256) void add_k(float* __restrict__ dst, const float* __restrict__ src)
{
    const int i = blockIdx.x * 256 + threadIdx.x;
    float4 a = ((const float4*)dst)[i];
    float4 b = ((const float4*)src)[i];
    a.x += b.x; a.y += b.y; a.z += b.z; a.w += b.w;
    ((float4*)dst)[i] = a;
}

__global__ __launch_bounds__(256) void reduce4_k(
    float* __restrict__ x, const float* __restrict__ p,
    u16* __restrict__ xh, u16* __restrict__ xl)
{
    const int i = blockIdx.x * 256 + threadIdx.x;
    const size_t MN4 = (size_t)R_ * D_ / 4;
    float4 a = ((const float4*)x)[i];
    float4 b0 = ((const float4*)p)[i];
    float4 b1 = ((const float4*)p)[i + MN4];
    float4 b2 = ((const float4*)p)[i + 2 * MN4];
    float4 b3 = ((const float4*)p)[i + 3 * MN4];
    a.x += (b0.x + b1.x) + (b2.x + b3.x);
    a.y += (b0.y + b1.y) + (b2.y + b3.y);
    a.z += (b0.z + b1.z) + (b2.z + b3.z);
    a.w += (b0.w + b1.w) + (b2.w + b3.w);
    ((float4*)x)[i] = a;
    ushort4 vh, vl;
    split_bf(a.x, vh.x, vl.x); split_bf(a.y, vh.y, vl.y);
    split_bf(a.z, vh.z, vl.z); split_bf(a.w, vh.w, vl.w);
    ((ushort4*)xh)[i] = vh;
    ((ushort4*)xl)[i] = vl;
}

// ---------------- launch ----------------
extern "C" void kernel_launch(void* const* d_in, const int* in_sizes, int n_in,
                              void* d_out, int out_size)
{
    const float* inputs  = (const float*)d_in[0];
    const float* sigma   = (const float*)d_in[1];
    const float* phi     = (const float*)d_in[2];
    const float* in_proj = (const float*)d_in[3];
    const float* rn_w    = (const float*)d_in[4];
    const float* M_u     = (const float*)d_in[5];
    const float* M_p     = (const float*)d_in[6];
    const float* M_m     = (const float*)d_in[7];
    const float* fc1     = (const float*)d_in[8];
    const float* fc2     = (const float*)d_in[9];
    const float* out_w   = (const float*)d_in[10];
    float* out = (float*)d_out;

    float *x, *z, *h, *part, *m1;
    u16 *Uh, *Ul, *Wh, *Wl, *m2h, *m2l, *xh, *xl;
    u16 *hTeh, *hTel, *hToh, *hTol;
    u16 *inh, *inl, *iph, *ipl, *f1h, *f1l, *f2h, *f2l;
    u32 *P2h, *P2l;
    cudaGetSymbolAddress((void**)&x,   g_x);
    cudaGetSymbolAddress((void**)&z,   g_z);
    cudaGetSymbolAddress((void**)&h,   g_h);
    cudaGetSymbolAddress((void**)&part,g_part);
    cudaGetSymbolAddress((void**)&m1,  g_m1);
    cudaGetSymbolAddress((void**)&Uh,  g_Uh);
    cudaGetSymbolAddress((void**)&Ul,  g_Ul);
    cudaGetSymbolAddress((void**)&Wh,  g_Wh);
    cudaGetSymbolAddress((void**)&Wl,  g_Wl);
    cudaGetSymbolAddress((void**)&m2h, g_m2h);
    cudaGetSymbolAddress((void**)&m2l, g_m2l);
    cudaGetSymbolAddress((void**)&hTeh, g_hTeh);
    cudaGetSymbolAddress((void**)&hTel, g_hTel);
    cudaGetSymbolAddress((void**)&hToh, g_hToh);
    cudaGetSymbolAddress((void**)&hTol, g_hTol);
    cudaGetSymbolAddress((void**)&xh,  g_xh);
    cudaGetSymbolAddress((void**)&xl,  g_xl);
    cudaGetSymbolAddress((void**)&inh, g_inh);
    cudaGetSymbolAddress((void**)&inl, g_inl);
    cudaGetSymbolAddress((void**)&iph, g_iph);
    cudaGetSymbolAddress((void**)&ipl, g_ipl);
    cudaGetSymbolAddress((void**)&f1h, g_f1h);
    cudaGetSymbolAddress((void**)&f1l, g_f1l);
    cudaGetSymbolAddress((void**)&f2h, g_f2h);
    cudaGetSymbolAddress((void**)&f2l, g_f2l);
    cudaGetSymbolAddress((void**)&P2h, g_P2h);
    cudaGetSymbolAddress((void**)&P2l, g_P2l);

    cudaFuncSetAttribute(gemm_bf3<128, 128, 4, 1>,
                         cudaFuncAttributeMaxDynamicSharedMemorySize, 81920);
    cudaFuncSetAttribute(gemm_bf3<128, 128, 4, NSPLIT_>,
                         cudaFuncAttributeMaxDynamicSharedMemorySize, 81920);

    const int ew_blocks = (R_ * D_ / 4) / 256;
    const int wfill_blocks = (int)(((size_t)D_ * UCOLS + 255) / 256);
    const int silu_blocks = (R_ * H_) / 256;

    phipack_k<<<(K_ * P2LEN + 255) / 256, 256>>>(phi, P2h, P2l);
    split_k<<<(R_ * DIN_ + 255) / 256, 256>>>(inputs, inh, inl, R_ * DIN_);

    for (int m = 0; m < M_; m++) {
        // x = inputs @ in_proj[m]^T   (2048 x 512, K=64)
        split_k<<<(D_ * DIN_ + 255) / 256, 256>>>(
            in_proj + (size_t)m * D_ * DIN_, iph, ipl, D_ * DIN_);
        gemm_bf3<64, 64, 2, 1><<<dim3(D_ / 64, R_ / 64), 256, 40960>>>(
            inh, inl, iph, ipl, x, R_, D_, DIN_, 0);

        for (int l = 0; l < L_; l++) {
            const int ml = m * L_ + l;

            rmsnorm_k<<<R_, 256>>>(x, rn_w + (size_t)ml * D_, h, z, Uh, Ul);
            transplit_k<<<dim3(S_ / 32, D_ / 32, B_), 256>>>(h, hTeh, hTel, hToh, hTol);
            conv_bf<<<dim3(D_ / 64, S_ / 128, B_ * K_), 256>>>(
                hTeh, hTel, hToh, hTol, P2h, P2l, Uh, Ul);
            wfill_k<<<wfill_blocks, 256>>>(
                sigma,
                M_p + (size_t)ml * K_ * D_ * D_,
                M_m + (size_t)ml * K_ * D_ * D_,
                M_u + (size_t)ml * KU_ * D_ * D_,
                Wh, Wl);
            // partials = U @ W^T (split-K=4); x += sum; emit x split for fc1
            gemm_bf3<128, 128, 4, NSPLIT_>
                <<<dim3(D_ / 128, R_ / 128, NSPLIT_), 256, 81920>>>(
                Uh, Ul, Wh, Wl, part, R_, D_, UCOLS, 0);
            reduce4_k<<<ew_blocks, 256>>>(x, part, xh, xl);

            // MLP
            split_k<<<(2 * H_ * D_ + 255) / 256, 256>>>(
                fc1 + (size_t)ml * 2 * H_ * D_, f1h, f1l, 2 * H_ * D_);
            gemm_bf3<128, 128, 4, 1><<<dim3(2 * H_ / 128, R_ / 128), 256, 81920>>>(
                xh, xl, f1h, f1l, m1, R_, 2 * H_, D_, 0);
            silu_k<<<silu_blocks, 256>>>(m1, m2h, m2l);
            split_k<<<(D_ * H_ + 255) / 256, 256>>>(
                fc2 + (size_t)ml * D_ * H_, f2h, f2l, D_ * H_);
            gemm_bf3<64, 64, 2, 1><<<dim3(D_ / 64, R_ / 64), 256, 40960>>>(
                m2h, m2l, f2h, f2l, x, R_, D_, H_, 1);

            add_k<<<ew_blocks, 256>>>(x, z);
        }

        // preds += x @ out_proj[m]^T  (N=64)
        gemm_nt<<<dim3(DIN_ / 64, R_ / 64), 256>>>(
            x, out_w + (size_t)m * DIN_ * D_, out, R_, DIN_, D_, m);
    }
    (void)in_sizes; (void)n_in; (void)out_size;
}

// round 11
// speedup vs baseline: 2.5649x; 1.0426x over previous
#include <cuda_runtime.h>
#include <cuda_bf16.h>
#include <cstddef>

// ---------------- problem constants ----------------
#define B_    2
#define S_    1024
#define S2_   (S_ / 2)
#define DIN_  64
#define D_    512
#define K_    16
#define KU_   3
#define L_    2
#define M_    2
#define H_    2048
#define R_    (B_ * S_)                 // 2048 rows (b*S + t)
#define SPECC (2 * K_ * D_)             // 16384 spectral columns of U
#define UCOLS (SPECC + KU_ * D_)        // 17920 = spectral + AR columns
#define EPS_  1e-5f
#define NSPLIT_ 8
#define P2LEN 1280                      // stride-2 phi pair table (offset 192)

typedef unsigned short u16;
typedef unsigned int   u32;

// ---------------- scratch (static device globals; no allocation) ----------------
__device__ __align__(16) float g_x[R_ * D_];
__device__ __align__(16) float g_z[R_ * D_];
__device__ __align__(16) float g_h[R_ * D_];
__device__ __align__(16) float g_part[(size_t)NSPLIT_ * R_ * D_];
__device__ __align__(16) float g_m1[(size_t)R_ * 2 * H_];

__device__ __align__(16) u16 g_Uh[(size_t)R_ * UCOLS];
__device__ __align__(16) u16 g_Ul[(size_t)R_ * UCOLS];
__device__ __align__(16) u16 g_Wh[(size_t)D_ * UCOLS];
__device__ __align__(16) u16 g_Wl[(size_t)D_ * UCOLS];
__device__ __align__(16) u16 g_m2h[(size_t)R_ * H_];
__device__ __align__(16) u16 g_m2l[(size_t)R_ * H_];
__device__ __align__(16) u16 g_hTeh[B_ * D_ * S2_];
__device__ __align__(16) u16 g_hTel[B_ * D_ * S2_];
__device__ __align__(16) u16 g_hToh[B_ * D_ * S2_];
__device__ __align__(16) u16 g_hTol[B_ * D_ * S2_];
__device__ __align__(16) u16 g_xh[R_ * D_];
__device__ __align__(16) u16 g_xl[R_ * D_];
__device__ __align__(16) u16 g_inh[R_ * DIN_];
__device__ __align__(16) u16 g_inl[R_ * DIN_];
__device__ __align__(16) u16 g_iph[D_ * DIN_];
__device__ __align__(16) u16 g_ipl[D_ * DIN_];
__device__ __align__(16) u16 g_f1h[2 * H_ * D_];
__device__ __align__(16) u16 g_f1l[2 * H_ * D_];
__device__ __align__(16) u16 g_f2h[D_ * H_];
__device__ __align__(16) u16 g_f2l[D_ * H_];
__device__ __align__(16) u32 g_P2h[K_ * P2LEN];
__device__ __align__(16) u32 g_P2l[K_ * P2LEN];

// ---------------- helpers ----------------
__device__ __forceinline__ void split_bf(float a, u16& hi, u16& lo) {
    __nv_bfloat16 h = __float2bfloat16(a);
    float r = a - __bfloat162float(h);
    __nv_bfloat16 l = __float2bfloat16(r);
    hi = reinterpret_cast<u16&>(h);
    lo = reinterpret_cast<u16&>(l);
}

__device__ __forceinline__ void mma_bf16(float c[4],
                                         u32 a0, u32 a1, u32 a2, u32 a3,
                                         u32 b0, u32 b1) {
    asm volatile(
        "mma.sync.aligned.m16n8k16.row.col.f32.bf16.bf16.f32 "
        "{%0,%1,%2,%3},{%4,%5,%6,%7},{%8,%9},{%0,%1,%2,%3};\n"
        : "+f"(c[0]), "+f"(c[1]), "+f"(c[2]), "+f"(c[3])
        : "r"(a0), "r"(a1), "r"(a2), "r"(a3), "r"(b0), "r"(b1));
}

__device__ __forceinline__ u32 smem_u32(const void* p) {
    u32 a;
    asm("{ .reg .u64 t; cvta.to.shared.u64 t, %1; cvt.u32.u64 %0, t; }" : "=r"(a) : "l"(p));
    return a;
}

__device__ __forceinline__ void ldsm4(u32& r0, u32& r1, u32& r2, u32& r3, u32 saddr) {
    asm volatile("ldmatrix.sync.aligned.m8n8.x4.shared.b16 {%0,%1,%2,%3}, [%4];"
                 : "=r"(r0), "=r"(r1), "=r"(r2), "=r"(r3) : "r"(saddr));
}

__device__ __forceinline__ void cp16(u32* smem_dst, const void* gsrc) {
    unsigned saddr = (unsigned)__cvta_generic_to_shared(smem_dst);
    asm volatile("cp.async.cg.shared.global [%0], [%1], 16;\n" :: "r"(saddr), "l"(gsrc));
}
#define CP_COMMIT() asm volatile("cp.async.commit_group;\n" ::: "memory")
#define CP_WAIT1()  asm volatile("cp.async.wait_group 1;\n" ::: "memory")

// ---------------- bf16 3-term NT GEMM, cp.async 2-stage + ldmatrix ----------------
template<int BM, int BN, int WARPS_M, int NSPLIT>
__global__ __launch_bounds__(256) void gemm_bf3(
    const u16* __restrict__ Ah, const u16* __restrict__ Al,
    const u16* __restrict__ Bh, const u16* __restrict__ Bl,
    float* __restrict__ C, int M, int N, int K, int accum)
{
    constexpr int WARPS_N = 8 / WARPS_M;
    constexpr int WM = BM / WARPS_M;
    constexpr int WN = BN / WARPS_N;
    constexpr int MT = WM / 16;
    constexpr int NT = WN / 8;
    constexpr int AOFF  = 0;
    constexpr int ALOFF = BM * 20;
    constexpr int BOFF  = 2 * BM * 20;
    constexpr int BLOFF = 2 * BM * 20 + BN * 20;
    constexpr int STAGE = 2 * (BM + BN) * 20;   // u32 per stage
    extern __shared__ __align__(16) u32 dsm[];

    int kb = 0, ke = K;
    if (NSPLIT > 1) {
        const int z = blockIdx.z;
        const int steps = K / 32;
        kb = ((z * steps) / NSPLIT) * 32;
        ke = (((z + 1) * steps) / NSPLIT) * 32;
        C += (size_t)z * M * N;
        accum = 0;
    }

    const int bm = blockIdx.y * BM;
    const int bn = blockIdx.x * BN;
    const int tid  = threadIdx.x;
    const int lane = tid & 31;
    const int warp = tid >> 5;
    const int wm = (warp % WARPS_M) * WM;
    const int wn = (warp / WARPS_M) * WN;
    const int g  = lane >> 2;
    const int tg = lane & 3;

    const int lr = tid >> 2;
    const int c4 = (tid & 3) * 4;

    const u32 dsmAddr = smem_u32(dsm);
    const u32 rowA = (lane & 7) + ((lane >> 3) & 1) * 8;
    const u32 kbA  = ((lane >> 4) & 1) * 16;
    const u32 colB = (lane & 7) + ((lane >> 4) & 1) * 8;
    const u32 kbB  = ((lane >> 3) & 1) * 16;
    const u32 aoff = (u32)AOFF * 4 + (wm + rowA) * 80 + kbA;
    const u32 boff = (u32)BOFF * 4 + (wn + colB) * 80 + kbB;

    auto issue = [&](int k0, int s) {
        u32* base = dsm + s * STAGE;
#pragma unroll
        for (int r = 0; r < BM / 64; r++) {
            const int rrow = lr + 64 * r;
            const size_t go = (size_t)(bm + rrow) * K + k0 + c4 * 2;
            cp16(base + AOFF  + rrow * 20 + c4, &Ah[go]);
            cp16(base + ALOFF + rrow * 20 + c4, &Al[go]);
        }
#pragma unroll
        for (int r = 0; r < BN / 64; r++) {
            const int rrow = lr + 64 * r;
            const size_t go = (size_t)(bn + rrow) * K + k0 + c4 * 2;
            cp16(base + BOFF  + rrow * 20 + c4, &Bh[go]);
            cp16(base + BLOFF + rrow * 20 + c4, &Bl[go]);
        }
    };

    float acc[MT][NT][4] = {};

    const int nIters = (ke - kb) / 32;
    issue(kb, 0); CP_COMMIT();

    for (int i = 0; i < nIters; i++) {
        if (i + 1 < nIters) issue(kb + (i + 1) * 32, (i + 1) & 1);
        CP_COMMIT();
        CP_WAIT1();
        __syncthreads();
        const u32 sb = dsmAddr + (u32)((i & 1) * STAGE * 4);

#pragma unroll
        for (int ks = 0; ks < 2; ks++) {
            const u32 kso = (u32)ks * 32;
            u32 ah[MT][4], al[MT][4];
#pragma unroll
            for (int mt = 0; mt < MT; mt++) {
                const u32 base_a = sb + aoff + (u32)mt * 1280 + kso;
                ldsm4(ah[mt][0], ah[mt][1], ah[mt][2], ah[mt][3], base_a);
                ldsm4(al[mt][0], al[mt][1], al[mt][2], al[mt][3], base_a + (u32)BM * 80);
            }
#pragma unroll
            for (int ntp = 0; ntp < NT / 2; ntp++) {
                u32 bh0, bh1, bh2, bh3, bl0, bl1, bl2, bl3;
                const u32 base_b = sb + boff + (u32)ntp * 1280 + kso;
                ldsm4(bh0, bh1, bh2, bh3, base_b);
                ldsm4(bl0, bl1, bl2, bl3, base_b + (u32)BN * 80);
#pragma unroll
                for (int mt = 0; mt < MT; mt++) {
                    mma_bf16(acc[mt][2 * ntp],     ah[mt][0], ah[mt][1], ah[mt][2], ah[mt][3], bh0, bh1);
                    mma_bf16(acc[mt][2 * ntp],     al[mt][0], al[mt][1], al[mt][2], al[mt][3], bh0, bh1);
                    mma_bf16(acc[mt][2 * ntp],     ah[mt][0], ah[mt][1], ah[mt][2], ah[mt][3], bl0, bl1);
                    mma_bf16(acc[mt][2 * ntp + 1], ah[mt][0], ah[mt][1], ah[mt][2], ah[mt][3], bh2, bh3);
                    mma_bf16(acc[mt][2 * ntp + 1], al[mt][0], al[mt][1], al[mt][2], al[mt][3], bh2, bh3);
                    mma_bf16(acc[mt][2 * ntp + 1], ah[mt][0], ah[mt][1], ah[mt][2], ah[mt][3], bl2, bl3);
                }
            }
        }
        __syncthreads();
    }

#pragma unroll
    for (int mt = 0; mt < MT; mt++) {
        const int r0 = bm + wm + mt * 16 + g;
        const int r1 = r0 + 8;
#pragma unroll
        for (int nt = 0; nt < NT; nt++) {
            const int col = bn + wn + nt * 8 + 2 * tg;
            float2* p0 = (float2*)&C[(size_t)r0 * N + col];
            float2* p1 = (float2*)&C[(size_t)r1 * N + col];
            float2 v0 = make_float2(acc[mt][nt][0], acc[mt][nt][1]);
            float2 v1 = make_float2(acc[mt][nt][2], acc[mt][nt][3]);
            if (accum) {
                float2 o0 = *p0, o1 = *p1;
                v0.x += o0.x; v0.y += o0.y; v1.x += o1.x; v1.y += o1.y;
            }
            *p0 = v0;
            *p1 = v1;
        }
    }
}

// ---------------- causal spectral conv, PARITY-SPLIT (half K-depth) ----------------
__global__ __launch_bounds__(256) void conv_bf(
    const u16* __restrict__ hTeh, const u16* __restrict__ hTel,
    const u16* __restrict__ hToh, const u16* __restrict__ hTol,
    const u32* __restrict__ P2h, const u32* __restrict__ P2l,
    u16* __restrict__ Uh, u16* __restrict__ Ul)
{
    constexpr int CXEH = 0;
    constexpr int CXEL = 1280;
    constexpr int CXOH = 2560;
    constexpr int CXOL = 3840;
    constexpr int CQH  = 5120;
    constexpr int CQL  = 5320;
    constexpr int CSTAGE = 5520;   // u32
    __shared__ __align__(16) u32 csm[2 * CSTAGE];

    const int d0 = blockIdx.x * 64;
    const int t0 = blockIdx.y * 128;
    const int b  = blockIdx.z >> 4;
    const int k  = blockIdx.z & 15;
    const int tid  = threadIdx.x;
    const int lane = tid & 31;
    const int warp = tid >> 5;
    const int wm = (warp & 3) * 32;
    const int wn = (warp >> 2) * 32;
    const int g  = lane >> 2;
    const int tg = lane & 3;

    const int xr = tid >> 2;
    const int c4 = (tid & 3) * 4;

    const u32 csmAddr = smem_u32(csm);
    const u32 colB = (lane & 7) + ((lane >> 4) & 1) * 8;
    const u32 kbB  = ((lane >> 3) & 1) * 16;
    const u32 xoff = (wn + colB) * 80 + kbB;

    auto issue = [&](int ii, int s) {
        u32* base = csm + s * CSTAGE;
        const int j0 = ii * 32;
        const size_t go = (size_t)(b * D_ + d0 + xr) * S2_ + j0 + c4 * 2;
        cp16(base + CXEH + xr * 20 + c4, &hTeh[go]);
        cp16(base + CXEL + xr * 20 + c4, &hTel[go]);
        cp16(base + CXOH + xr * 20 + c4, &hToh[go]);
        cp16(base + CXOL + xr * 20 + c4, &hTol[go]);
        const int tb = k * P2LEN + t0 - 2 * j0 + 124;
        if (tid < 50)
            cp16(base + CQH + tid * 4, &P2h[tb + tid * 4]);
        else if (tid >= 64 && tid < 114)
            cp16(base + CQL + (tid - 64) * 4, &P2l[tb + (tid - 64) * 4]);
    };

    float accE[2][4][4] = {};
    float accO[2][4][4] = {};

    const int nIters = (t0 + 128) / 64;
    issue(0, 0); CP_COMMIT();

    for (int i = 0; i < nIters; i++) {
        if (i + 1 < nIters) issue(i + 1, (i + 1) & 1);
        CP_COMMIT();
        CP_WAIT1();
        __syncthreads();
        const int s = i & 1;
        const u32 sb = csmAddr + (u32)(s * CSTAGE * 4);
        const u32* base = csm + s * CSTAGE;
        const u32* sQh = base + CQH;
        const u32* sQl = base + CQL;

#pragma unroll
        for (int ks = 0; ks < 2; ks++) {
            u32 aEh[2][4], aEl[2][4], aOh[2][4], aOl[2][4];
#pragma unroll
            for (int mt = 0; mt < 2; mt++) {
                const int n = wm + mt * 16 + g - 32 * ks - 4 * tg + 68;
                aEh[mt][0] = sQh[n];      aEh[mt][1] = sQh[n + 8];
                aEh[mt][2] = sQh[n - 16]; aEh[mt][3] = sQh[n - 8];
                aEl[mt][0] = sQl[n];      aEl[mt][1] = sQl[n + 8];
                aEl[mt][2] = sQl[n - 16]; aEl[mt][3] = sQl[n - 8];
                aOh[mt][0] = sQh[n - 1];      aOh[mt][1] = sQh[n + 7];
                aOh[mt][2] = sQh[n - 17];     aOh[mt][3] = sQh[n - 9];
                aOl[mt][0] = sQl[n - 1];      aOl[mt][1] = sQl[n + 7];
                aOl[mt][2] = sQl[n - 17];     aOl[mt][3] = sQl[n - 9];
            }
#pragma unroll
            for (int ntp = 0; ntp < 2; ntp++) {
                u32 eh0, eh1, eh2, eh3, el0, el1, el2, el3;
                u32 oh0, oh1, oh2, oh3, ol0, ol1, ol2, ol3;
                const u32 base_x = sb + xoff + (u32)ntp * 1280 + (u32)ks * 32;
                ldsm4(eh0, eh1, eh2, eh3, base_x);
                ldsm4(el0, el1, el2, el3, base_x + 5120u);
                ldsm4(oh0, oh1, oh2, oh3, base_x + 10240u);
                ldsm4(ol0, ol1, ol2, ol3, base_x + 15360u);
#pragma unroll
                for (int mt = 0; mt < 2; mt++) {
                    float* e0 = accE[mt][2 * ntp];
                    float* e1 = accE[mt][2 * ntp + 1];
                    float* o0 = accO[mt][2 * ntp];
                    float* o1 = accO[mt][2 * ntp + 1];
                    mma_bf16(e0, aEh[mt][0], aEh[mt][1], aEh[mt][2], aEh[mt][3], eh0, eh1);
                    mma_bf16(e0, aEl[mt][0], aEl[mt][1], aEl[mt][2], aEl[mt][3], eh0, eh1);
                    mma_bf16(e0, aEh[mt][0], aEh[mt][1], aEh[mt][2], aEh[mt][3], el0, el1);
                    mma_bf16(e1, aEh[mt][0], aEh[mt][1], aEh[mt][2], aEh[mt][3], eh2, eh3);
                    mma_bf16(e1, aEl[mt][0], aEl[mt][1], aEl[mt][2], aEl[mt][3], eh2, eh3);
                    mma_bf16(e1, aEh[mt][0], aEh[mt][1], aEh[mt][2], aEh[mt][3], el2, el3);
                    mma_bf16(o0, aOh[mt][0], aOh[mt][1], aOh[mt][2], aOh[mt][3], oh0, oh1);
                    mma_bf16(o0, aOl[mt][0], aOl[mt][1], aOl[mt][2], aOl[mt][3], oh0, oh1);
                    mma_bf16(o0, aOh[mt][0], aOh[mt][1], aOh[mt][2], aOh[mt][3], ol0, ol1);
                    mma_bf16(o1, aOh[mt][0], aOh[mt][1], aOh[mt][2], aOh[mt][3], oh2, oh3);
                    mma_bf16(o1, aOl[mt][0], aOl[mt][1], aOl[mt][2], aOl[mt][3], oh2, oh3);
                    mma_bf16(o1, aOh[mt][0], aOh[mt][1], aOh[mt][2], aOh[mt][3], ol2, ol3);
                }
            }
        }
        __syncthreads();
    }

#pragma unroll
    for (int mt = 0; mt < 2; mt++) {
#pragma unroll
        for (int half = 0; half < 2; half++) {
            const int t = t0 + wm + mt * 16 + g + half * 8;
            const float st = (t & 1) ? -1.f : 1.f;
            const size_t rowo = (size_t)(b * S_ + t) * UCOLS;
#pragma unroll
            for (int nt = 0; nt < 4; nt++) {
                const int d = d0 + wn + nt * 8 + 2 * tg;
                const float e0 = accE[mt][nt][half * 2 + 0];
                const float e1 = accE[mt][nt][half * 2 + 1];
                const float o0 = accO[mt][nt][half * 2 + 0];
                const float o1 = accO[mt][nt][half * 2 + 1];
                const float up0 = e0 + o0, up1 = e1 + o1;
                const float um0 = st * (e0 - o0), um1 = st * (e1 - o1);
                u16 h0, l0, h1, l1;
                split_bf(up0, h0, l0); split_bf(up1, h1, l1);
                *(ushort2*)&Uh[rowo + (size_t)k * D_ + d] = make_ushort2(h0, h1);
                *(ushort2*)&Ul[rowo + (size_t)k * D_ + d] = make_ushort2(l0, l1);
                split_bf(um0, h0, l0); split_bf(um1, h1, l1);
                *(ushort2*)&Uh[rowo + (size_t)(K_ + k) * D_ + d] = make_ushort2(h0, h1);
                *(ushort2*)&Ul[rowo + (size_t)(K_ + k) * D_ + d] = make_ushort2(l0, l1);
            }
        }
    }
}

// ---------------- fp32 NT GEMM (tiny out_proj: N=64) ----------------
__global__ __launch_bounds__(256) void gemm_nt(
    const float* __restrict__ A, const float* __restrict__ B, float* __restrict__ C,
    int M, int N, int K, int accum)
{
    __shared__ float As[16][65];
    __shared__ float Bs[16][65];
    const int bm = blockIdx.y * 64;
    const int bn = blockIdx.x * 64;
    const int tid = threadIdx.x;
    const int tx = tid & 15;
    const int ty = tid >> 4;
    const int lr = tid >> 2;
    const int lk = (tid & 3) << 2;

    const float* Ap = A + (size_t)(bm + lr) * K + lk;
    const float* Bp = B + (size_t)(bn + lr) * K + lk;

    float acc[4][4] = {};

    for (int k0 = 0; k0 < K; k0 += 16) {
        float4 av = *(const float4*)(Ap + k0);
        float4 bv = *(const float4*)(Bp + k0);
        __syncthreads();
        As[lk + 0][lr] = av.x; As[lk + 1][lr] = av.y;
        As[lk + 2][lr] = av.z; As[lk + 3][lr] = av.w;
        Bs[lk + 0][lr] = bv.x; Bs[lk + 1][lr] = bv.y;
        Bs[lk + 2][lr] = bv.z; Bs[lk + 3][lr] = bv.w;
        __syncthreads();
#pragma unroll
        for (int kk = 0; kk < 16; kk++) {
            float a[4], b[4];
#pragma unroll
            for (int i = 0; i < 4; i++) a[i] = As[kk][ty * 4 + i];
#pragma unroll
            for (int j = 0; j < 4; j++) b[j] = Bs[kk][tx * 4 + j];
#pragma unroll
            for (int i = 0; i < 4; i++)
#pragma unroll
                for (int j = 0; j < 4; j++)
                    acc[i][j] += a[i] * b[j];
        }
    }

#pragma unroll
    for (int i = 0; i < 4; i++) {
        const int r = bm + ty * 4 + i;
#pragma unroll
        for (int j = 0; j < 4; j++) {
            const int c = bn + tx * 4 + j;
            const size_t idx = (size_t)r * N + c;
            C[idx] = accum ? (C[idx] + acc[i][j]) : acc[i][j];
        }
    }
}

// ---------------- rmsnorm + z copy + AR column scatter (bf16 pairs) ----------------
__global__ __launch_bounds__(256) void rmsnorm_k(
    const float* __restrict__ x, const float* __restrict__ w,
    float* __restrict__ h, float* __restrict__ z,
    u16* __restrict__ Uh, u16* __restrict__ Ul)
{
    __shared__ float red[256];
    const int row = blockIdx.x;
    const int t = row & (S_ - 1);
    const int tid = threadIdx.x;

    const float v0 = x[(size_t)row * D_ + tid];
    const float v1 = x[(size_t)row * D_ + 256 + tid];
    z[(size_t)row * D_ + tid] = v0;
    z[(size_t)row * D_ + 256 + tid] = v1;
    red[tid] = v0 * v0 + v1 * v1;
    __syncthreads();
    for (int s = 128; s > 0; s >>= 1) {
        if (tid < s) red[tid] += red[tid + s];
        __syncthreads();
    }
    const float scale = rsqrtf(red[0] * (1.f / D_) + EPS_);
    const float h0 = v0 * scale * w[tid];
    const float h1 = v1 * scale * w[tid + 256];
    h[(size_t)row * D_ + tid] = h0;
    h[(size_t)row * D_ + 256 + tid] = h1;

    u16 h0h, h0l, h1h, h1l;
    split_bf(h0, h0h, h0l); split_bf(h1, h1h, h1l);

#pragma unroll
    for (int j = 0; j < KU_; j++) {
        if (t + j < S_) {
            const size_t base = (size_t)(row + j) * UCOLS + SPECC + j * D_;
            Uh[base + tid] = h0h; Ul[base + tid] = h0l;
            Uh[base + 256 + tid] = h1h; Ul[base + 256 + tid] = h1l;
        }
        if (t < j) {
            const size_t base = (size_t)row * UCOLS + SPECC + j * D_;
            Uh[base + tid] = 0; Ul[base + tid] = 0;
            Uh[base + 256 + tid] = 0; Ul[base + 256 + tid] = 0;
        }
    }
}

// ---------------- transpose + parity split h -> hTe/hTo pairs ----------------
__global__ __launch_bounds__(256) void transplit_k(
    const float* __restrict__ h,
    u16* __restrict__ hTeh, u16* __restrict__ hTel,
    u16* __restrict__ hToh, u16* __restrict__ hTol)
{
    __shared__ float tile[32][33];
    const int i0 = blockIdx.x * 32;
    const int d0 = blockIdx.y * 32;
    const int b  = blockIdx.z;
    const int tx = threadIdx.x & 31;
    const int ty = threadIdx.x >> 5;
#pragma unroll
    for (int r = 0; r < 4; r++)
        tile[ty + 8 * r][tx] = h[(size_t)(b * S_ + i0 + ty + 8 * r) * D_ + d0 + tx];
    __syncthreads();
#pragma unroll
    for (int r = 0; r < 4; r++) {
        const float v = tile[tx][ty + 8 * r];
        u16 hi, lo; split_bf(v, hi, lo);
        const size_t o = (size_t)(b * D_ + d0 + ty + 8 * r) * S2_ + (i0 >> 1) + (tx >> 1);
        if (tx & 1) { hToh[o] = hi; hTol[o] = lo; }
        else        { hTeh[o] = hi; hTel[o] = lo; }
    }
}

// ---------------- fused weight fill (bf16 pairs) ----------------
__global__ __launch_bounds__(256) void wfill_k(
    const float* __restrict__ sigma, const float* __restrict__ mp,
    const float* __restrict__ mm, const float* __restrict__ mu,
    u16* __restrict__ Wh, u16* __restrict__ Wl)
{
    const size_t idx = (size_t)blockIdx.x * 256 + threadIdx.x;
    if (idx >= (size_t)D_ * UCOLS) return;
    const int o = (int)(idx / UCOLS);
    const int col = (int)(idx % UCOLS);
    float v;
    if (col < K_ * D_) {
        const int k = col / D_, d = col % D_;
        v = sqrtf(sqrtf(sigma[k])) * mp[((size_t)k * D_ + d) * D_ + o];
    } else if (col < SPECC) {
        const int c = col - K_ * D_;
        const int k = c / D_, d = c % D_;
        v = sqrtf(sqrtf(sigma[k])) * mm[((size_t)k * D_ + d) * D_ + o];
    } else {
        const int c = col - SPECC;
        const int j = c / D_, d = c % D_;
        v = mu[((size_t)j * D_ + d) * D_ + o];
    }
    u16 hi, lo; split_bf(v, hi, lo);
    Wh[idx] = hi; Wl[idx] = lo;
}

// ---------------- generic split ----------------
__global__ __launch_bounds__(256) void split_k(
    const float* __restrict__ src, u16* __restrict__ hi, u16* __restrict__ lo, int n)
{
    const int i = blockIdx.x * 256 + threadIdx.x;
    if (i < n) { u16 h, l; split_bf(src[i], h, l); hi[i] = h; lo[i] = l; }
}

// ---------------- stride-2 phi pair table ----------------
__global__ __launch_bounds__(256) void phipack_k(
    const float* __restrict__ phi, u32* __restrict__ P2h, u32* __restrict__ P2l)
{
    const int i = blockIdx.x * 256 + threadIdx.x;
    if (i >= K_ * P2LEN) return;
    const int k = i / P2LEN, pp = i % P2LEN;
    const int p = pp - 192;
    u16 lh = 0, ll = 0, hh = 0, hl = 0;
    if (p >= 0 && p < S_)         split_bf(phi[p * K_ + k], lh, ll);
    if (p - 2 >= 0 && p - 2 < S_) split_bf(phi[(p - 2) * K_ + k], hh, hl);
    P2h[i] = (u32)lh | ((u32)hh << 16);
    P2l[i] = (u32)ll | ((u32)hl << 16);
}

// ---------------- elementwise ----------------
__global__ __launch_bounds__(256) void silu_k(
    const float* __restrict__ m1, u16* __restrict__ m2h, u16* __restrict__ m2l)
{
    const int idx = blockIdx.x * 256 + threadIdx.x;
    const int r = idx >> 11;
    const int j = idx & (H_ - 1);
    const float y = m1[(size_t)r * (2 * H_) + j];
    const float gg = m1[(size_t)r * (2 * H_) + H_ + j];
    const float v = y * gg / (1.f + expf(-gg));
    u16 h, l; split_bf(v, h, l);
    m2h[idx] = h; m2l[idx] = l;
}

// x += sum of 8 partials; emit bf16 split of new x
__global__ __launch_bounds__(256) void reduce8_k(
    float* __restrict__ x, const float* __restrict__ p,
    u16* __restrict__ xh, u16* __restrict__ xl)
{
    const int i = blockIdx.x * 256 + threadIdx.x;
    const size_t MN4 = (size_t)R_ * D_ / 4;
    float4 a = ((const float4*)x)[i];
    float sx = 0.f, sy = 0.f, sz = 0.f, sw = 0.f;
#pragma unroll
    for (int j = 0; j < 8; j++) {
        float4 bj = ((const float4*)p)[i + j * MN4];
        sx += bj.x; sy += bj.y; sz += bj.z; sw += bj.w;
    }
    a.x += sx; a.y += sy; a.z += sz; a.w += sw;
    ((float4*)x)[i] = a;
    ushort4 vh, vl;
    split_bf(a.x, vh.x, vl.x); split_bf(a.y, vh.y, vl.y);
    split_bf(a.z, vh.z, vl.z); split_bf(a.w, vh.w, vl.w);
    ((ushort4*)xh)[i] = vh;
    ((ushort4*)xl)[i] = vl;
}

// x += sum of 4 partials + z   (fc2 epilogue + layer residual)
__global__ __launch_bounds__(256) void reduce4z_k(
    float* __restrict__ x, const float* __restrict__ p, const float* __restrict__ z)
{
    const int i = blockIdx.x * 256 + threadIdx.x;
    const size_t MN4 = (size_t)R_ * D_ / 4;
    float4 a = ((const float4*)x)[i];
    float4 b0 = ((const float4*)p)[i];
    float4 b1 = ((const float4*)p)[i + MN4];
    float4 b2 = ((const float4*)p)[i + 2 * MN4];
    float4 b3 = ((const float4*)p)[i + 3 * MN4];
    float4 zz = ((const float4*)z)[i];
    a.x += (b0.x + b1.x) + (b2.x + b3.x) + zz.x;
    a.y += (b0.y + b1.y) + (b2.y + b3.y) + zz.y;
    a.z += (b0.z + b1.z) + (b2.z + b3.z) + zz.z;
    a.w += (b0.w + b1.w) + (b2.w + b3.w) + zz.w;
    ((float4*)x)[i] = a;
}

// ---------------- launch ----------------
extern "C" void kernel_launch(void* const* d_in, const int* in_sizes, int n_in,
                              void* d_out, int out_size)
{
    const float* inputs  = (const float*)d_in[0];
    const float* sigma   = (const float*)d_in[1];
    const float* phi     = (const float*)d_in[2];
    const float* in_proj = (const float*)d_in[3];
    const float* rn_w    = (const float*)d_in[4];
    const float* M_u     = (const float*)d_in[5];
    const float* M_p     = (const float*)d_in[6];
    const float* M_m     = (const float*)d_in[7];
    const float* fc1     = (const float*)d_in[8];
    const float* fc2     = (const float*)d_in[9];
    const float* out_w   = (const float*)d_in[10];
    float* out = (float*)d_out;

    float *x, *z, *h, *part, *m1;
    u16 *Uh, *Ul, *Wh, *Wl, *m2h, *m2l, *xh, *xl;
    u16 *hTeh, *hTel, *hToh, *hTol;
    u16 *inh, *inl, *iph, *ipl, *f1h, *f1l, *f2h, *f2l;
    u32 *P2h, *P2l;
    cudaGetSymbolAddress((void**)&x,   g_x);
    cudaGetSymbolAddress((void**)&z,   g_z);
    cudaGetSymbolAddress((void**)&h,   g_h);
    cudaGetSymbolAddress((void**)&part,g_part);
    cudaGetSymbolAddress((void**)&m1,  g_m1);
    cudaGetSymbolAddress((void**)&Uh,  g_Uh);
    cudaGetSymbolAddress((void**)&Ul,  g_Ul);
    cudaGetSymbolAddress((void**)&Wh,  g_Wh);
    cudaGetSymbolAddress((void**)&Wl,  g_Wl);
    cudaGetSymbolAddress((void**)&m2h, g_m2h);
    cudaGetSymbolAddress((void**)&m2l, g_m2l);
    cudaGetSymbolAddress((void**)&hTeh, g_hTeh);
    cudaGetSymbolAddress((void**)&hTel, g_hTel);
    cudaGetSymbolAddress((void**)&hToh, g_hToh);
    cudaGetSymbolAddress((void**)&hTol, g_hTol);
    cudaGetSymbolAddress((void**)&xh,  g_xh);
    cudaGetSymbolAddress((void**)&xl,  g_xl);
    cudaGetSymbolAddress((void**)&inh, g_inh);
    cudaGetSymbolAddress((void**)&inl, g_inl);
    cudaGetSymbolAddress((void**)&iph, g_iph);
    cudaGetSymbolAddress((void**)&ipl, g_ipl);
    cudaGetSymbolAddress((void**)&f1h, g_f1h);
    cudaGetSymbolAddress((void**)&f1l, g_f1l);
    cudaGetSymbolAddress((void**)&f2h, g_f2h);
    cudaGetSymbolAddress((void**)&f2l, g_f2l);
    cudaGetSymbolAddress((void**)&P2h, g_P2h);
    cudaGetSymbolAddress((void**)&P2l, g_P2l);

    // 64x128 stage = 2*(64+128)*20*4*2 = 61440 B > 48K default
    cudaFuncSetAttribute(gemm_bf3<64, 128, 2, 1>,
                         cudaFuncAttributeMaxDynamicSharedMemorySize, 61440);
    cudaFuncSetAttribute(gemm_bf3<64, 128, 2, NSPLIT_>,
                         cudaFuncAttributeMaxDynamicSharedMemorySize, 61440);

    const int ew_blocks = (R_ * D_ / 4) / 256;
    const int wfill_blocks = (int)(((size_t)D_ * UCOLS + 255) / 256);
    const int silu_blocks = (R_ * H_) / 256;

    phipack_k<<<(K_ * P2LEN + 255) / 256, 256>>>(phi, P2h, P2l);
    split_k<<<(R_ * DIN_ + 255) / 256, 256>>>(inputs, inh, inl, R_ * DIN_);

    for (int m = 0; m < M_; m++) {
        // x = inputs @ in_proj[m]^T   (2048 x 512, K=64)
        split_k<<<(D_ * DIN_ + 255) / 256, 256>>>(
            in_proj + (size_t)m * D_ * DIN_, iph, ipl, D_ * DIN_);
        gemm_bf3<64, 64, 2, 1><<<dim3(D_ / 64, R_ / 64), 256, 40960>>>(
            inh, inl, iph, ipl, x, R_, D_, DIN_, 0);

        for (int l = 0; l < L_; l++) {
            const int ml = m * L_ + l;

            rmsnorm_k<<<R_, 256>>>(x, rn_w + (size_t)ml * D_, h, z, Uh, Ul);
            transplit_k<<<dim3(S_ / 32, D_ / 32, B_), 256>>>(h, hTeh, hTel, hToh, hTol);
            conv_bf<<<dim3(D_ / 64, S_ / 128, B_ * K_), 256>>>(
                hTeh, hTel, hToh, hTol, P2h, P2l, Uh, Ul);
            wfill_k<<<wfill_blocks, 256>>>(
                sigma,
                M_p + (size_t)ml * K_ * D_ * D_,
                M_m + (size_t)ml * K_ * D_ * D_,
                M_u + (size_t)ml * KU_ * D_ * D_,
                Wh, Wl);
            // partials = U @ W^T (64x128 tiles, split-K=8 -> 1024 blocks)
            gemm_bf3<64, 128, 2, NSPLIT_>
                <<<dim3(D_ / 128, R_ / 64, NSPLIT_), 256, 61440>>>(
                Uh, Ul, Wh, Wl, part, R_, D_, UCOLS, 0);
            reduce8_k<<<ew_blocks, 256>>>(x, part, xh, xl);

            // MLP
            split_k<<<(2 * H_ * D_ + 255) / 256, 256>>>(
                fc1 + (size_t)ml * 2 * H_ * D_, f1h, f1l, 2 * H_ * D_);
            gemm_bf3<64, 128, 2, 1><<<dim3(2 * H_ / 128, R_ / 64), 256, 61440>>>(
                xh, xl, f1h, f1l, m1, R_, 2 * H_, D_, 0);
            silu_k<<<silu_blocks, 256>>>(m1, m2h, m2l);
            split_k<<<(D_ * H_ + 255) / 256, 256>>>(
                fc2 + (size_t)ml * D_ * H_, f2h, f2l, D_ * H_);
            // fc2: 64x64 tiles, split-K=4 -> 1024 blocks; reduce folds +z
            gemm_bf3<64, 64, 2, 4><<<dim3(D_ / 64, R_ / 64, 4), 256, 40960>>>(
                m2h, m2l, f2h, f2l, part, R_, D_, H_, 0);
            reduce4z_k<<<ew_blocks, 256>>>(x, part, z);
        }

        // preds += x @ out_proj[m]^T  (N=64)
        gemm_nt<<<dim3(DIN_ / 64, R_ / 64), 256>>>(
            x, out_w + (size_t)m * DIN_ * D_, out, R_, DIN_, D_, m);
    }
    (void)in_sizes; (void)n_in; (void)out_size;
}

// round 12
// speedup vs baseline: 3.0977x; 1.2077x over previous
#include <cuda_runtime.h>
#include <cuda_fp16.h>
#include <cstddef>

// ---------------- problem constants ----------------
#define B_    2
#define S_    1024
#define S2_   (S_ / 2)
#define DIN_  64
#define D_    512
#define K_    16
#define KU_   3
#define L_    2
#define M_    2
#define H_    2048
#define R_    (B_ * S_)                 // 2048 rows (b*S + t)
#define SPECC (2 * K_ * D_)             // 16384 spectral columns of U
#define UCOLS (SPECC + KU_ * D_)        // 17920 = spectral + AR columns
#define EPS_  1e-5f
#define NSPLIT_ 8
#define P2LEN 1280                      // stride-2 phi pair table (offset 192)

typedef unsigned short u16;
typedef unsigned int   u32;

// ---------------- scratch (static device globals; no allocation) ----------------
__device__ __align__(16) float g_x[R_ * D_];
__device__ __align__(16) float g_z[R_ * D_];
__device__ __align__(16) float g_h[R_ * D_];
__device__ __align__(16) float g_part[(size_t)NSPLIT_ * R_ * D_];
__device__ __align__(16) float g_m1[(size_t)R_ * 2 * H_];

__device__ __align__(16) u16 g_Uh[(size_t)R_ * UCOLS];
__device__ __align__(16) u16 g_Ul[(size_t)R_ * UCOLS];
__device__ __align__(16) u16 g_Wh[(size_t)D_ * UCOLS];
__device__ __align__(16) u16 g_Wl[(size_t)D_ * UCOLS];
__device__ __align__(16) u16 g_m2h[(size_t)R_ * H_];
__device__ __align__(16) u16 g_m2l[(size_t)R_ * H_];
__device__ __align__(16) u16 g_hTeh[B_ * D_ * S2_];
__device__ __align__(16) u16 g_hToh[B_ * D_ * S2_];
__device__ __align__(16) u16 g_xh[R_ * D_];
__device__ __align__(16) u16 g_xl[R_ * D_];
__device__ __align__(16) u16 g_inh[R_ * DIN_];
__device__ __align__(16) u16 g_inl[R_ * DIN_];
__device__ __align__(16) u16 g_iph[D_ * DIN_];
__device__ __align__(16) u16 g_ipl[D_ * DIN_];
__device__ __align__(16) u16 g_f1h[2 * H_ * D_];
__device__ __align__(16) u16 g_f2h[D_ * H_];
__device__ __align__(16) u32 g_P2h[K_ * P2LEN];
__device__ __align__(16) u32 g_P2l[K_ * P2LEN];

// ---------------- helpers (fp16 pair split) ----------------
__device__ __forceinline__ void split_bf(float a, u16& hi, u16& lo) {
    __half h = __float2half_rn(a);
    float r = a - __half2float(h);
    __half l = __float2half_rn(r);
    hi = reinterpret_cast<u16&>(h);
    lo = reinterpret_cast<u16&>(l);
}
__device__ __forceinline__ u16 f2h_bits(float a) {
    __half h = __float2half_rn(a);
    return reinterpret_cast<u16&>(h);
}

__device__ __forceinline__ void mma_f16(float c[4],
                                        u32 a0, u32 a1, u32 a2, u32 a3,
                                        u32 b0, u32 b1) {
    asm volatile(
        "mma.sync.aligned.m16n8k16.row.col.f32.f16.f16.f32 "
        "{%0,%1,%2,%3},{%4,%5,%6,%7},{%8,%9},{%0,%1,%2,%3};\n"
        : "+f"(c[0]), "+f"(c[1]), "+f"(c[2]), "+f"(c[3])
        : "r"(a0), "r"(a1), "r"(a2), "r"(a3), "r"(b0), "r"(b1));
}

__device__ __forceinline__ u32 smem_u32(const void* p) {
    u32 a;
    asm("{ .reg .u64 t; cvta.to.shared.u64 t, %1; cvt.u32.u64 %0, t; }" : "=r"(a) : "l"(p));
    return a;
}

__device__ __forceinline__ void ldsm4(u32& r0, u32& r1, u32& r2, u32& r3, u32 saddr) {
    asm volatile("ldmatrix.sync.aligned.m8n8.x4.shared.b16 {%0,%1,%2,%3}, [%4];"
                 : "=r"(r0), "=r"(r1), "=r"(r2), "=r"(r3) : "r"(saddr));
}

__device__ __forceinline__ void cp16(u32* smem_dst, const void* gsrc) {
    unsigned saddr = (unsigned)__cvta_generic_to_shared(smem_dst);
    asm volatile("cp.async.cg.shared.global [%0], [%1], 16;\n" :: "r"(saddr), "l"(gsrc));
}
#define CP_COMMIT() asm volatile("cp.async.commit_group;\n" ::: "memory")
#define CP_WAIT1()  asm volatile("cp.async.wait_group 1;\n" ::: "memory")

// ---------------- fp16 emulated NT GEMM, cp.async 2-stage + ldmatrix ----------------
// TERMS=3: ah*bh + al*bh + ah*bl.  TERMS=2: ah*bh + al*bh (Bl not loaded).
template<int BM, int BN, int WARPS_M, int TERMS, int NSPLIT>
__global__ __launch_bounds__(256) void gemm_bf3(
    const u16* __restrict__ Ah, const u16* __restrict__ Al,
    const u16* __restrict__ Bh, const u16* __restrict__ Bl,
    float* __restrict__ C, int M, int N, int K, int accum)
{
    constexpr int WARPS_N = 8 / WARPS_M;
    constexpr int WM = BM / WARPS_M;
    constexpr int WN = BN / WARPS_N;
    constexpr int MT = WM / 16;
    constexpr int NT = WN / 8;
    constexpr int AOFF  = 0;
    constexpr int ALOFF = BM * 20;
    constexpr int BOFF  = 2 * BM * 20;
    constexpr int BLOFF = 2 * BM * 20 + BN * 20;            // only if TERMS==3
    constexpr int STAGE = (2 * BM + (TERMS - 1) * BN) * 20; // u32 per stage
    extern __shared__ __align__(16) u32 dsm[];

    int kb = 0, ke = K;
    if (NSPLIT > 1) {
        const int z = blockIdx.z;
        const int steps = K / 32;
        kb = ((z * steps) / NSPLIT) * 32;
        ke = (((z + 1) * steps) / NSPLIT) * 32;
        C += (size_t)z * M * N;
        accum = 0;
    }

    const int bm = blockIdx.y * BM;
    const int bn = blockIdx.x * BN;
    const int tid  = threadIdx.x;
    const int lane = tid & 31;
    const int warp = tid >> 5;
    const int wm = (warp % WARPS_M) * WM;
    const int wn = (warp / WARPS_M) * WN;
    const int g  = lane >> 2;
    const int tg = lane & 3;

    const int lr = tid >> 2;
    const int c4 = (tid & 3) * 4;

    const u32 dsmAddr = smem_u32(dsm);
    const u32 rowA = (lane & 7) + ((lane >> 3) & 1) * 8;
    const u32 kbA  = ((lane >> 4) & 1) * 16;
    const u32 colB = (lane & 7) + ((lane >> 4) & 1) * 8;
    const u32 kbB  = ((lane >> 3) & 1) * 16;
    const u32 aoff = (u32)AOFF * 4 + (wm + rowA) * 80 + kbA;
    const u32 boff = (u32)BOFF * 4 + (wn + colB) * 80 + kbB;

    auto issue = [&](int k0, int s) {
        u32* base = dsm + s * STAGE;
#pragma unroll
        for (int r = 0; r < BM / 64; r++) {
            const int rrow = lr + 64 * r;
            const size_t go = (size_t)(bm + rrow) * K + k0 + c4 * 2;
            cp16(base + AOFF  + rrow * 20 + c4, &Ah[go]);
            cp16(base + ALOFF + rrow * 20 + c4, &Al[go]);
        }
#pragma unroll
        for (int r = 0; r < BN / 64; r++) {
            const int rrow = lr + 64 * r;
            const size_t go = (size_t)(bn + rrow) * K + k0 + c4 * 2;
            cp16(base + BOFF + rrow * 20 + c4, &Bh[go]);
            if (TERMS == 3)
                cp16(base + BLOFF + rrow * 20 + c4, &Bl[go]);
        }
    };

    float acc[MT][NT][4] = {};

    const int nIters = (ke - kb) / 32;
    issue(kb, 0); CP_COMMIT();

    for (int i = 0; i < nIters; i++) {
        if (i + 1 < nIters) issue(kb + (i + 1) * 32, (i + 1) & 1);
        CP_COMMIT();
        CP_WAIT1();
        __syncthreads();
        const u32 sb = dsmAddr + (u32)((i & 1) * STAGE * 4);

#pragma unroll
        for (int ks = 0; ks < 2; ks++) {
            const u32 kso = (u32)ks * 32;
            u32 ah[MT][4], al[MT][4];
#pragma unroll
            for (int mt = 0; mt < MT; mt++) {
                const u32 base_a = sb + aoff + (u32)mt * 1280 + kso;
                ldsm4(ah[mt][0], ah[mt][1], ah[mt][2], ah[mt][3], base_a);
                ldsm4(al[mt][0], al[mt][1], al[mt][2], al[mt][3], base_a + (u32)BM * 80);
            }
#pragma unroll
            for (int ntp = 0; ntp < NT / 2; ntp++) {
                u32 bh0, bh1, bh2, bh3;
                const u32 base_b = sb + boff + (u32)ntp * 1280 + kso;
                ldsm4(bh0, bh1, bh2, bh3, base_b);
                u32 bl0 = 0, bl1 = 0, bl2 = 0, bl3 = 0;
                if (TERMS == 3)
                    ldsm4(bl0, bl1, bl2, bl3, base_b + (u32)BN * 80);
#pragma unroll
                for (int mt = 0; mt < MT; mt++) {
                    mma_f16(acc[mt][2 * ntp],     ah[mt][0], ah[mt][1], ah[mt][2], ah[mt][3], bh0, bh1);
                    mma_f16(acc[mt][2 * ntp],     al[mt][0], al[mt][1], al[mt][2], al[mt][3], bh0, bh1);
                    mma_f16(acc[mt][2 * ntp + 1], ah[mt][0], ah[mt][1], ah[mt][2], ah[mt][3], bh2, bh3);
                    mma_f16(acc[mt][2 * ntp + 1], al[mt][0], al[mt][1], al[mt][2], al[mt][3], bh2, bh3);
                    if (TERMS == 3) {
                        mma_f16(acc[mt][2 * ntp],     ah[mt][0], ah[mt][1], ah[mt][2], ah[mt][3], bl0, bl1);
                        mma_f16(acc[mt][2 * ntp + 1], ah[mt][0], ah[mt][1], ah[mt][2], ah[mt][3], bl2, bl3);
                    }
                }
            }
        }
        __syncthreads();
    }

#pragma unroll
    for (int mt = 0; mt < MT; mt++) {
        const int r0 = bm + wm + mt * 16 + g;
        const int r1 = r0 + 8;
#pragma unroll
        for (int nt = 0; nt < NT; nt++) {
            const int col = bn + wn + nt * 8 + 2 * tg;
            float2* p0 = (float2*)&C[(size_t)r0 * N + col];
            float2* p1 = (float2*)&C[(size_t)r1 * N + col];
            float2 v0 = make_float2(acc[mt][nt][0], acc[mt][nt][1]);
            float2 v1 = make_float2(acc[mt][nt][2], acc[mt][nt][3]);
            if (accum) {
                float2 o0 = *p0, o1 = *p1;
                v0.x += o0.x; v0.y += o0.y; v1.x += o1.x; v1.y += o1.y;
            }
            *p0 = v0;
            *p1 = v1;
        }
    }
}

// ---------------- causal spectral conv, parity-split, 2-term fp16 ----------------
// E = sum even i, O = sum odd i; Up = E+O, Um = st*(E-O).
// Terms per parity: (Qh + Ql) x Xhi  (X low dropped: ~2^-12 relative).
__global__ __launch_bounds__(256) void conv_bf(
    const u16* __restrict__ hTeh, const u16* __restrict__ hToh,
    const u32* __restrict__ P2h, const u32* __restrict__ P2l,
    u16* __restrict__ Uh, u16* __restrict__ Ul)
{
    constexpr int CXE = 0;
    constexpr int CXO = 1280;
    constexpr int CQH = 2560;
    constexpr int CQL = 2760;
    constexpr int CSTAGE = 2960;   // u32; 11840 B/stage
    __shared__ __align__(16) u32 csm[2 * CSTAGE];

    const int d0 = blockIdx.x * 64;
    const int t0 = ((int)gridDim.y - 1 - (int)blockIdx.y) * 128;   // longest blocks first
    const int b  = blockIdx.z >> 4;
    const int k  = blockIdx.z & 15;
    const int tid  = threadIdx.x;
    const int lane = tid & 31;
    const int warp = tid >> 5;
    const int wm = (warp & 3) * 32;
    const int wn = (warp >> 2) * 32;
    const int g  = lane >> 2;
    const int tg = lane & 3;

    const int xr = tid >> 2;
    const int c4 = (tid & 3) * 4;

    const u32 csmAddr = smem_u32(csm);
    const u32 colB = (lane & 7) + ((lane >> 4) & 1) * 8;
    const u32 kbB  = ((lane >> 3) & 1) * 16;
    const u32 xoff = (wn + colB) * 80 + kbB;

    auto issue = [&](int ii, int s) {
        u32* base = csm + s * CSTAGE;
        const int j0 = ii * 32;
        const size_t go = (size_t)(b * D_ + d0 + xr) * S2_ + j0 + c4 * 2;
        cp16(base + CXE + xr * 20 + c4, &hTeh[go]);
        cp16(base + CXO + xr * 20 + c4, &hToh[go]);
        const int tb = k * P2LEN + t0 - 2 * j0 + 124;
        if (tid < 50)
            cp16(base + CQH + tid * 4, &P2h[tb + tid * 4]);
        else if (tid >= 64 && tid < 114)
            cp16(base + CQL + (tid - 64) * 4, &P2l[tb + (tid - 64) * 4]);
    };

    float accE[2][4][4] = {};
    float accO[2][4][4] = {};

    const int nIters = (t0 + 128) / 64;
    issue(0, 0); CP_COMMIT();

    for (int i = 0; i < nIters; i++) {
        if (i + 1 < nIters) issue(i + 1, (i + 1) & 1);
        CP_COMMIT();
        CP_WAIT1();
        __syncthreads();
        const int s = i & 1;
        const u32 sb = csmAddr + (u32)(s * CSTAGE * 4);
        const u32* base = csm + s * CSTAGE;
        const u32* sQh = base + CQH;
        const u32* sQl = base + CQL;

#pragma unroll
        for (int ks = 0; ks < 2; ks++) {
            u32 aEh[2][4], aEl[2][4], aOh[2][4], aOl[2][4];
#pragma unroll
            for (int mt = 0; mt < 2; mt++) {
                const int n = wm + mt * 16 + g - 32 * ks - 4 * tg + 68;
                aEh[mt][0] = sQh[n];      aEh[mt][1] = sQh[n + 8];
                aEh[mt][2] = sQh[n - 16]; aEh[mt][3] = sQh[n - 8];
                aEl[mt][0] = sQl[n];      aEl[mt][1] = sQl[n + 8];
                aEl[mt][2] = sQl[n - 16]; aEl[mt][3] = sQl[n - 8];
                aOh[mt][0] = sQh[n - 1];      aOh[mt][1] = sQh[n + 7];
                aOh[mt][2] = sQh[n - 17];     aOh[mt][3] = sQh[n - 9];
                aOl[mt][0] = sQl[n - 1];      aOl[mt][1] = sQl[n + 7];
                aOl[mt][2] = sQl[n - 17];     aOl[mt][3] = sQl[n - 9];
            }
#pragma unroll
            for (int ntp = 0; ntp < 2; ntp++) {
                u32 e0r, e1r, e2r, e3r, o0r, o1r, o2r, o3r;
                const u32 base_x = sb + xoff + (u32)ntp * 1280 + (u32)ks * 32;
                ldsm4(e0r, e1r, e2r, e3r, base_x);
                ldsm4(o0r, o1r, o2r, o3r, base_x + 5120u);   // CXO = 1280 u32
#pragma unroll
                for (int mt = 0; mt < 2; mt++) {
                    float* e0 = accE[mt][2 * ntp];
                    float* e1 = accE[mt][2 * ntp + 1];
                    float* o0 = accO[mt][2 * ntp];
                    float* o1 = accO[mt][2 * ntp + 1];
                    mma_f16(e0, aEh[mt][0], aEh[mt][1], aEh[mt][2], aEh[mt][3], e0r, e1r);
                    mma_f16(e0, aEl[mt][0], aEl[mt][1], aEl[mt][2], aEl[mt][3], e0r, e1r);
                    mma_f16(e1, aEh[mt][0], aEh[mt][1], aEh[mt][2], aEh[mt][3], e2r, e3r);
                    mma_f16(e1, aEl[mt][0], aEl[mt][1], aEl[mt][2], aEl[mt][3], e2r, e3r);
                    mma_f16(o0, aOh[mt][0], aOh[mt][1], aOh[mt][2], aOh[mt][3], o0r, o1r);
                    mma_f16(o0, aOl[mt][0], aOl[mt][1], aOl[mt][2], aOl[mt][3], o0r, o1r);
                    mma_f16(o1, aOh[mt][0], aOh[mt][1], aOh[mt][2], aOh[mt][3], o2r, o3r);
                    mma_f16(o1, aOl[mt][0], aOl[mt][1], aOl[mt][2], aOl[mt][3], o2r, o3r);
                }
            }
        }
        __syncthreads();
    }

#pragma unroll
    for (int mt = 0; mt < 2; mt++) {
#pragma unroll
        for (int half = 0; half < 2; half++) {
            const int t = t0 + wm + mt * 16 + g + half * 8;
            const float st = (t & 1) ? -1.f : 1.f;
            const size_t rowo = (size_t)(b * S_ + t) * UCOLS;
#pragma unroll
            for (int nt = 0; nt < 4; nt++) {
                const int d = d0 + wn + nt * 8 + 2 * tg;
                const float e0 = accE[mt][nt][half * 2 + 0];
                const float e1 = accE[mt][nt][half * 2 + 1];
                const float o0 = accO[mt][nt][half * 2 + 0];
                const float o1 = accO[mt][nt][half * 2 + 1];
                const float up0 = e0 + o0, up1 = e1 + o1;
                const float um0 = st * (e0 - o0), um1 = st * (e1 - o1);
                u16 h0, l0, h1, l1;
                split_bf(up0, h0, l0); split_bf(up1, h1, l1);
                *(ushort2*)&Uh[rowo + (size_t)k * D_ + d] = make_ushort2(h0, h1);
                *(ushort2*)&Ul[rowo + (size_t)k * D_ + d] = make_ushort2(l0, l1);
                split_bf(um0, h0, l0); split_bf(um1, h1, l1);
                *(ushort2*)&Uh[rowo + (size_t)(K_ + k) * D_ + d] = make_ushort2(h0, h1);
                *(ushort2*)&Ul[rowo + (size_t)(K_ + k) * D_ + d] = make_ushort2(l0, l1);
            }
        }
    }
}

// ---------------- fp32 NT GEMM (tiny out_proj: N=64) ----------------
__global__ __launch_bounds__(256) void gemm_nt(
    const float* __restrict__ A, const float* __restrict__ B, float* __restrict__ C,
    int M, int N, int K, int accum)
{
    __shared__ float As[16][65];
    __shared__ float Bs[16][65];
    const int bm = blockIdx.y * 64;
    const int bn = blockIdx.x * 64;
    const int tid = threadIdx.x;
    const int tx = tid & 15;
    const int ty = tid >> 4;
    const int lr = tid >> 2;
    const int lk = (tid & 3) << 2;

    const float* Ap = A + (size_t)(bm + lr) * K + lk;
    const float* Bp = B + (size_t)(bn + lr) * K + lk;

    float acc[4][4] = {};

    for (int k0 = 0; k0 < K; k0 += 16) {
        float4 av = *(const float4*)(Ap + k0);
        float4 bv = *(const float4*)(Bp + k0);
        __syncthreads();
        As[lk + 0][lr] = av.x; As[lk + 1][lr] = av.y;
        As[lk + 2][lr] = av.z; As[lk + 3][lr] = av.w;
        Bs[lk + 0][lr] = bv.x; Bs[lk + 1][lr] = bv.y;
        Bs[lk + 2][lr] = bv.z; Bs[lk + 3][lr] = bv.w;
        __syncthreads();
#pragma unroll
        for (int kk = 0; kk < 16; kk++) {
            float a[4], b[4];
#pragma unroll
            for (int i = 0; i < 4; i++) a[i] = As[kk][ty * 4 + i];
#pragma unroll
            for (int j = 0; j < 4; j++) b[j] = Bs[kk][tx * 4 + j];
#pragma unroll
            for (int i = 0; i < 4; i++)
#pragma unroll
                for (int j = 0; j < 4; j++)
                    acc[i][j] += a[i] * b[j];
        }
    }

#pragma unroll
    for (int i = 0; i < 4; i++) {
        const int r = bm + ty * 4 + i;
#pragma unroll
        for (int j = 0; j < 4; j++) {
            const int c = bn + tx * 4 + j;
            const size_t idx = (size_t)r * N + c;
            C[idx] = accum ? (C[idx] + acc[i][j]) : acc[i][j];
        }
    }
}

// ---------------- rmsnorm + z copy + AR column scatter (fp16 pairs) ----------------
__global__ __launch_bounds__(256) void rmsnorm_k(
    const float* __restrict__ x, const float* __restrict__ w,
    float* __restrict__ h, float* __restrict__ z,
    u16* __restrict__ Uh, u16* __restrict__ Ul)
{
    __shared__ float red[256];
    const int row = blockIdx.x;
    const int t = row & (S_ - 1);
    const int tid = threadIdx.x;

    const float v0 = x[(size_t)row * D_ + tid];
    const float v1 = x[(size_t)row * D_ + 256 + tid];
    z[(size_t)row * D_ + tid] = v0;
    z[(size_t)row * D_ + 256 + tid] = v1;
    red[tid] = v0 * v0 + v1 * v1;
    __syncthreads();
    for (int s = 128; s > 0; s >>= 1) {
        if (tid < s) red[tid] += red[tid + s];
        __syncthreads();
    }
    const float scale = rsqrtf(red[0] * (1.f / D_) + EPS_);
    const float h0 = v0 * scale * w[tid];
    const float h1 = v1 * scale * w[tid + 256];
    h[(size_t)row * D_ + tid] = h0;
    h[(size_t)row * D_ + 256 + tid] = h1;

    u16 h0h, h0l, h1h, h1l;
    split_bf(h0, h0h, h0l); split_bf(h1, h1h, h1l);

#pragma unroll
    for (int j = 0; j < KU_; j++) {
        if (t + j < S_) {
            const size_t base = (size_t)(row + j) * UCOLS + SPECC + j * D_;
            Uh[base + tid] = h0h; Ul[base + tid] = h0l;
            Uh[base + 256 + tid] = h1h; Ul[base + 256 + tid] = h1l;
        }
        if (t < j) {
            const size_t base = (size_t)row * UCOLS + SPECC + j * D_;
            Uh[base + tid] = 0; Ul[base + tid] = 0;
            Uh[base + 256 + tid] = 0; Ul[base + 256 + tid] = 0;
        }
    }
}

// ---------------- transpose + parity split h -> hTe/hTo (hi only) ----------------
__global__ __launch_bounds__(256) void transplit_k(
    const float* __restrict__ h,
    u16* __restrict__ hTeh, u16* __restrict__ hToh)
{
    __shared__ float tile[32][33];
    const int i0 = blockIdx.x * 32;
    const int d0 = blockIdx.y * 32;
    const int b  = blockIdx.z;
    const int tx = threadIdx.x & 31;
    const int ty = threadIdx.x >> 5;
#pragma unroll
    for (int r = 0; r < 4; r++)
        tile[ty + 8 * r][tx] = h[(size_t)(b * S_ + i0 + ty + 8 * r) * D_ + d0 + tx];
    __syncthreads();
#pragma unroll
    for (int r = 0; r < 4; r++) {
        const float v = tile[tx][ty + 8 * r];
        const u16 hv = f2h_bits(v);
        const size_t o = (size_t)(b * D_ + d0 + ty + 8 * r) * S2_ + (i0 >> 1) + (tx >> 1);
        if (tx & 1) hToh[o] = hv;
        else        hTeh[o] = hv;
    }
}

// ---------------- fused weight fill (fp16 pairs) ----------------
__global__ __launch_bounds__(256) void wfill_k(
    const float* __restrict__ sigma, const float* __restrict__ mp,
    const float* __restrict__ mm, const float* __restrict__ mu,
    u16* __restrict__ Wh, u16* __restrict__ Wl)
{
    const size_t idx = (size_t)blockIdx.x * 256 + threadIdx.x;
    if (idx >= (size_t)D_ * UCOLS) return;
    const int o = (int)(idx / UCOLS);
    const int col = (int)(idx % UCOLS);
    float v;
    if (col < K_ * D_) {
        const int k = col / D_, d = col % D_;
        v = sqrtf(sqrtf(sigma[k])) * mp[((size_t)k * D_ + d) * D_ + o];
    } else if (col < SPECC) {
        const int c = col - K_ * D_;
        const int k = c / D_, d = c % D_;
        v = sqrtf(sqrtf(sigma[k])) * mm[((size_t)k * D_ + d) * D_ + o];
    } else {
        const int c = col - SPECC;
        const int j = c / D_, d = c % D_;
        v = mu[((size_t)j * D_ + d) * D_ + o];
    }
    u16 hi, lo; split_bf(v, hi, lo);
    Wh[idx] = hi; Wl[idx] = lo;
}

// ---------------- splits ----------------
__global__ __launch_bounds__(256) void split_k(
    const float* __restrict__ src, u16* __restrict__ hi, u16* __restrict__ lo, int n)
{
    const int i = blockIdx.x * 256 + threadIdx.x;
    if (i < n) { u16 h, l; split_bf(src[i], h, l); hi[i] = h; lo[i] = l; }
}
__global__ __launch_bounds__(256) void split1_k(
    const float* __restrict__ src, u16* __restrict__ hi, int n)
{
    const int i = blockIdx.x * 256 + threadIdx.x;
    if (i < n) hi[i] = f2h_bits(src[i]);
}

// ---------------- stride-2 phi pair table (fp16 pairs) ----------------
__global__ __launch_bounds__(256) void phipack_k(
    const float* __restrict__ phi, u32* __restrict__ P2h, u32* __restrict__ P2l)
{
    const int i = blockIdx.x * 256 + threadIdx.x;
    if (i >= K_ * P2LEN) return;
    const int k = i / P2LEN, pp = i % P2LEN;
    const int p = pp - 192;
    u16 lh = 0, ll = 0, hh = 0, hl = 0;
    if (p >= 0 && p < S_)         split_bf(phi[p * K_ + k], lh, ll);
    if (p - 2 >= 0 && p - 2 < S_) split_bf(phi[(p - 2) * K_ + k], hh, hl);
    P2h[i] = (u32)lh | ((u32)hh << 16);
    P2l[i] = (u32)ll | ((u32)hl << 16);
}

// ---------------- elementwise ----------------
__global__ __launch_bounds__(256) void silu_k(
    const float* __restrict__ m1, u16* __restrict__ m2h, u16* __restrict__ m2l)
{
    const int idx = blockIdx.x * 256 + threadIdx.x;
    const int r = idx >> 11;
    const int j = idx & (H_ - 1);
    const float y = m1[(size_t)r * (2 * H_) + j];
    const float gg = m1[(size_t)r * (2 * H_) + H_ + j];
    const float v = y * gg / (1.f + expf(-gg));
    u16 h, l; split_bf(v, h, l);
    m2h[idx] = h; m2l[idx] = l;
}

// x += sum of 8 partials; emit fp16 split of new x
__global__ __launch_bounds__(256) void reduce8_k(
    float* __restrict__ x, const float* __restrict__ p,
    u16* __restrict__ xh, u16* __restrict__ xl)
{
    const int i = blockIdx.x * 256 + threadIdx.x;
    const size_t MN4 = (size_t)R_ * D_ / 4;
    float4 a = ((const float4*)x)[i];
    float sx = 0.f, sy = 0.f, sz = 0.f, sw = 0.f;
#pragma unroll
    for (int j = 0; j < 8; j++) {
        float4 bj = ((const float4*)p)[i + j * MN4];
        sx += bj.x; sy += bj.y; sz += bj.z; sw += bj.w;
    }
    a.x += sx; a.y += sy; a.z += sz; a.w += sw;
    ((float4*)x)[i] = a;
    ushort4 vh, vl;
    split_bf(a.x, vh.x, vl.x); split_bf(a.y, vh.y, vl.y);
    split_bf(a.z, vh.z, vl.z); split_bf(a.w, vh.w, vl.w);
    ((ushort4*)xh)[i] = vh;
    ((ushort4*)xl)[i] = vl;
}

// x += sum of 4 partials + z   (fc2 epilogue + layer residual)
__global__ __launch_bounds__(256) void reduce4z_k(
    float* __restrict__ x, const float* __restrict__ p, const float* __restrict__ z)
{
    const int i = blockIdx.x * 256 + threadIdx.x;
    const size_t MN4 = (size_t)R_ * D_ / 4;
    float4 a = ((const float4*)x)[i];
    float4 b0 = ((const float4*)p)[i];
    float4 b1 = ((const float4*)p)[i + MN4];
    float4 b2 = ((const float4*)p)[i + 2 * MN4];
    float4 b3 = ((const float4*)p)[i + 3 * MN4];
    float4 zz = ((const float4*)z)[i];
    a.x += (b0.x + b1.x) + (b2.x + b3.x) + zz.x;
    a.y += (b0.y + b1.y) + (b2.y + b3.y) + zz.y;
    a.z += (b0.z + b1.z) + (b2.z + b3.z) + zz.z;
    a.w += (b0.w + b1.w) + (b2.w + b3.w) + zz.w;
    ((float4*)x)[i] = a;
}

// ---------------- launch ----------------
extern "C" void kernel_launch(void* const* d_in, const int* in_sizes, int n_in,
                              void* d_out, int out_size)
{
    const float* inputs  = (const float*)d_in[0];
    const float* sigma   = (const float*)d_in[1];
    const float* phi     = (const float*)d_in[2];
    const float* in_proj = (const float*)d_in[3];
    const float* rn_w    = (const float*)d_in[4];
    const float* M_u     = (const float*)d_in[5];
    const float* M_p     = (const float*)d_in[6];
    const float* M_m     = (const float*)d_in[7];
    const float* fc1     = (const float*)d_in[8];
    const float* fc2     = (const float*)d_in[9];
    const float* out_w   = (const float*)d_in[10];
    float* out = (float*)d_out;

    float *x, *z, *h, *part, *m1;
    u16 *Uh, *Ul, *Wh, *Wl, *m2h, *m2l, *xh, *xl;
    u16 *hTeh, *hToh;
    u16 *inh, *inl, *iph, *ipl, *f1h, *f2h;
    u32 *P2h, *P2l;
    cudaGetSymbolAddress((void**)&x,   g_x);
    cudaGetSymbolAddress((void**)&z,   g_z);
    cudaGetSymbolAddress((void**)&h,   g_h);
    cudaGetSymbolAddress((void**)&part,g_part);
    cudaGetSymbolAddress((void**)&m1,  g_m1);
    cudaGetSymbolAddress((void**)&Uh,  g_Uh);
    cudaGetSymbolAddress((void**)&Ul,  g_Ul);
    cudaGetSymbolAddress((void**)&Wh,  g_Wh);
    cudaGetSymbolAddress((void**)&Wl,  g_Wl);
    cudaGetSymbolAddress((void**)&m2h, g_m2h);
    cudaGetSymbolAddress((void**)&m2l, g_m2l);
    cudaGetSymbolAddress((void**)&hTeh, g_hTeh);
    cudaGetSymbolAddress((void**)&hToh, g_hToh);
    cudaGetSymbolAddress((void**)&xh,  g_xh);
    cudaGetSymbolAddress((void**)&xl,  g_xl);
    cudaGetSymbolAddress((void**)&inh, g_inh);
    cudaGetSymbolAddress((void**)&inl, g_inl);
    cudaGetSymbolAddress((void**)&iph, g_iph);
    cudaGetSymbolAddress((void**)&ipl, g_ipl);
    cudaGetSymbolAddress((void**)&f1h, g_f1h);
    cudaGetSymbolAddress((void**)&f2h, g_f2h);
    cudaGetSymbolAddress((void**)&P2h, g_P2h);
    cudaGetSymbolAddress((void**)&P2l, g_P2l);

    // contraction stage (TERMS=3, 64x128) = (128+256)*20*4*2 = 61440 B > 48K default
    cudaFuncSetAttribute(gemm_bf3<64, 128, 2, 3, NSPLIT_>,
                         cudaFuncAttributeMaxDynamicSharedMemorySize, 61440);

    const int ew_blocks = (R_ * D_ / 4) / 256;
    const int wfill_blocks = (int)(((size_t)D_ * UCOLS + 255) / 256);
    const int silu_blocks = (R_ * H_) / 256;

    phipack_k<<<(K_ * P2LEN + 255) / 256, 256>>>(phi, P2h, P2l);
    split_k<<<(R_ * DIN_ + 255) / 256, 256>>>(inputs, inh, inl, R_ * DIN_);

    for (int m = 0; m < M_; m++) {
        // x = inputs @ in_proj[m]^T   (2048 x 512, K=64) — 3-term (signal path)
        split_k<<<(D_ * DIN_ + 255) / 256, 256>>>(
            in_proj + (size_t)m * D_ * DIN_, iph, ipl, D_ * DIN_);
        gemm_bf3<64, 64, 2, 3, 1><<<dim3(D_ / 64, R_ / 64), 256, 40960>>>(
            inh, inl, iph, ipl, x, R_, D_, DIN_, 0);

        for (int l = 0; l < L_; l++) {
            const int ml = m * L_ + l;

            rmsnorm_k<<<R_, 256>>>(x, rn_w + (size_t)ml * D_, h, z, Uh, Ul);
            transplit_k<<<dim3(S_ / 32, D_ / 32, B_), 256>>>(h, hTeh, hToh);
            conv_bf<<<dim3(D_ / 64, S_ / 128, B_ * K_), 256>>>(
                hTeh, hToh, P2h, P2l, Uh, Ul);
            wfill_k<<<wfill_blocks, 256>>>(
                sigma,
                M_p + (size_t)ml * K_ * D_ * D_,
                M_m + (size_t)ml * K_ * D_ * D_,
                M_u + (size_t)ml * KU_ * D_ * D_,
                Wh, Wl);
            // partials = U @ W^T (3-term, 64x128 tiles, split-K=8 -> 1024 blocks)
            gemm_bf3<64, 128, 2, 3, NSPLIT_>
                <<<dim3(D_ / 128, R_ / 64, NSPLIT_), 256, 61440>>>(
                Uh, Ul, Wh, Wl, part, R_, D_, UCOLS, 0);
            reduce8_k<<<ew_blocks, 256>>>(x, part, xh, xl);

            // MLP (2-term: weight-lo dropped)
            split1_k<<<(2 * H_ * D_ + 255) / 256, 256>>>(
                fc1 + (size_t)ml * 2 * H_ * D_, f1h, 2 * H_ * D_);
            gemm_bf3<64, 128, 2, 2, 1><<<dim3(2 * H_ / 128, R_ / 64), 256, 40960>>>(
                xh, xl, f1h, (const u16*)0, m1, R_, 2 * H_, D_, 0);
            silu_k<<<silu_blocks, 256>>>(m1, m2h, m2l);
            split1_k<<<(D_ * H_ + 255) / 256, 256>>>(
                fc2 + (size_t)ml * D_ * H_, f2h, D_ * H_);
            // fc2: 2-term, 64x64 tiles, split-K=4 -> 1024 blocks; reduce folds +z
            gemm_bf3<64, 64, 2, 2, 4><<<dim3(D_ / 64, R_ / 64, 4), 256, 30720>>>(
                m2h, m2l, f2h, (const u16*)0, part, R_, D_, H_, 0);
            reduce4z_k<<<ew_blocks, 256>>>(x, part, z);
        }

        // preds += x @ out_proj[m]^T  (N=64)
        gemm_nt<<<dim3(DIN_ / 64, R_ / 64), 256>>>(
            x, out_w + (size_t)m * DIN_ * D_, out, R_, DIN_, D_, m);
    }
    (void)in_sizes; (void)n_in; (void)out_size;
}

// round 15
// speedup vs baseline: 3.1051x; 1.0024x over previous
#include <cuda_runtime.h>
#include <cuda_fp16.h>
#include <cstddef>

// ---------------- problem constants ----------------
#define B_    2
#define S_    1024
#define S2_   (S_ / 2)
#define DIN_  64
#define D_    512
#define K_    16
#define KU_   3
#define L_    2
#define M_    2
#define H_    2048
#define R_    (B_ * S_)                 // 2048 rows (b*S + t)
#define SPECC (2 * K_ * D_)             // 16384 spectral columns of U
#define UCOLS (SPECC + KU_ * D_)        // 17920 = spectral + AR columns
#define EPS_  1e-5f
#define NSPLIT_ 8
#define P2LEN 1280                      // stride-2 phi pair table (offset 192)

typedef unsigned short u16;
typedef unsigned int   u32;

// ---------------- scratch (static device globals; no allocation) ----------------
__device__ __align__(16) float g_x[R_ * D_];
__device__ __align__(16) float g_z[R_ * D_];
__device__ __align__(16) float g_h[R_ * D_];
__device__ __align__(16) float g_part[(size_t)NSPLIT_ * R_ * D_];

__device__ __align__(16) u16 g_Uh[(size_t)R_ * UCOLS];
__device__ __align__(16) u16 g_Ul[(size_t)R_ * UCOLS];
__device__ __align__(16) u16 g_Wh[(size_t)D_ * UCOLS];
__device__ __align__(16) u16 g_Wl[(size_t)D_ * UCOLS];
__device__ __align__(16) u16 g_m2h[(size_t)R_ * H_];
__device__ __align__(16) u16 g_m2l[(size_t)R_ * H_];
__device__ __align__(16) u16 g_hTeh[B_ * D_ * S2_];
__device__ __align__(16) u16 g_hToh[B_ * D_ * S2_];
__device__ __align__(16) u16 g_xh[R_ * D_];
__device__ __align__(16) u16 g_xl[R_ * D_];
__device__ __align__(16) u16 g_inh[R_ * DIN_];
__device__ __align__(16) u16 g_inl[R_ * DIN_];
__device__ __align__(16) u16 g_iph[D_ * DIN_];
__device__ __align__(16) u16 g_ipl[D_ * DIN_];
__device__ __align__(16) u16 g_f1h[2 * H_ * D_];
__device__ __align__(16) u16 g_f2h[D_ * H_];
__device__ __align__(16) u32 g_P2h[K_ * P2LEN];
__device__ __align__(16) u32 g_P2l[K_ * P2LEN];

// ---------------- helpers (fp16 pair split) ----------------
__device__ __forceinline__ void split_bf(float a, u16& hi, u16& lo) {
    __half h = __float2half_rn(a);
    float r = a - __half2float(h);
    __half l = __float2half_rn(r);
    hi = reinterpret_cast<u16&>(h);
    lo = reinterpret_cast<u16&>(l);
}
__device__ __forceinline__ u16 f2h_bits(float a) {
    __half h = __float2half_rn(a);
    return reinterpret_cast<u16&>(h);
}

__device__ __forceinline__ void mma_f16(float c[4],
                                        u32 a0, u32 a1, u32 a2, u32 a3,
                                        u32 b0, u32 b1) {
    asm volatile(
        "mma.sync.aligned.m16n8k16.row.col.f32.f16.f16.f32 "
        "{%0,%1,%2,%3},{%4,%5,%6,%7},{%8,%9},{%0,%1,%2,%3};\n"
        : "+f"(c[0]), "+f"(c[1]), "+f"(c[2]), "+f"(c[3])
        : "r"(a0), "r"(a1), "r"(a2), "r"(a3), "r"(b0), "r"(b1));
}

__device__ __forceinline__ u32 smem_u32(const void* p) {
    u32 a;
    asm("{ .reg .u64 t; cvta.to.shared.u64 t, %1; cvt.u32.u64 %0, t; }" : "=r"(a) : "l"(p));
    return a;
}

__device__ __forceinline__ void ldsm4(u32& r0, u32& r1, u32& r2, u32& r3, u32 saddr) {
    asm volatile("ldmatrix.sync.aligned.m8n8.x4.shared.b16 {%0,%1,%2,%3}, [%4];"
                 : "=r"(r0), "=r"(r1), "=r"(r2), "=r"(r3) : "r"(saddr));
}

__device__ __forceinline__ void cp16(u32* smem_dst, const void* gsrc) {
    unsigned saddr = (unsigned)__cvta_generic_to_shared(smem_dst);
    asm volatile("cp.async.cg.shared.global [%0], [%1], 16;\n" :: "r"(saddr), "l"(gsrc));
}
#define CP_COMMIT() asm volatile("cp.async.commit_group;\n" ::: "memory")
#define CP_WAIT1()  asm volatile("cp.async.wait_group 1;\n" ::: "memory")

// ---------------- fp16 emulated NT GEMM, cp.async 2-stage + ldmatrix ----------------
// TERMS=3: ah*bh + al*bh + ah*bl.  TERMS=2: ah*bh + al*bh (Bl not loaded).
// EPI=0: write fp32 C (accum opt).  EPI=1: columns are interleaved (y, gate) pairs;
//        write split fp16 of y*silu(gate) to Oh/Ol with N/2 columns.
template<int BM, int BN, int WARPS_M, int TERMS, int NSPLIT, int EPI>
__global__ __launch_bounds__(256) void gemm_bf3(
    const u16* __restrict__ Ah, const u16* __restrict__ Al,
    const u16* __restrict__ Bh, const u16* __restrict__ Bl,
    float* __restrict__ C, u16* __restrict__ Oh, u16* __restrict__ Ol,
    int M, int N, int K, int accum)
{
    constexpr int WARPS_N = 8 / WARPS_M;
    constexpr int WM = BM / WARPS_M;
    constexpr int WN = BN / WARPS_N;
    constexpr int MT = WM / 16;
    constexpr int NT = WN / 8;
    constexpr int AOFF  = 0;
    constexpr int ALOFF = BM * 20;
    constexpr int BOFF  = 2 * BM * 20;
    constexpr int BLOFF = 2 * BM * 20 + BN * 20;            // only if TERMS==3
    constexpr int STAGE = (2 * BM + (TERMS - 1) * BN) * 20; // u32 per stage
    extern __shared__ __align__(16) u32 dsm[];

    int kb = 0, ke = K;
    if (NSPLIT > 1) {
        const int z = blockIdx.z;
        const int steps = K / 32;
        kb = ((z * steps) / NSPLIT) * 32;
        ke = (((z + 1) * steps) / NSPLIT) * 32;
        C += (size_t)z * M * N;
        accum = 0;
    }

    const int bm = blockIdx.y * BM;
    const int bn = blockIdx.x * BN;
    const int tid  = threadIdx.x;
    const int lane = tid & 31;
    const int warp = tid >> 5;
    const int wm = (warp % WARPS_M) * WM;
    const int wn = (warp / WARPS_M) * WN;
    const int g  = lane >> 2;
    const int tg = lane & 3;

    const int lr = tid >> 2;
    const int c4 = (tid & 3) * 4;

    const u32 dsmAddr = smem_u32(dsm);
    const u32 rowA = (lane & 7) + ((lane >> 3) & 1) * 8;
    const u32 kbA  = ((lane >> 4) & 1) * 16;
    const u32 colB = (lane & 7) + ((lane >> 4) & 1) * 8;
    const u32 kbB  = ((lane >> 3) & 1) * 16;
    const u32 aoff = (u32)AOFF * 4 + (wm + rowA) * 80 + kbA;
    const u32 boff = (u32)BOFF * 4 + (wn + colB) * 80 + kbB;

    auto issue = [&](int k0, int s) {
        u32* base = dsm + s * STAGE;
#pragma unroll
        for (int r = 0; r < BM / 64; r++) {
            const int rrow = lr + 64 * r;
            const size_t go = (size_t)(bm + rrow) * K + k0 + c4 * 2;
            cp16(base + AOFF  + rrow * 20 + c4, &Ah[go]);
            cp16(base + ALOFF + rrow * 20 + c4, &Al[go]);
        }
#pragma unroll
        for (int r = 0; r < BN / 64; r++) {
            const int rrow = lr + 64 * r;
            const size_t go = (size_t)(bn + rrow) * K + k0 + c4 * 2;
            cp16(base + BOFF + rrow * 20 + c4, &Bh[go]);
            if (TERMS == 3)
                cp16(base + BLOFF + rrow * 20 + c4, &Bl[go]);
        }
    };

    float acc[MT][NT][4] = {};

    const int nIters = (ke - kb) / 32;
    issue(kb, 0); CP_COMMIT();

    for (int i = 0; i < nIters; i++) {
        if (i + 1 < nIters) issue(kb + (i + 1) * 32, (i + 1) & 1);
        CP_COMMIT();
        CP_WAIT1();
        __syncthreads();
        const u32 sb = dsmAddr + (u32)((i & 1) * STAGE * 4);

#pragma unroll
        for (int ks = 0; ks < 2; ks++) {
            const u32 kso = (u32)ks * 32;
            u32 ah[MT][4], al[MT][4];
#pragma unroll
            for (int mt = 0; mt < MT; mt++) {
                const u32 base_a = sb + aoff + (u32)mt * 1280 + kso;
                ldsm4(ah[mt][0], ah[mt][1], ah[mt][2], ah[mt][3], base_a);
                ldsm4(al[mt][0], al[mt][1], al[mt][2], al[mt][3], base_a + (u32)BM * 80);
            }
#pragma unroll
            for (int ntp = 0; ntp < NT / 2; ntp++) {
                u32 bh0, bh1, bh2, bh3;
                const u32 base_b = sb + boff + (u32)ntp * 1280 + kso;
                ldsm4(bh0, bh1, bh2, bh3, base_b);
                u32 bl0 = 0, bl1 = 0, bl2 = 0, bl3 = 0;
                if (TERMS == 3)
                    ldsm4(bl0, bl1, bl2, bl3, base_b + (u32)BN * 80);
#pragma unroll
                for (int mt = 0; mt < MT; mt++) {
                    mma_f16(acc[mt][2 * ntp],     ah[mt][0], ah[mt][1], ah[mt][2], ah[mt][3], bh0, bh1);
                    mma_f16(acc[mt][2 * ntp],     al[mt][0], al[mt][1], al[mt][2], al[mt][3], bh0, bh1);
                    mma_f16(acc[mt][2 * ntp + 1], ah[mt][0], ah[mt][1], ah[mt][2], ah[mt][3], bh2, bh3);
                    mma_f16(acc[mt][2 * ntp + 1], al[mt][0], al[mt][1], al[mt][2], al[mt][3], bh2, bh3);
                    if (TERMS == 3) {
                        mma_f16(acc[mt][2 * ntp],     ah[mt][0], ah[mt][1], ah[mt][2], ah[mt][3], bl0, bl1);
                        mma_f16(acc[mt][2 * ntp + 1], ah[mt][0], ah[mt][1], ah[mt][2], ah[mt][3], bl2, bl3);
                    }
                }
            }
        }
        __syncthreads();
    }

    if (EPI == 1) {
        // columns come in (y, gate) pairs; emit split fp16 of y*silu(gate)
        const int N2 = N >> 1;
#pragma unroll
        for (int mt = 0; mt < MT; mt++) {
            const int r0 = bm + wm + mt * 16 + g;
            const int r1 = r0 + 8;
#pragma unroll
            for (int nt = 0; nt < NT; nt++) {
                const int c2 = (bn + wn + nt * 8 + 2 * tg) >> 1;
                const float y0 = acc[mt][nt][0], g0 = acc[mt][nt][1];
                const float y1 = acc[mt][nt][2], g1 = acc[mt][nt][3];
                const float v0 = y0 * g0 / (1.f + expf(-g0));
                const float v1 = y1 * g1 / (1.f + expf(-g1));
                u16 h, l;
                split_bf(v0, h, l);
                Oh[(size_t)r0 * N2 + c2] = h; Ol[(size_t)r0 * N2 + c2] = l;
                split_bf(v1, h, l);
                Oh[(size_t)r1 * N2 + c2] = h; Ol[(size_t)r1 * N2 + c2] = l;
            }
        }
        return;
    }

#pragma unroll
    for (int mt = 0; mt < MT; mt++) {
        const int r0 = bm + wm + mt * 16 + g;
        const int r1 = r0 + 8;
#pragma unroll
        for (int nt = 0; nt < NT; nt++) {
            const int col = bn + wn + nt * 8 + 2 * tg;
            float2* p0 = (float2*)&C[(size_t)r0 * N + col];
            float2* p1 = (float2*)&C[(size_t)r1 * N + col];
            float2 v0 = make_float2(acc[mt][nt][0], acc[mt][nt][1]);
            float2 v1 = make_float2(acc[mt][nt][2], acc[mt][nt][3]);
            if (accum) {
                float2 o0 = *p0, o1 = *p1;
                v0.x += o0.x; v0.y += o0.y; v1.x += o1.x; v1.y += o1.y;
            }
            *p0 = v0;
            *p1 = v1;
        }
    }
}

// ---------------- causal spectral conv, parity-split, 2-term fp16 ----------------
__global__ __launch_bounds__(256) void conv_bf(
    const u16* __restrict__ hTeh, const u16* __restrict__ hToh,
    const u32* __restrict__ P2h, const u32* __restrict__ P2l,
    u16* __restrict__ Uh, u16* __restrict__ Ul)
{
    constexpr int CXE = 0;
    constexpr int CXO = 1280;
    constexpr int CQH = 2560;
    constexpr int CQL = 2760;
    constexpr int CSTAGE = 2960;   // u32
    __shared__ __align__(16) u32 csm[2 * CSTAGE];

    const int d0 = blockIdx.x * 64;
    const int t0 = ((int)gridDim.y - 1 - (int)blockIdx.y) * 128;   // longest first
    const int b  = blockIdx.z >> 4;
    const int k  = blockIdx.z & 15;
    const int tid  = threadIdx.x;
    const int lane = tid & 31;
    const int warp = tid >> 5;
    const int wm = (warp & 3) * 32;
    const int wn = (warp >> 2) * 32;
    const int g  = lane >> 2;
    const int tg = lane & 3;

    const int xr = tid >> 2;
    const int c4 = (tid & 3) * 4;

    const u32 csmAddr = smem_u32(csm);
    const u32 colB = (lane & 7) + ((lane >> 4) & 1) * 8;
    const u32 kbB  = ((lane >> 3) & 1) * 16;
    const u32 xoff = (wn + colB) * 80 + kbB;

    auto issue = [&](int ii, int s) {
        u32* base = csm + s * CSTAGE;
        const int j0 = ii * 32;
        const size_t go = (size_t)(b * D_ + d0 + xr) * S2_ + j0 + c4 * 2;
        cp16(base + CXE + xr * 20 + c4, &hTeh[go]);
        cp16(base + CXO + xr * 20 + c4, &hToh[go]);
        const int tb = k * P2LEN + t0 - 2 * j0 + 124;
        if (tid < 50)
            cp16(base + CQH + tid * 4, &P2h[tb + tid * 4]);
        else if (tid >= 64 && tid < 114)
            cp16(base + CQL + (tid - 64) * 4, &P2l[tb + (tid - 64) * 4]);
    };

    float accE[2][4][4] = {};
    float accO[2][4][4] = {};

    const int nIters = (t0 + 128) / 64;
    issue(0, 0); CP_COMMIT();

    for (int i = 0; i < nIters; i++) {
        if (i + 1 < nIters) issue(i + 1, (i + 1) & 1);
        CP_COMMIT();
        CP_WAIT1();
        __syncthreads();
        const int s = i & 1;
        const u32 sb = csmAddr + (u32)(s * CSTAGE * 4);
        const u32* base = csm + s * CSTAGE;
        const u32* sQh = base + CQH;
        const u32* sQl = base + CQL;

#pragma unroll
        for (int ks = 0; ks < 2; ks++) {
            u32 aEh[2][4], aEl[2][4], aOh[2][4], aOl[2][4];
#pragma unroll
            for (int mt = 0; mt < 2; mt++) {
                const int n = wm + mt * 16 + g - 32 * ks - 4 * tg + 68;
                aEh[mt][0] = sQh[n];      aEh[mt][1] = sQh[n + 8];
                aEh[mt][2] = sQh[n - 16]; aEh[mt][3] = sQh[n - 8];
                aEl[mt][0] = sQl[n];      aEl[mt][1] = sQl[n + 8];
                aEl[mt][2] = sQl[n - 16]; aEl[mt][3] = sQl[n - 8];
                aOh[mt][0] = sQh[n - 1];      aOh[mt][1] = sQh[n + 7];
                aOh[mt][2] = sQh[n - 17];     aOh[mt][3] = sQh[n - 9];
                aOl[mt][0] = sQl[n - 1];      aOl[mt][1] = sQl[n + 7];
                aOl[mt][2] = sQl[n - 17];     aOl[mt][3] = sQl[n - 9];
            }
#pragma unroll
            for (int ntp = 0; ntp < 2; ntp++) {
                u32 e0r, e1r, e2r, e3r, o0r, o1r, o2r, o3r;
                const u32 base_x = sb + xoff + (u32)ntp * 1280 + (u32)ks * 32;
                ldsm4(e0r, e1r, e2r, e3r, base_x);
                ldsm4(o0r, o1r, o2r, o3r, base_x + 5120u);
#pragma unroll
                for (int mt = 0; mt < 2; mt++) {
                    float* e0 = accE[mt][2 * ntp];
                    float* e1 = accE[mt][2 * ntp + 1];
                    float* o0 = accO[mt][2 * ntp];
                    float* o1 = accO[mt][2 * ntp + 1];
                    mma_f16(e0, aEh[mt][0], aEh[mt][1], aEh[mt][2], aEh[mt][3], e0r, e1r);
                    mma_f16(e0, aEl[mt][0], aEl[mt][1], aEl[mt][2], aEl[mt][3], e0r, e1r);
                    mma_f16(e1, aEh[mt][0], aEh[mt][1], aEh[mt][2], aEh[mt][3], e2r, e3r);
                    mma_f16(e1, aEl[mt][0], aEl[mt][1], aEl[mt][2], aEl[mt][3], e2r, e3r);
                    mma_f16(o0, aOh[mt][0], aOh[mt][1], aOh[mt][2], aOh[mt][3], o0r, o1r);
                    mma_f16(o0, aOl[mt][0], aOl[mt][1], aOl[mt][2], aOl[mt][3], o0r, o1r);
                    mma_f16(o1, aOh[mt][0], aOh[mt][1], aOh[mt][2], aOh[mt][3], o2r, o3r);
                    mma_f16(o1, aOl[mt][0], aOl[mt][1], aOl[mt][2], aOl[mt][3], o2r, o3r);
                }
            }
        }
        __syncthreads();
    }

#pragma unroll
    for (int mt = 0; mt < 2; mt++) {
#pragma unroll
        for (int half = 0; half < 2; half++) {
            const int t = t0 + wm + mt * 16 + g + half * 8;
            const float st = (t & 1) ? -1.f : 1.f;
            const size_t rowo = (size_t)(b * S_ + t) * UCOLS;
#pragma unroll
            for (int nt = 0; nt < 4; nt++) {
                const int d = d0 + wn + nt * 8 + 2 * tg;
                const float e0 = accE[mt][nt][half * 2 + 0];
                const float e1 = accE[mt][nt][half * 2 + 1];
                const float o0 = accO[mt][nt][half * 2 + 0];
                const float o1 = accO[mt][nt][half * 2 + 1];
                const float up0 = e0 + o0, up1 = e1 + o1;
                const float um0 = st * (e0 - o0), um1 = st * (e1 - o1);
                u16 h0, l0, h1, l1;
                split_bf(up0, h0, l0); split_bf(up1, h1, l1);
                *(ushort2*)&Uh[rowo + (size_t)k * D_ + d] = make_ushort2(h0, h1);
                *(ushort2*)&Ul[rowo + (size_t)k * D_ + d] = make_ushort2(l0, l1);
                split_bf(um0, h0, l0); split_bf(um1, h1, l1);
                *(ushort2*)&Uh[rowo + (size_t)(K_ + k) * D_ + d] = make_ushort2(h0, h1);
                *(ushort2*)&Ul[rowo + (size_t)(K_ + k) * D_ + d] = make_ushort2(l0, l1);
            }
        }
    }
}

// ---------------- fp32 NT GEMM (tiny out_proj: N=64) ----------------
__global__ __launch_bounds__(256) void gemm_nt(
    const float* __restrict__ A, const float* __restrict__ B, float* __restrict__ C,
    int M, int N, int K, int accum)
{
    __shared__ float As[16][65];
    __shared__ float Bs[16][65];
    const int bm = blockIdx.y * 64;
    const int bn = blockIdx.x * 64;
    const int tid = threadIdx.x;
    const int tx = tid & 15;
    const int ty = tid >> 4;
    const int lr = tid >> 2;
    const int lk = (tid & 3) << 2;

    const float* Ap = A + (size_t)(bm + lr) * K + lk;
    const float* Bp = B + (size_t)(bn + lr) * K + lk;

    float acc[4][4] = {};

    for (int k0 = 0; k0 < K; k0 += 16) {
        float4 av = *(const float4*)(Ap + k0);
        float4 bv = *(const float4*)(Bp + k0);
        __syncthreads();
        As[lk + 0][lr] = av.x; As[lk + 1][lr] = av.y;
        As[lk + 2][lr] = av.z; As[lk + 3][lr] = av.w;
        Bs[lk + 0][lr] = bv.x; Bs[lk + 1][lr] = bv.y;
        Bs[lk + 2][lr] = bv.z; Bs[lk + 3][lr] = bv.w;
        __syncthreads();
#pragma unroll
        for (int kk = 0; kk < 16; kk++) {
            float a[4], b[4];
#pragma unroll
            for (int i = 0; i < 4; i++) a[i] = As[kk][ty * 4 + i];
#pragma unroll
            for (int j = 0; j < 4; j++) b[j] = Bs[kk][tx * 4 + j];
#pragma unroll
            for (int i = 0; i < 4; i++)
#pragma unroll
                for (int j = 0; j < 4; j++)
                    acc[i][j] += a[i] * b[j];
        }
    }

#pragma unroll
    for (int i = 0; i < 4; i++) {
        const int r = bm + ty * 4 + i;
#pragma unroll
        for (int j = 0; j < 4; j++) {
            const int c = bn + tx * 4 + j;
            const size_t idx = (size_t)r * N + c;
            C[idx] = accum ? (C[idx] + acc[i][j]) : acc[i][j];
        }
    }
}

// ---------------- rmsnorm + z copy + AR column scatter (fp16 pairs) ----------------
__global__ __launch_bounds__(256) void rmsnorm_k(
    const float* __restrict__ x, const float* __restrict__ w,
    float* __restrict__ h, float* __restrict__ z,
    u16* __restrict__ Uh, u16* __restrict__ Ul)
{
    __shared__ float red[256];
    const int row = blockIdx.x;
    const int t = row & (S_ - 1);
    const int tid = threadIdx.x;

    const float v0 = x[(size_t)row * D_ + tid];
    const float v1 = x[(size_t)row * D_ + 256 + tid];
    z[(size_t)row * D_ + tid] = v0;
    z[(size_t)row * D_ + 256 + tid] = v1;
    red[tid] = v0 * v0 + v1 * v1;
    __syncthreads();
    for (int s = 128; s > 0; s >>= 1) {
        if (tid < s) red[tid] += red[tid + s];
        __syncthreads();
    }
    const float scale = rsqrtf(red[0] * (1.f / D_) + EPS_);
    const float h0 = v0 * scale * w[tid];
    const float h1 = v1 * scale * w[tid + 256];
    h[(size_t)row * D_ + tid] = h0;
    h[(size_t)row * D_ + 256 + tid] = h1;

    u16 h0h, h0l, h1h, h1l;
    split_bf(h0, h0h, h0l); split_bf(h1, h1h, h1l);

#pragma unroll
    for (int j = 0; j < KU_; j++) {
        if (t + j < S_) {
            const size_t base = (size_t)(row + j) * UCOLS + SPECC + j * D_;
            Uh[base + tid] = h0h; Ul[base + tid] = h0l;
            Uh[base + 256 + tid] = h1h; Ul[base + 256 + tid] = h1l;
        }
        if (t < j) {
            const size_t base = (size_t)row * UCOLS + SPECC + j * D_;
            Uh[base + tid] = 0; Ul[base + tid] = 0;
            Uh[base + 256 + tid] = 0; Ul[base + 256 + tid] = 0;
        }
    }
}

// ---------------- transpose + parity split h -> hTe/hTo (hi only) ----------------
__global__ __launch_bounds__(256) void transplit_k(
    const float* __restrict__ h,
    u16* __restrict__ hTeh, u16* __restrict__ hToh)
{
    __shared__ float tile[32][33];
    const int i0 = blockIdx.x * 32;
    const int d0 = blockIdx.y * 32;
    const int b  = blockIdx.z;
    const int tx = threadIdx.x & 31;
    const int ty = threadIdx.x >> 5;
#pragma unroll
    for (int r = 0; r < 4; r++)
        tile[ty + 8 * r][tx] = h[(size_t)(b * S_ + i0 + ty + 8 * r) * D_ + d0 + tx];
    __syncthreads();
#pragma unroll
    for (int r = 0; r < 4; r++) {
        const float v = tile[tx][ty + 8 * r];
        const u16 hv = f2h_bits(v);
        const size_t o = (size_t)(b * D_ + d0 + ty + 8 * r) * S2_ + (i0 >> 1) + (tx >> 1);
        if (tx & 1) hToh[o] = hv;
        else        hTeh[o] = hv;
    }
}

// ---------------- fused weight fill (fp16 pairs) ----------------
__global__ __launch_bounds__(256) void wfill_k(
    const float* __restrict__ sigma, const float* __restrict__ mp,
    const float* __restrict__ mm, const float* __restrict__ mu,
    u16* __restrict__ Wh, u16* __restrict__ Wl)
{
    const size_t idx = (size_t)blockIdx.x * 256 + threadIdx.x;
    if (idx >= (size_t)D_ * UCOLS) return;
    const int o = (int)(idx / UCOLS);
    const int col = (int)(idx % UCOLS);
    float v;
    if (col < K_ * D_) {
        const int k = col / D_, d = col % D_;
        v = sqrtf(sqrtf(sigma[k])) * mp[((size_t)k * D_ + d) * D_ + o];
    } else if (col < SPECC) {
        const int c = col - K_ * D_;
        const int k = c / D_, d = c % D_;
        v = sqrtf(sqrtf(sigma[k])) * mm[((size_t)k * D_ + d) * D_ + o];
    } else {
        const int c = col - SPECC;
        const int j = c / D_, d = c % D_;
        v = mu[((size_t)j * D_ + d) * D_ + o];
    }
    u16 hi, lo; split_bf(v, hi, lo);
    Wh[idx] = hi; Wl[idx] = lo;
}

// ---------------- splits ----------------
__global__ __launch_bounds__(256) void split_k(
    const float* __restrict__ src, u16* __restrict__ hi, u16* __restrict__ lo, int n)
{
    const int i = blockIdx.x * 256 + threadIdx.x;
    if (i < n) { u16 h, l; split_bf(src[i], h, l); hi[i] = h; lo[i] = l; }
}
__global__ __launch_bounds__(256) void split1_k(
    const float* __restrict__ src, u16* __restrict__ hi, int n)
{
    const int i = blockIdx.x * 256 + threadIdx.x;
    if (i < n) hi[i] = f2h_bits(src[i]);
}
// fc1 split with (y, gate) row interleave: new row 2j <- src j, 2j+1 <- src H+j
__global__ __launch_bounds__(256) void split1i_k(
    const float* __restrict__ src, u16* __restrict__ hi)
{
    const int i = blockIdx.x * 256 + threadIdx.x;   // over 2H*D (new layout)
    if (i >= 2 * H_ * D_) return;
    const int r = i / D_, c = i % D_;
    const int sr = (r & 1) ? (H_ + (r >> 1)) : (r >> 1);
    hi[i] = f2h_bits(src[(size_t)sr * D_ + c]);
}

// ---------------- stride-2 phi pair table (fp16 pairs) ----------------
__global__ __launch_bounds__(256) void phipack_k(
    const float* __restrict__ phi, u32* __restrict__ P2h, u32* __restrict__ P2l)
{
    const int i = blockIdx.x * 256 + threadIdx.x;
    if (i >= K_ * P2LEN) return;
    const int k = i / P2LEN, pp = i % P2LEN;
    const int p = pp - 192;
    u16 lh = 0, ll = 0, hh = 0, hl = 0;
    if (p >= 0 && p < S_)         split_bf(phi[p * K_ + k], lh, ll);
    if (p - 2 >= 0 && p - 2 < S_) split_bf(phi[(p - 2) * K_ + k], hh, hl);
    P2h[i] = (u32)lh | ((u32)hh << 16);
    P2l[i] = (u32)ll | ((u32)hl << 16);
}

// ---------------- reduces ----------------
// x += sum of 8 partials; emit fp16 split of new x
__global__ __launch_bounds__(256) void reduce8_k(
    float* __restrict__ x, const float* __restrict__ p,
    u16* __restrict__ xh, u16* __restrict__ xl)
{
    const int i = blockIdx.x * 256 + threadIdx.x;
    const size_t MN4 = (size_t)R_ * D_ / 4;
    float4 a = ((const float4*)x)[i];
    float sx = 0.f, sy = 0.f, sz = 0.f, sw = 0.f;
#pragma unroll
    for (int j = 0; j < 8; j++) {
        float4 bj = ((const float4*)p)[i + j * MN4];
        sx += bj.x; sy += bj.y; sz += bj.z; sw += bj.w;
    }
    a.x += sx; a.y += sy; a.z += sz; a.w += sw;
    ((float4*)x)[i] = a;
    ushort4 vh, vl;
    split_bf(a.x, vh.x, vl.x); split_bf(a.y, vh.y, vl.y);
    split_bf(a.z, vh.z, vl.z); split_bf(a.w, vh.w, vl.w);
    ((ushort4*)xh)[i] = vh;
    ((ushort4*)xl)[i] = vl;
}

// x += sum of 4 partials + z   (fc2 epilogue + layer residual)
__global__ __launch_bounds__(256) void reduce4z_k(
    float* __restrict__ x, const float* __restrict__ p, const float* __restrict__ z)
{
    const int i = blockIdx.x * 256 + threadIdx.x;
    const size_t MN4 = (size_t)R_ * D_ / 4;
    float4 a = ((const float4*)x)[i];
    float4 b0 = ((const float4*)p)[i];
    float4 b1 = ((const float4*)p)[i + MN4];
    float4 b2 = ((const float4*)p)[i + 2 * MN4];
    float4 b3 = ((const float4*)p)[i + 3 * MN4];
    float4 zz = ((const float4*)z)[i];
    a.x += (b0.x + b1.x) + (b2.x + b3.x) + zz.x;
    a.y += (b0.y + b1.y) + (b2.y + b3.y) + zz.y;
    a.z += (b0.z + b1.z) + (b2.z + b3.z) + zz.z;
    a.w += (b0.w + b1.w) + (b2.w + b3.w) + zz.w;
    ((float4*)x)[i] = a;
}

// ---------------- launch ----------------
extern "C" void kernel_launch(void* const* d_in, const int* in_sizes, int n_in,
                              void* d_out, int out_size)
{
    const float* inputs  = (const float*)d_in[0];
    const float* sigma   = (const float*)d_in[1];
    const float* phi     = (const float*)d_in[2];
    const float* in_proj = (const float*)d_in[3];
    const float* rn_w    = (const float*)d_in[4];
    const float* M_u     = (const float*)d_in[5];
    const float* M_p     = (const float*)d_in[6];
    const float* M_m     = (const float*)d_in[7];
    const float* fc1     = (const float*)d_in[8];
    const float* fc2     = (const float*)d_in[9];
    const float* out_w   = (const float*)d_in[10];
    float* out = (float*)d_out;

    float *x, *z, *h, *part;
    u16 *Uh, *Ul, *Wh, *Wl, *m2h, *m2l, *xh, *xl;
    u16 *hTeh, *hToh;
    u16 *inh, *inl, *iph, *ipl, *f1h, *f2h;
    u32 *P2h, *P2l;
    cudaGetSymbolAddress((void**)&x,   g_x);
    cudaGetSymbolAddress((void**)&z,   g_z);
    cudaGetSymbolAddress((void**)&h,   g_h);
    cudaGetSymbolAddress((void**)&part,g_part);
    cudaGetSymbolAddress((void**)&Uh,  g_Uh);
    cudaGetSymbolAddress((void**)&Ul,  g_Ul);
    cudaGetSymbolAddress((void**)&Wh,  g_Wh);
    cudaGetSymbolAddress((void**)&Wl,  g_Wl);
    cudaGetSymbolAddress((void**)&m2h, g_m2h);
    cudaGetSymbolAddress((void**)&m2l, g_m2l);
    cudaGetSymbolAddress((void**)&hTeh, g_hTeh);
    cudaGetSymbolAddress((void**)&hToh, g_hToh);
    cudaGetSymbolAddress((void**)&xh,  g_xh);
    cudaGetSymbolAddress((void**)&xl,  g_xl);
    cudaGetSymbolAddress((void**)&inh, g_inh);
    cudaGetSymbolAddress((void**)&inl, g_inl);
    cudaGetSymbolAddress((void**)&iph, g_iph);
    cudaGetSymbolAddress((void**)&ipl, g_ipl);
    cudaGetSymbolAddress((void**)&f1h, g_f1h);
    cudaGetSymbolAddress((void**)&f2h, g_f2h);
    cudaGetSymbolAddress((void**)&P2h, g_P2h);
    cudaGetSymbolAddress((void**)&P2l, g_P2l);

    // contraction stage (TERMS=3, 64x128) = (128+256)*20*4*2 = 61440 B > 48K default
    cudaFuncSetAttribute(gemm_bf3<64, 128, 2, 3, NSPLIT_, 0>,
                         cudaFuncAttributeMaxDynamicSharedMemorySize, 61440);

    const int ew_blocks = (R_ * D_ / 4) / 256;
    const int wfill_blocks = (int)(((size_t)D_ * UCOLS + 255) / 256);

    phipack_k<<<(K_ * P2LEN + 255) / 256, 256>>>(phi, P2h, P2l);
    split_k<<<(R_ * DIN_ + 255) / 256, 256>>>(inputs, inh, inl, R_ * DIN_);

    for (int m = 0; m < M_; m++) {
        // x = inputs @ in_proj[m]^T   (2048 x 512, K=64) — 3-term (signal path)
        split_k<<<(D_ * DIN_ + 255) / 256, 256>>>(
            in_proj + (size_t)m * D_ * DIN_, iph, ipl, D_ * DIN_);
        gemm_bf3<64, 64, 2, 3, 1, 0><<<dim3(D_ / 64, R_ / 64), 256, 40960>>>(
            inh, inl, iph, ipl, x, (u16*)0, (u16*)0, R_, D_, DIN_, 0);

        for (int l = 0; l < L_; l++) {
            const int ml = m * L_ + l;

            rmsnorm_k<<<R_, 256>>>(x, rn_w + (size_t)ml * D_, h, z, Uh, Ul);
            transplit_k<<<dim3(S_ / 32, D_ / 32, B_), 256>>>(h, hTeh, hToh);
            conv_bf<<<dim3(D_ / 64, S_ / 128, B_ * K_), 256>>>(
                hTeh, hToh, P2h, P2l, Uh, Ul);
            wfill_k<<<wfill_blocks, 256>>>(
                sigma,
                M_p + (size_t)ml * K_ * D_ * D_,
                M_m + (size_t)ml * K_ * D_ * D_,
                M_u + (size_t)ml * KU_ * D_ * D_,
                Wh, Wl);
            // partials = U @ W^T (3-term, 64x128 tiles, split-K=8 -> 1024 blocks)
            gemm_bf3<64, 128, 2, 3, NSPLIT_, 0>
                <<<dim3(D_ / 128, R_ / 64, NSPLIT_), 256, 61440>>>(
                Uh, Ul, Wh, Wl, part, (u16*)0, (u16*)0, R_, D_, UCOLS, 0);
            reduce8_k<<<ew_blocks, 256>>>(x, part, xh, xl);

            // MLP: fc1 with interleaved (y,gate) weights + fused SiLU epilogue
            split1i_k<<<(2 * H_ * D_ + 255) / 256, 256>>>(
                fc1 + (size_t)ml * 2 * H_ * D_, f1h);
            gemm_bf3<64, 128, 2, 2, 1, 1><<<dim3(2 * H_ / 128, R_ / 64), 256, 40960>>>(
                xh, xl, f1h, (const u16*)0, (float*)0, m2h, m2l, R_, 2 * H_, D_, 0);
            split1_k<<<(D_ * H_ + 255) / 256, 256>>>(
                fc2 + (size_t)ml * D_ * H_, f2h, D_ * H_);
            // fc2: 2-term, 64x64 tiles, split-K=4 -> 1024 blocks; reduce folds +z
            gemm_bf3<64, 64, 2, 2, 4, 0><<<dim3(D_ / 64, R_ / 64, 4), 256, 30720>>>(
                m2h, m2l, f2h, (const u16*)0, part, (u16*)0, (u16*)0, R_, D_, H_, 0);
            reduce4z_k<<<ew_blocks, 256>>>(x, part, z);
        }

        // preds += x @ out_proj[m]^T  (N=64)
        gemm_nt<<<dim3(DIN_ / 64, R_ / 64), 256>>>(
            x, out_w + (size_t)m * DIN_ * D_, out, R_, DIN_, D_, m);
    }
    (void)in_sizes; (void)n_in; (void)out_size;
}

// round 16
// speedup vs baseline: 3.5536x; 1.1444x over previous
#include <cuda_runtime.h>
#include <cuda_fp16.h>
#include <cstddef>

// ---------------- problem constants ----------------
#define B_    2
#define S_    1024
#define S2_   (S_ / 2)
#define DIN_  64
#define D_    512
#define K_    16
#define KU_   3
#define L_    2
#define M_    2
#define H_    2048
#define R_    (B_ * S_)                 // 2048 rows (b*S + t)
#define SPECC (2 * K_ * D_)             // 16384 spectral columns of U
#define UCOLS (SPECC + KU_ * D_)        // 17920 = spectral + AR columns
#define EPS_  1e-5f
#define NSPLIT_ 8
#define P2LEN 1280                      // stride-2 phi pair table (offset 192)

typedef unsigned short u16;
typedef unsigned int   u32;

// ---------------- scratch (static device globals; no allocation) ----------------
__device__ __align__(16) float g_x[R_ * D_];
__device__ __align__(16) float g_z[R_ * D_];
__device__ __align__(16) float g_h[R_ * D_];
__device__ __align__(16) float g_part[(size_t)NSPLIT_ * R_ * D_];

__device__ __align__(16) u16 g_Uh[(size_t)R_ * UCOLS];
__device__ __align__(16) u16 g_Ul[(size_t)R_ * UCOLS];
__device__ __align__(16) u16 g_Wh[(size_t)D_ * UCOLS];
__device__ __align__(16) u16 g_m2h[(size_t)R_ * H_];
__device__ __align__(16) u16 g_m2l[(size_t)R_ * H_];
__device__ __align__(16) u16 g_hTeh[B_ * D_ * S2_];
__device__ __align__(16) u16 g_hTel[B_ * D_ * S2_];
__device__ __align__(16) u16 g_hToh[B_ * D_ * S2_];
__device__ __align__(16) u16 g_hTol[B_ * D_ * S2_];
__device__ __align__(16) u16 g_xh[R_ * D_];
__device__ __align__(16) u16 g_xl[R_ * D_];
__device__ __align__(16) u16 g_inh[R_ * DIN_];
__device__ __align__(16) u16 g_inl[R_ * DIN_];
__device__ __align__(16) u16 g_iph[D_ * DIN_];
__device__ __align__(16) u16 g_ipl[D_ * DIN_];
__device__ __align__(16) u16 g_f1h[2 * H_ * D_];
__device__ __align__(16) u16 g_f2h[D_ * H_];
__device__ __align__(16) u32 g_P2h[K_ * P2LEN];
__device__ __align__(16) u32 g_P2l[K_ * P2LEN];

// ---------------- helpers (fp16 pair split) ----------------
__device__ __forceinline__ void split_bf(float a, u16& hi, u16& lo) {
    __half h = __float2half_rn(a);
    float r = a - __half2float(h);
    __half l = __float2half_rn(r);
    hi = reinterpret_cast<u16&>(h);
    lo = reinterpret_cast<u16&>(l);
}
__device__ __forceinline__ u16 f2h_bits(float a) {
    __half h = __float2half_rn(a);
    return reinterpret_cast<u16&>(h);
}

__device__ __forceinline__ void mma_f16(float c[4],
                                        u32 a0, u32 a1, u32 a2, u32 a3,
                                        u32 b0, u32 b1) {
    asm volatile(
        "mma.sync.aligned.m16n8k16.row.col.f32.f16.f16.f32 "
        "{%0,%1,%2,%3},{%4,%5,%6,%7},{%8,%9},{%0,%1,%2,%3};\n"
        : "+f"(c[0]), "+f"(c[1]), "+f"(c[2]), "+f"(c[3])
        : "r"(a0), "r"(a1), "r"(a2), "r"(a3), "r"(b0), "r"(b1));
}

__device__ __forceinline__ u32 smem_u32(const void* p) {
    u32 a;
    asm("{ .reg .u64 t; cvta.to.shared.u64 t, %1; cvt.u32.u64 %0, t; }" : "=r"(a) : "l"(p));
    return a;
}

__device__ __forceinline__ void ldsm4(u32& r0, u32& r1, u32& r2, u32& r3, u32 saddr) {
    asm volatile("ldmatrix.sync.aligned.m8n8.x4.shared.b16 {%0,%1,%2,%3}, [%4];"
                 : "=r"(r0), "=r"(r1), "=r"(r2), "=r"(r3) : "r"(saddr));
}

__device__ __forceinline__ void cp16(u32* smem_dst, const void* gsrc) {
    unsigned saddr = (unsigned)__cvta_generic_to_shared(smem_dst);
    asm volatile("cp.async.cg.shared.global [%0], [%1], 16;\n" :: "r"(saddr), "l"(gsrc));
}
#define CP_COMMIT() asm volatile("cp.async.commit_group;\n" ::: "memory")
#define CP_WAIT1()  asm volatile("cp.async.wait_group 1;\n" ::: "memory")

// ---------------- fp16 emulated NT GEMM, cp.async 2-stage + ldmatrix ----------------
// TERMS=3: ah*bh + al*bh + ah*bl.  TERMS=2: ah*bh + al*bh (Bl not loaded).
// EPI=0: write fp32 C (accum opt).  EPI=1: columns are interleaved (y, gate) pairs;
//        write split fp16 of y*silu(gate) to Oh/Ol with N/2 columns.
template<int BM, int BN, int WARPS_M, int TERMS, int NSPLIT, int EPI>
__global__ __launch_bounds__(256) void gemm_bf3(
    const u16* __restrict__ Ah, const u16* __restrict__ Al,
    const u16* __restrict__ Bh, const u16* __restrict__ Bl,
    float* __restrict__ C, u16* __restrict__ Oh, u16* __restrict__ Ol,
    int M, int N, int K, int accum)
{
    constexpr int WARPS_N = 8 / WARPS_M;
    constexpr int WM = BM / WARPS_M;
    constexpr int WN = BN / WARPS_N;
    constexpr int MT = WM / 16;
    constexpr int NT = WN / 8;
    constexpr int AOFF  = 0;
    constexpr int ALOFF = BM * 20;
    constexpr int BOFF  = 2 * BM * 20;
    constexpr int BLOFF = 2 * BM * 20 + BN * 20;            // only if TERMS==3
    constexpr int STAGE = (2 * BM + (TERMS - 1) * BN) * 20; // u32 per stage
    extern __shared__ __align__(16) u32 dsm[];

    int kb = 0, ke = K;
    if (NSPLIT > 1) {
        const int z = blockIdx.z;
        const int steps = K / 32;
        kb = ((z * steps) / NSPLIT) * 32;
        ke = (((z + 1) * steps) / NSPLIT) * 32;
        C += (size_t)z * M * N;
        accum = 0;
    }

    const int bm = blockIdx.y * BM;
    const int bn = blockIdx.x * BN;
    const int tid  = threadIdx.x;
    const int lane = tid & 31;
    const int warp = tid >> 5;
    const int wm = (warp % WARPS_M) * WM;
    const int wn = (warp / WARPS_M) * WN;
    const int g  = lane >> 2;
    const int tg = lane & 3;

    const int lr = tid >> 2;
    const int c4 = (tid & 3) * 4;

    const u32 dsmAddr = smem_u32(dsm);
    const u32 rowA = (lane & 7) + ((lane >> 3) & 1) * 8;
    const u32 kbA  = ((lane >> 4) & 1) * 16;
    const u32 colB = (lane & 7) + ((lane >> 4) & 1) * 8;
    const u32 kbB  = ((lane >> 3) & 1) * 16;
    const u32 aoff = (u32)AOFF * 4 + (wm + rowA) * 80 + kbA;
    const u32 boff = (u32)BOFF * 4 + (wn + colB) * 80 + kbB;

    auto issue = [&](int k0, int s) {
        u32* base = dsm + s * STAGE;
#pragma unroll
        for (int r = 0; r < BM / 64; r++) {
            const int rrow = lr + 64 * r;
            const size_t go = (size_t)(bm + rrow) * K + k0 + c4 * 2;
            cp16(base + AOFF  + rrow * 20 + c4, &Ah[go]);
            cp16(base + ALOFF + rrow * 20 + c4, &Al[go]);
        }
#pragma unroll
        for (int r = 0; r < BN / 64; r++) {
            const int rrow = lr + 64 * r;
            const size_t go = (size_t)(bn + rrow) * K + k0 + c4 * 2;
            cp16(base + BOFF + rrow * 20 + c4, &Bh[go]);
            if (TERMS == 3)
                cp16(base + BLOFF + rrow * 20 + c4, &Bl[go]);
        }
    };

    float acc[MT][NT][4] = {};

    const int nIters = (ke - kb) / 32;
    issue(kb, 0); CP_COMMIT();

    for (int i = 0; i < nIters; i++) {
        if (i + 1 < nIters) issue(kb + (i + 1) * 32, (i + 1) & 1);
        CP_COMMIT();
        CP_WAIT1();
        __syncthreads();
        const u32 sb = dsmAddr + (u32)((i & 1) * STAGE * 4);

#pragma unroll
        for (int ks = 0; ks < 2; ks++) {
            const u32 kso = (u32)ks * 32;
            u32 ah[MT][4], al[MT][4];
#pragma unroll
            for (int mt = 0; mt < MT; mt++) {
                const u32 base_a = sb + aoff + (u32)mt * 1280 + kso;
                ldsm4(ah[mt][0], ah[mt][1], ah[mt][2], ah[mt][3], base_a);
                ldsm4(al[mt][0], al[mt][1], al[mt][2], al[mt][3], base_a + (u32)BM * 80);
            }
#pragma unroll
            for (int ntp = 0; ntp < NT / 2; ntp++) {
                u32 bh0, bh1, bh2, bh3;
                const u32 base_b = sb + boff + (u32)ntp * 1280 + kso;
                ldsm4(bh0, bh1, bh2, bh3, base_b);
                u32 bl0 = 0, bl1 = 0, bl2 = 0, bl3 = 0;
                if (TERMS == 3)
                    ldsm4(bl0, bl1, bl2, bl3, base_b + (u32)BN * 80);
#pragma unroll
                for (int mt = 0; mt < MT; mt++) {
                    mma_f16(acc[mt][2 * ntp],     ah[mt][0], ah[mt][1], ah[mt][2], ah[mt][3], bh0, bh1);
                    mma_f16(acc[mt][2 * ntp],     al[mt][0], al[mt][1], al[mt][2], al[mt][3], bh0, bh1);
                    mma_f16(acc[mt][2 * ntp + 1], ah[mt][0], ah[mt][1], ah[mt][2], ah[mt][3], bh2, bh3);
                    mma_f16(acc[mt][2 * ntp + 1], al[mt][0], al[mt][1], al[mt][2], al[mt][3], bh2, bh3);
                    if (TERMS == 3) {
                        mma_f16(acc[mt][2 * ntp],     ah[mt][0], ah[mt][1], ah[mt][2], ah[mt][3], bl0, bl1);
                        mma_f16(acc[mt][2 * ntp + 1], ah[mt][0], ah[mt][1], ah[mt][2], ah[mt][3], bl2, bl3);
                    }
                }
            }
        }
        __syncthreads();
    }

    if (EPI == 1) {
        const int N2 = N >> 1;
#pragma unroll
        for (int mt = 0; mt < MT; mt++) {
            const int r0 = bm + wm + mt * 16 + g;
            const int r1 = r0 + 8;
#pragma unroll
            for (int nt = 0; nt < NT; nt++) {
                const int c2 = (bn + wn + nt * 8 + 2 * tg) >> 1;
                const float y0 = acc[mt][nt][0], g0 = acc[mt][nt][1];
                const float y1 = acc[mt][nt][2], g1 = acc[mt][nt][3];
                const float v0 = y0 * g0 / (1.f + expf(-g0));
                const float v1 = y1 * g1 / (1.f + expf(-g1));
                u16 h, l;
                split_bf(v0, h, l);
                Oh[(size_t)r0 * N2 + c2] = h; Ol[(size_t)r0 * N2 + c2] = l;
                split_bf(v1, h, l);
                Oh[(size_t)r1 * N2 + c2] = h; Ol[(size_t)r1 * N2 + c2] = l;
            }
        }
        return;
    }

#pragma unroll
    for (int mt = 0; mt < MT; mt++) {
        const int r0 = bm + wm + mt * 16 + g;
        const int r1 = r0 + 8;
#pragma unroll
        for (int nt = 0; nt < NT; nt++) {
            const int col = bn + wn + nt * 8 + 2 * tg;
            float2* p0 = (float2*)&C[(size_t)r0 * N + col];
            float2* p1 = (float2*)&C[(size_t)r1 * N + col];
            float2 v0 = make_float2(acc[mt][nt][0], acc[mt][nt][1]);
            float2 v1 = make_float2(acc[mt][nt][2], acc[mt][nt][3]);
            if (accum) {
                float2 o0 = *p0, o1 = *p1;
                v0.x += o0.x; v0.y += o0.y; v1.x += o1.x; v1.y += o1.y;
            }
            *p0 = v0;
            *p1 = v1;
        }
    }
}

// ---------------- causal spectral conv, parity-split, 3-term fp16 ----------------
// E = sum even i, O = sum odd i; Up = E+O, Um = st*(E-O).
// Terms per parity: Qh*Xh + Ql*Xh + Qh*Xl (dropped Ql*Xl ~2^-24).
__global__ __launch_bounds__(256) void conv_bf(
    const u16* __restrict__ hTeh, const u16* __restrict__ hTel,
    const u16* __restrict__ hToh, const u16* __restrict__ hTol,
    const u32* __restrict__ P2h, const u32* __restrict__ P2l,
    u16* __restrict__ Uh, u16* __restrict__ Ul)
{
    constexpr int CXEH = 0;
    constexpr int CXEL = 1280;
    constexpr int CXOH = 2560;
    constexpr int CXOL = 3840;
    constexpr int CQH  = 5120;
    constexpr int CQL  = 5320;
    constexpr int CSTAGE = 5520;   // u32; 22080 B/stage, 2 stages = 44160 B
    __shared__ __align__(16) u32 csm[2 * CSTAGE];

    const int d0 = blockIdx.x * 64;
    const int t0 = ((int)gridDim.y - 1 - (int)blockIdx.y) * 128;   // longest first
    const int b  = blockIdx.z >> 4;
    const int k  = blockIdx.z & 15;
    const int tid  = threadIdx.x;
    const int lane = tid & 31;
    const int warp = tid >> 5;
    const int wm = (warp & 3) * 32;
    const int wn = (warp >> 2) * 32;
    const int g  = lane >> 2;
    const int tg = lane & 3;

    const int xr = tid >> 2;
    const int c4 = (tid & 3) * 4;

    const u32 csmAddr = smem_u32(csm);
    const u32 colB = (lane & 7) + ((lane >> 4) & 1) * 8;
    const u32 kbB  = ((lane >> 3) & 1) * 16;
    const u32 xoff = (wn + colB) * 80 + kbB;

    auto issue = [&](int ii, int s) {
        u32* base = csm + s * CSTAGE;
        const int j0 = ii * 32;
        const size_t go = (size_t)(b * D_ + d0 + xr) * S2_ + j0 + c4 * 2;
        cp16(base + CXEH + xr * 20 + c4, &hTeh[go]);
        cp16(base + CXEL + xr * 20 + c4, &hTel[go]);
        cp16(base + CXOH + xr * 20 + c4, &hToh[go]);
        cp16(base + CXOL + xr * 20 + c4, &hTol[go]);
        const int tb = k * P2LEN + t0 - 2 * j0 + 124;
        if (tid < 50)
            cp16(base + CQH + tid * 4, &P2h[tb + tid * 4]);
        else if (tid >= 64 && tid < 114)
            cp16(base + CQL + (tid - 64) * 4, &P2l[tb + (tid - 64) * 4]);
    };

    float accE[2][4][4] = {};
    float accO[2][4][4] = {};

    const int nIters = (t0 + 128) / 64;
    issue(0, 0); CP_COMMIT();

    for (int i = 0; i < nIters; i++) {
        if (i + 1 < nIters) issue(i + 1, (i + 1) & 1);
        CP_COMMIT();
        CP_WAIT1();
        __syncthreads();
        const int s = i & 1;
        const u32 sb = csmAddr + (u32)(s * CSTAGE * 4);
        const u32* base = csm + s * CSTAGE;
        const u32* sQh = base + CQH;
        const u32* sQl = base + CQL;

#pragma unroll
        for (int ks = 0; ks < 2; ks++) {
            u32 aEh[2][4], aEl[2][4], aOh[2][4], aOl[2][4];
#pragma unroll
            for (int mt = 0; mt < 2; mt++) {
                const int n = wm + mt * 16 + g - 32 * ks - 4 * tg + 68;
                aEh[mt][0] = sQh[n];      aEh[mt][1] = sQh[n + 8];
                aEh[mt][2] = sQh[n - 16]; aEh[mt][3] = sQh[n - 8];
                aEl[mt][0] = sQl[n];      aEl[mt][1] = sQl[n + 8];
                aEl[mt][2] = sQl[n - 16]; aEl[mt][3] = sQl[n - 8];
                aOh[mt][0] = sQh[n - 1];      aOh[mt][1] = sQh[n + 7];
                aOh[mt][2] = sQh[n - 17];     aOh[mt][3] = sQh[n - 9];
                aOl[mt][0] = sQl[n - 1];      aOl[mt][1] = sQl[n + 7];
                aOl[mt][2] = sQl[n - 17];     aOl[mt][3] = sQl[n - 9];
            }
#pragma unroll
            for (int ntp = 0; ntp < 2; ntp++) {
                u32 eh0, eh1, eh2, eh3, el0, el1, el2, el3;
                u32 oh0, oh1, oh2, oh3, ol0, ol1, ol2, ol3;
                const u32 base_x = sb + xoff + (u32)ntp * 1280 + (u32)ks * 32;
                ldsm4(eh0, eh1, eh2, eh3, base_x);
                ldsm4(el0, el1, el2, el3, base_x + 5120u);
                ldsm4(oh0, oh1, oh2, oh3, base_x + 10240u);
                ldsm4(ol0, ol1, ol2, ol3, base_x + 15360u);
#pragma unroll
                for (int mt = 0; mt < 2; mt++) {
                    float* e0 = accE[mt][2 * ntp];
                    float* e1 = accE[mt][2 * ntp + 1];
                    float* o0 = accO[mt][2 * ntp];
                    float* o1 = accO[mt][2 * ntp + 1];
                    mma_f16(e0, aEh[mt][0], aEh[mt][1], aEh[mt][2], aEh[mt][3], eh0, eh1);
                    mma_f16(e0, aEl[mt][0], aEl[mt][1], aEl[mt][2], aEl[mt][3], eh0, eh1);
                    mma_f16(e0, aEh[mt][0], aEh[mt][1], aEh[mt][2], aEh[mt][3], el0, el1);
                    mma_f16(e1, aEh[mt][0], aEh[mt][1], aEh[mt][2], aEh[mt][3], eh2, eh3);
                    mma_f16(e1, aEl[mt][0], aEl[mt][1], aEl[mt][2], aEl[mt][3], eh2, eh3);
                    mma_f16(e1, aEh[mt][0], aEh[mt][1], aEh[mt][2], aEh[mt][3], el2, el3);
                    mma_f16(o0, aOh[mt][0], aOh[mt][1], aOh[mt][2], aOh[mt][3], oh0, oh1);
                    mma_f16(o0, aOl[mt][0], aOl[mt][1], aOl[mt][2], aOl[mt][3], oh0, oh1);
                    mma_f16(o0, aOh[mt][0], aOh[mt][1], aOh[mt][2], aOh[mt][3], ol0, ol1);
                    mma_f16(o1, aOh[mt][0], aOh[mt][1], aOh[mt][2], aOh[mt][3], oh2, oh3);
                    mma_f16(o1, aOl[mt][0], aOl[mt][1], aOl[mt][2], aOl[mt][3], oh2, oh3);
                    mma_f16(o1, aOh[mt][0], aOh[mt][1], aOh[mt][2], aOh[mt][3], ol2, ol3);
                }
            }
        }
        __syncthreads();
    }

#pragma unroll
    for (int mt = 0; mt < 2; mt++) {
#pragma unroll
        for (int half = 0; half < 2; half++) {
            const int t = t0 + wm + mt * 16 + g + half * 8;
            const float st = (t & 1) ? -1.f : 1.f;
            const size_t rowo = (size_t)(b * S_ + t) * UCOLS;
#pragma unroll
            for (int nt = 0; nt < 4; nt++) {
                const int d = d0 + wn + nt * 8 + 2 * tg;
                const float e0 = accE[mt][nt][half * 2 + 0];
                const float e1 = accE[mt][nt][half * 2 + 1];
                const float o0 = accO[mt][nt][half * 2 + 0];
                const float o1 = accO[mt][nt][half * 2 + 1];
                const float up0 = e0 + o0, up1 = e1 + o1;
                const float um0 = st * (e0 - o0), um1 = st * (e1 - o1);
                u16 h0, l0, h1, l1;
                split_bf(up0, h0, l0); split_bf(up1, h1, l1);
                *(ushort2*)&Uh[rowo + (size_t)k * D_ + d] = make_ushort2(h0, h1);
                *(ushort2*)&Ul[rowo + (size_t)k * D_ + d] = make_ushort2(l0, l1);
                split_bf(um0, h0, l0); split_bf(um1, h1, l1);
                *(ushort2*)&Uh[rowo + (size_t)(K_ + k) * D_ + d] = make_ushort2(h0, h1);
                *(ushort2*)&Ul[rowo + (size_t)(K_ + k) * D_ + d] = make_ushort2(l0, l1);
            }
        }
    }
}

// ---------------- rmsnorm + z copy + AR column scatter (fp16 pairs) ----------------
__global__ __launch_bounds__(256) void rmsnorm_k(
    const float* __restrict__ x, const float* __restrict__ w,
    float* __restrict__ h, float* __restrict__ z,
    u16* __restrict__ Uh, u16* __restrict__ Ul)
{
    __shared__ float red[256];
    const int row = blockIdx.x;
    const int t = row & (S_ - 1);
    const int tid = threadIdx.x;

    const float v0 = x[(size_t)row * D_ + tid];
    const float v1 = x[(size_t)row * D_ + 256 + tid];
    z[(size_t)row * D_ + tid] = v0;
    z[(size_t)row * D_ + 256 + tid] = v1;
    red[tid] = v0 * v0 + v1 * v1;
    __syncthreads();
    for (int s = 128; s > 0; s >>= 1) {
        if (tid < s) red[tid] += red[tid + s];
        __syncthreads();
    }
    const float scale = rsqrtf(red[0] * (1.f / D_) + EPS_);
    const float h0 = v0 * scale * w[tid];
    const float h1 = v1 * scale * w[tid + 256];
    h[(size_t)row * D_ + tid] = h0;
    h[(size_t)row * D_ + 256 + tid] = h1;

    u16 h0h, h0l, h1h, h1l;
    split_bf(h0, h0h, h0l); split_bf(h1, h1h, h1l);

#pragma unroll
    for (int j = 0; j < KU_; j++) {
        if (t + j < S_) {
            const size_t base = (size_t)(row + j) * UCOLS + SPECC + j * D_;
            Uh[base + tid] = h0h; Ul[base + tid] = h0l;
            Uh[base + 256 + tid] = h1h; Ul[base + 256 + tid] = h1l;
        }
        if (t < j) {
            const size_t base = (size_t)row * UCOLS + SPECC + j * D_;
            Uh[base + tid] = 0; Ul[base + tid] = 0;
            Uh[base + 256 + tid] = 0; Ul[base + 256 + tid] = 0;
        }
    }
}

// ---------------- transpose + parity split h -> hTe/hTo (hi+lo) ----------------
__global__ __launch_bounds__(256) void transplit_k(
    const float* __restrict__ h,
    u16* __restrict__ hTeh, u16* __restrict__ hTel,
    u16* __restrict__ hToh, u16* __restrict__ hTol)
{
    __shared__ float tile[32][33];
    const int i0 = blockIdx.x * 32;
    const int d0 = blockIdx.y * 32;
    const int b  = blockIdx.z;
    const int tx = threadIdx.x & 31;
    const int ty = threadIdx.x >> 5;
#pragma unroll
    for (int r = 0; r < 4; r++)
        tile[ty + 8 * r][tx] = h[(size_t)(b * S_ + i0 + ty + 8 * r) * D_ + d0 + tx];
    __syncthreads();
#pragma unroll
    for (int r = 0; r < 4; r++) {
        const float v = tile[tx][ty + 8 * r];
        u16 hi, lo; split_bf(v, hi, lo);
        const size_t o = (size_t)(b * D_ + d0 + ty + 8 * r) * S2_ + (i0 >> 1) + (tx >> 1);
        if (tx & 1) { hToh[o] = hi; hTol[o] = lo; }
        else        { hTeh[o] = hi; hTel[o] = lo; }
    }
}

// ---------------- fused weight fill, transposed/coalesced, hi only ----------------
// grid (UCOLS/32, D/32); reads mp/mm/mu with contiguous o, writes Wh[o][col].
__global__ __launch_bounds__(256) void wfillT_k(
    const float* __restrict__ sigma, const float* __restrict__ mp,
    const float* __restrict__ mm, const float* __restrict__ mu,
    u16* __restrict__ Wh)
{
    __shared__ float t[32][33];
    const int col0 = blockIdx.x * 32;
    const int o0   = blockIdx.y * 32;
    const int tx = threadIdx.x & 31;
    const int ty = threadIdx.x >> 5;
#pragma unroll
    for (int r = 0; r < 4; r++) {
        const int col = col0 + ty + 8 * r;
        float v;
        if (col < K_ * D_) {
            const int k = col / D_, d = col % D_;
            v = sqrtf(sqrtf(sigma[k])) * mp[((size_t)k * D_ + d) * D_ + o0 + tx];
        } else if (col < SPECC) {
            const int c = col - K_ * D_;
            const int k = c / D_, d = c % D_;
            v = sqrtf(sqrtf(sigma[k])) * mm[((size_t)k * D_ + d) * D_ + o0 + tx];
        } else {
            const int c = col - SPECC;
            const int j = c / D_, d = c % D_;
            v = mu[((size_t)j * D_ + d) * D_ + o0 + tx];
        }
        t[ty + 8 * r][tx] = v;
    }
    __syncthreads();
#pragma unroll
    for (int r = 0; r < 4; r++) {
        const int o = o0 + ty + 8 * r;
        Wh[(size_t)o * UCOLS + col0 + tx] = f2h_bits(t[tx][ty + 8 * r]);
    }
}

// ---------------- splits ----------------
__global__ __launch_bounds__(256) void split_k(
    const float* __restrict__ src, u16* __restrict__ hi, u16* __restrict__ lo, int n)
{
    const int i = blockIdx.x * 256 + threadIdx.x;
    if (i < n) { u16 h, l; split_bf(src[i], h, l); hi[i] = h; lo[i] = l; }
}
__global__ __launch_bounds__(256) void split1_k(
    const float* __restrict__ src, u16* __restrict__ hi, int n)
{
    const int i = blockIdx.x * 256 + threadIdx.x;
    if (i < n) hi[i] = f2h_bits(src[i]);
}
// fc1 split with (y, gate) row interleave: new row 2j <- src j, 2j+1 <- src H+j
__global__ __launch_bounds__(256) void split1i_k(
    const float* __restrict__ src, u16* __restrict__ hi)
{
    const int i = blockIdx.x * 256 + threadIdx.x;   // over 2H*D (new layout)
    if (i >= 2 * H_ * D_) return;
    const int r = i / D_, c = i % D_;
    const int sr = (r & 1) ? (H_ + (r >> 1)) : (r >> 1);
    hi[i] = f2h_bits(src[(size_t)sr * D_ + c]);
}

// ---------------- stride-2 phi pair table (fp16 pairs) ----------------
__global__ __launch_bounds__(256) void phipack_k(
    const float* __restrict__ phi, u32* __restrict__ P2h, u32* __restrict__ P2l)
{
    const int i = blockIdx.x * 256 + threadIdx.x;
    if (i >= K_ * P2LEN) return;
    const int k = i / P2LEN, pp = i % P2LEN;
    const int p = pp - 192;
    u16 lh = 0, ll = 0, hh = 0, hl = 0;
    if (p >= 0 && p < S_)         split_bf(phi[p * K_ + k], lh, ll);
    if (p - 2 >= 0 && p - 2 < S_) split_bf(phi[(p - 2) * K_ + k], hh, hl);
    P2h[i] = (u32)lh | ((u32)hh << 16);
    P2l[i] = (u32)ll | ((u32)hl << 16);
}

// ---------------- reduces ----------------
// x += sum of 8 partials; emit fp16 split of new x
__global__ __launch_bounds__(256) void reduce8_k(
    float* __restrict__ x, const float* __restrict__ p,
    u16* __restrict__ xh, u16* __restrict__ xl)
{
    const int i = blockIdx.x * 256 + threadIdx.x;
    const size_t MN4 = (size_t)R_ * D_ / 4;
    float4 a = ((const float4*)x)[i];
    float sx = 0.f, sy = 0.f, sz = 0.f, sw = 0.f;
#pragma unroll
    for (int j = 0; j < 8; j++) {
        float4 bj = ((const float4*)p)[i + j * MN4];
        sx += bj.x; sy += bj.y; sz += bj.z; sw += bj.w;
    }
    a.x += sx; a.y += sy; a.z += sz; a.w += sw;
    ((float4*)x)[i] = a;
    ushort4 vh, vl;
    split_bf(a.x, vh.x, vl.x); split_bf(a.y, vh.y, vl.y);
    split_bf(a.z, vh.z, vl.z); split_bf(a.w, vh.w, vl.w);
    ((ushort4*)xh)[i] = vh;
    ((ushort4*)xl)[i] = vl;
}

// x += sum of 4 partials + z; emit fp16 split of new x (for out_proj)
__global__ __launch_bounds__(256) void reduce4z_k(
    float* __restrict__ x, const float* __restrict__ p, const float* __restrict__ z,
    u16* __restrict__ xh, u16* __restrict__ xl)
{
    const int i = blockIdx.x * 256 + threadIdx.x;
    const size_t MN4 = (size_t)R_ * D_ / 4;
    float4 a = ((const float4*)x)[i];
    float4 b0 = ((const float4*)p)[i];
    float4 b1 = ((const float4*)p)[i + MN4];
    float4 b2 = ((const float4*)p)[i + 2 * MN4];
    float4 b3 = ((const float4*)p)[i + 3 * MN4];
    float4 zz = ((const float4*)z)[i];
    a.x += (b0.x + b1.x) + (b2.x + b3.x) + zz.x;
    a.y += (b0.y + b1.y) + (b2.y + b3.y) + zz.y;
    a.z += (b0.z + b1.z) + (b2.z + b3.z) + zz.z;
    a.w += (b0.w + b1.w) + (b2.w + b3.w) + zz.w;
    ((float4*)x)[i] = a;
    ushort4 vh, vl;
    split_bf(a.x, vh.x, vl.x); split_bf(a.y, vh.y, vl.y);
    split_bf(a.z, vh.z, vl.z); split_bf(a.w, vh.w, vl.w);
    ((ushort4*)xh)[i] = vh;
    ((ushort4*)xl)[i] = vl;
}

// ---------------- launch ----------------
extern "C" void kernel_launch(void* const* d_in, const int* in_sizes, int n_in,
                              void* d_out, int out_size)
{
    const float* inputs  = (const float*)d_in[0];
    const float* sigma   = (const float*)d_in[1];
    const float* phi     = (const float*)d_in[2];
    const float* in_proj = (const float*)d_in[3];
    const float* rn_w    = (const float*)d_in[4];
    const float* M_u     = (const float*)d_in[5];
    const float* M_p     = (const float*)d_in[6];
    const float* M_m     = (const float*)d_in[7];
    const float* fc1     = (const float*)d_in[8];
    const float* fc2     = (const float*)d_in[9];
    const float* out_w   = (const float*)d_in[10];
    float* out = (float*)d_out;

    float *x, *z, *h, *part;
    u16 *Uh, *Ul, *Wh, *m2h, *m2l, *xh, *xl;
    u16 *hTeh, *hTel, *hToh, *hTol;
    u16 *inh, *inl, *iph, *ipl, *f1h, *f2h;
    u32 *P2h, *P2l;
    cudaGetSymbolAddress((void**)&x,   g_x);
    cudaGetSymbolAddress((void**)&z,   g_z);
    cudaGetSymbolAddress((void**)&h,   g_h);
    cudaGetSymbolAddress((void**)&part,g_part);
    cudaGetSymbolAddress((void**)&Uh,  g_Uh);
    cudaGetSymbolAddress((void**)&Ul,  g_Ul);
    cudaGetSymbolAddress((void**)&Wh,  g_Wh);
    cudaGetSymbolAddress((void**)&m2h, g_m2h);
    cudaGetSymbolAddress((void**)&m2l, g_m2l);
    cudaGetSymbolAddress((void**)&hTeh, g_hTeh);
    cudaGetSymbolAddress((void**)&hTel, g_hTel);
    cudaGetSymbolAddress((void**)&hToh, g_hToh);
    cudaGetSymbolAddress((void**)&hTol, g_hTol);
    cudaGetSymbolAddress((void**)&xh,  g_xh);
    cudaGetSymbolAddress((void**)&xl,  g_xl);
    cudaGetSymbolAddress((void**)&inh, g_inh);
    cudaGetSymbolAddress((void**)&inl, g_inl);
    cudaGetSymbolAddress((void**)&iph, g_iph);
    cudaGetSymbolAddress((void**)&ipl, g_ipl);
    cudaGetSymbolAddress((void**)&f1h, g_f1h);
    cudaGetSymbolAddress((void**)&f2h, g_f2h);
    cudaGetSymbolAddress((void**)&P2h, g_P2h);
    cudaGetSymbolAddress((void**)&P2l, g_P2l);

    const int ew_blocks = (R_ * D_ / 4) / 256;

    phipack_k<<<(K_ * P2LEN + 255) / 256, 256>>>(phi, P2h, P2l);
    split_k<<<(R_ * DIN_ + 255) / 256, 256>>>(inputs, inh, inl, R_ * DIN_);

    for (int m = 0; m < M_; m++) {
        // x = inputs @ in_proj[m]^T   (2048 x 512, K=64) — 3-term
        split_k<<<(D_ * DIN_ + 255) / 256, 256>>>(
            in_proj + (size_t)m * D_ * DIN_, iph, ipl, D_ * DIN_);
        gemm_bf3<64, 64, 2, 3, 1, 0><<<dim3(D_ / 64, R_ / 64), 256, 40960>>>(
            inh, inl, iph, ipl, x, (u16*)0, (u16*)0, R_, D_, DIN_, 0);

        for (int l = 0; l < L_; l++) {
            const int ml = m * L_ + l;

            rmsnorm_k<<<R_, 256>>>(x, rn_w + (size_t)ml * D_, h, z, Uh, Ul);
            transplit_k<<<dim3(S_ / 32, D_ / 32, B_), 256>>>(h, hTeh, hTel, hToh, hTol);
            conv_bf<<<dim3(D_ / 64, S_ / 128, B_ * K_), 256>>>(
                hTeh, hTel, hToh, hTol, P2h, P2l, Uh, Ul);
            wfillT_k<<<dim3(UCOLS / 32, D_ / 32), 256>>>(
                sigma,
                M_p + (size_t)ml * K_ * D_ * D_,
                M_m + (size_t)ml * K_ * D_ * D_,
                M_u + (size_t)ml * KU_ * D_ * D_,
                Wh);
            // partials = U @ W^T (2-term: W-lo dropped; 64x128 tiles, split-K=8)
            gemm_bf3<64, 128, 2, 2, NSPLIT_, 0>
                <<<dim3(D_ / 128, R_ / 64, NSPLIT_), 256, 40960>>>(
                Uh, Ul, Wh, (const u16*)0, part, (u16*)0, (u16*)0, R_, D_, UCOLS, 0);
            reduce8_k<<<ew_blocks, 256>>>(x, part, xh, xl);

            // MLP: fc1 with interleaved (y,gate) weights + fused SiLU epilogue
            split1i_k<<<(2 * H_ * D_ + 255) / 256, 256>>>(
                fc1 + (size_t)ml * 2 * H_ * D_, f1h);
            gemm_bf3<64, 128, 2, 2, 1, 1><<<dim3(2 * H_ / 128, R_ / 64), 256, 40960>>>(
                xh, xl, f1h, (const u16*)0, (float*)0, m2h, m2l, R_, 2 * H_, D_, 0);
            split1_k<<<(D_ * H_ + 255) / 256, 256>>>(
                fc2 + (size_t)ml * D_ * H_, f2h, D_ * H_);
            // fc2: 2-term, 64x64 tiles, split-K=4; reduce folds +z and emits x split
            gemm_bf3<64, 64, 2, 2, 4, 0><<<dim3(D_ / 64, R_ / 64, 4), 256, 30720>>>(
                m2h, m2l, f2h, (const u16*)0, part, (u16*)0, (u16*)0, R_, D_, H_, 0);
            reduce4z_k<<<ew_blocks, 256>>>(x, part, z, xh, xl);
        }

        // preds += x @ out_proj[m]^T  (N=64) — 3-term fp16
        split_k<<<(DIN_ * D_ + 255) / 256, 256>>>(
            out_w + (size_t)m * DIN_ * D_, iph, ipl, DIN_ * D_);
        gemm_bf3<64, 64, 2, 3, 1, 0><<<dim3(DIN_ / 64, R_ / 64), 256, 40960>>>(
            xh, xl, iph, ipl, out, (u16*)0, (u16*)0, R_, DIN_, D_, m);
    }
    (void)in_sizes; (void)n_in; (void)out_size;
}